// round 3
// baseline (speedup 1.0000x reference)
#include <cuda_runtime.h>
#include <math.h>

#define BB 512
#define TT 192
#define CC 256

typedef unsigned long long ull;

// ---------------- scratch (device globals; no allocation) ----------------
__device__ float g_conv[(size_t)BB * CC * TT];   // conv output   [B,256,192]
__device__ float g_xbuf[(size_t)BB * CC * TT];   // interp output [B,256,192]
__device__ float g_xg[(size_t)2 * BB * TT * 128];// lstm pre-gates [dir,B,T,128]
__device__ float g_mu[BB * 16];
__device__ float g_rsig[BB * 16];
__device__ int   g_gi[BB * TT];
__device__ float g_lam[BB * TT];

// ---------------- f32x2 packed helpers ----------------
__device__ __forceinline__ ull pk2(float lo, float hi) {
  ull r;
  asm("mov.b64 %0, {%1, %2};" : "=l"(r) : "f"(lo), "f"(hi));
  return r;
}
__device__ __forceinline__ ull fma2(ull a, ull b, ull c) {
  ull d;
  asm("fma.rn.f32x2 %0, %1, %2, %3;" : "=l"(d) : "l"(a), "l"(b), "l"(c));
  return d;
}
__device__ __forceinline__ void upk2(ull v, float& lo, float& hi) {
  asm("mov.b64 {%0, %1}, %2;" : "=f"(lo), "=f"(hi) : "l"(v));
}

// ---------------- threefry2x32 (JAX), host + device ----------------
__host__ __device__ __forceinline__ void tf2x32(unsigned k0, unsigned k1,
                                                unsigned x0, unsigned x1,
                                                unsigned& y0, unsigned& y1) {
  unsigned ks2 = k0 ^ k1 ^ 0x1BD11BDAu;
  x0 += k0; x1 += k1;
#define TFR(r) x0 += x1; x1 = (x1 << (r)) | (x1 >> (32 - (r))); x1 ^= x0;
  TFR(13) TFR(15) TFR(26) TFR(6)
  x0 += k1;  x1 += ks2 + 1u;
  TFR(17) TFR(29) TFR(16) TFR(24)
  x0 += ks2; x1 += k0 + 2u;
  TFR(13) TFR(15) TFR(26) TFR(6)
  x0 += k0;  x1 += k1 + 3u;
  TFR(17) TFR(29) TFR(16) TFR(24)
  x0 += k1;  x1 += ks2 + 4u;
  TFR(13) TFR(15) TFR(26) TFR(6)
  x0 += ks2; x1 += k0 + 5u;
#undef TFR
  y0 = x0; y1 = x1;
}

__device__ __forceinline__ unsigned tf_bits32(unsigned k0, unsigned k1, unsigned n) {
  unsigned y0, y1;
  tf2x32(k0, k1, 0u, n, y0, y1);
  return y0 ^ y1;   // jax partitionable random_bits (32-bit)
}

// ---------------- conv1d K=5 'same', implicit GEMM, f32x2 packed ----------------
// 128 threads/block; tile 128 O x 64 T; thread: 8 O (stride 16) x 8 T (contig).
#define CICH 8
__global__ __launch_bounds__(128) void conv_kernel(
    const float* __restrict__ x, const float* __restrict__ w,
    const float* __restrict__ bias, float* __restrict__ out, int Cin) {
  __shared__ float xs[CICH][72];              // 64 + 4 halo (+pad)
  __shared__ float ws2[CICH][5][128][2];      // weights duplicated (w,w)
  int b = blockIdx.z;
  int obase = blockIdx.y * 128;
  int tbase = blockIdx.x * 64;
  int tid = threadIdx.x;
  int otid = tid & 15;       // 16 output lanes
  int ttid = tid >> 4;       // 8 time lanes, 8 t each
  ull acc[8][4];
#pragma unroll
  for (int u = 0; u < 8; u++)
#pragma unroll
    for (int p = 0; p < 4; p++) acc[u][p] = pk2(0.f, 0.f);
  const float* xb = x + (size_t)b * Cin * TT;
  int wstride = Cin * 5;
  for (int ci0 = 0; ci0 < Cin; ci0 += CICH) {
    for (int idx = tid; idx < CICH * 68; idx += 128) {
      int i = idx / 68, j = idx - i * 68;
      int ci = ci0 + i, t = tbase + j - 2;
      xs[i][j] = (ci < Cin && t >= 0 && t < TT) ? xb[(size_t)ci * TT + t] : 0.f;
    }
    for (int idx = tid; idx < CICH * 5 * 128; idx += 128) {
      int o = idx / 40, r = idx - o * 40;
      int i = r / 5, k = r - i * 5;
      int ci = ci0 + i;
      float v = (ci < Cin) ? w[(size_t)(obase + o) * wstride + ci * 5 + k] : 0.f;
      ws2[i][k][o][0] = v;
      ws2[i][k][o][1] = v;
    }
    __syncthreads();
#pragma unroll
    for (int i = 0; i < CICH; i++) {
      float xv[12];
#pragma unroll
      for (int j = 0; j < 12; j++) xv[j] = xs[i][ttid * 8 + j];
      ull P[11];
#pragma unroll
      for (int j = 0; j < 11; j++) P[j] = pk2(xv[j], xv[j + 1]);
#pragma unroll
      for (int u = 0; u < 8; u++) {
        int o = otid + 16 * u;
#pragma unroll
        for (int k = 0; k < 5; k++) {
          ull wv = *reinterpret_cast<const ull*>(&ws2[i][k][o][0]);
          acc[u][0] = fma2(wv, P[k], acc[u][0]);
          acc[u][1] = fma2(wv, P[2 + k], acc[u][1]);
          acc[u][2] = fma2(wv, P[4 + k], acc[u][2]);
          acc[u][3] = fma2(wv, P[6 + k], acc[u][3]);
        }
      }
    }
    __syncthreads();
  }
#pragma unroll
  for (int u = 0; u < 8; u++) {
    int o = obase + otid + 16 * u;
    float bv = bias[o];
    float r[8];
#pragma unroll
    for (int p = 0; p < 4; p++) upk2(acc[u][p], r[2 * p], r[2 * p + 1]);
    float* op = out + ((size_t)b * CC + o) * TT + tbase + ttid * 8;
    float4 r4a, r4b;
    r4a.x = r[0] + bv; r4a.y = r[1] + bv; r4a.z = r[2] + bv; r4a.w = r[3] + bv;
    r4b.x = r[4] + bv; r4b.y = r[5] + bv; r4b.z = r[6] + bv; r4b.w = r[7] + bv;
    *reinterpret_cast<float4*>(op) = r4a;
    *reinterpret_cast<float4*>(op + 4) = r4b;
  }
}

// ---------------- GroupNorm stats: one block per (b, group) ----------------
__global__ __launch_bounds__(128) void gn_stats(const float* __restrict__ conv,
                                                float* __restrict__ mu,
                                                float* __restrict__ rsig) {
  __shared__ float ss[128], ss2[128];
  int b = blockIdx.x >> 4, g = blockIdx.x & 15;
  const float* p = conv + ((size_t)b * CC + g * 16) * TT;
  float s = 0.f, s2 = 0.f;
  for (int i = threadIdx.x; i < 16 * TT; i += 128) {
    float v = p[i];
    s += v;
    s2 = fmaf(v, v, s2);
  }
  ss[threadIdx.x] = s; ss2[threadIdx.x] = s2;
  __syncthreads();
  for (int off = 64; off > 0; off >>= 1) {
    if (threadIdx.x < off) {
      ss[threadIdx.x] += ss[threadIdx.x + off];
      ss2[threadIdx.x] += ss2[threadIdx.x + off];
    }
    __syncthreads();
  }
  if (threadIdx.x == 0) {
    float m = ss[0] * (1.0f / 3072.0f);
    float var = ss2[0] * (1.0f / 3072.0f) - m * m;
    mu[blockIdx.x] = m;
    rsig[blockIdx.x] = rsqrtf(var + 1e-5f);
  }
}

// ---------------- interp_lnr metadata: one thread per batch ----------------
__global__ void interp_meta(int* __restrict__ gi, float* __restrict__ lam,
                            unsigned u0, unsigned u1, unsigned a0, unsigned a1,
                            unsigned c0, unsigned c1) {
  int b = blockIdx.x * blockDim.x + threadIdx.x;
  if (b >= BB) return;
  int base = b * TT;
  for (int t = 0; t < TT; t++) gi[base + t] = -1;
  int off = 0, pos = 0;
  for (int s = 0; s < 7; s++) {
    unsigned n = (unsigned)(b * 7 + s);
    unsigned ub = tf_bits32(u0, u1, n);
    float f = __uint_as_float((ub >> 9) | 0x3f800000u) - 1.0f;  // [0,1)
    float scale = f + 0.5f;
    unsigned hb = tf_bits32(a0, a1, n);
    unsigned lb = tf_bits32(c0, c1, n);
    unsigned offt = ((hb % 13u) * 9u + lb % 13u) % 13u;  // 2^32 % 13 == 9
    int len = 19 + (int)offt;
    float lenm1 = (float)(len - 1);
    for (int l = 0; l < 64; l++) {
      float idx = __fdiv_rn((float)l, scale);
      float fl = floorf(idx);
      float lm = idx - fl;
      if (fl < lenm1) {
        int io = (int)fl + off;
        if (io < TT - 1) {
          if (pos < TT) { gi[base + pos] = io; lam[base + pos] = lm; }
          pos++;
        }
      }
    }
    off += len;
  }
}

// ---------------- interp apply: fused GN norm + ReLU + lerp gather ----------------
__global__ __launch_bounds__(192) void interp_apply(
    const float* __restrict__ conv, const int* __restrict__ gi,
    const float* __restrict__ lam, const float* __restrict__ mu,
    const float* __restrict__ rsig, const float* __restrict__ gnw,
    const float* __restrict__ gnb, float* __restrict__ out) {
  int b = blockIdx.x, t = threadIdx.x;
  __shared__ float smu[16], srs[16];
  __shared__ int sg[TT];
  __shared__ float sl[TT];
  if (t < 16) { smu[t] = mu[b * 16 + t]; srs[t] = rsig[b * 16 + t]; }
  sg[t] = gi[b * TT + t];
  sl[t] = lam[b * TT + t];
  __syncthreads();
  int g = sg[t];
  float lm = sl[t];
  const float* cb = conv + (size_t)b * CC * TT;
  float* ob = out + (size_t)b * CC * TT;
  for (int c = 0; c < CC; c++) {
    float val = 0.f;
    if (g >= 0) {
      float m = smu[c >> 4], rs = srs[c >> 4];
      float w = gnw[c], be = gnb[c];
      float a = cb[c * TT + g], e = cb[c * TT + g + 1];
      float fa = fmaxf((a - m) * rs * w + be, 0.f);
      float fb = fmaxf((e - m) * rs * w + be, 0.f);
      val = (1.0f - lm) * fa + lm * fb;
    }
    ob[c * TT + t] = val;
  }
}

// ---------------- xg pre-gate GEMM: [dir,B,T,128] ----------------
__global__ __launch_bounds__(256) void xg_gemm(
    const float* __restrict__ x, const float* __restrict__ wf,
    const float* __restrict__ wb, const float* __restrict__ bif,
    const float* __restrict__ bhf, const float* __restrict__ bib,
    const float* __restrict__ bhb, float* __restrict__ xg) {
  __shared__ float xs[8][64];
  __shared__ float ws[8][128];
  int d = blockIdx.y, b = blockIdx.z, tbase = blockIdx.x * 64;
  const float* w = d ? wb : wf;
  const float* bi = d ? bib : bif;
  const float* bh = d ? bhb : bhf;
  int tid = threadIdx.x, otid = tid & 15, ttid = tid >> 4;
  float acc[8][4];
#pragma unroll
  for (int u = 0; u < 8; u++)
#pragma unroll
    for (int v = 0; v < 4; v++) acc[u][v] = 0.f;
  const float* xb = x + (size_t)b * CC * TT;
  for (int ci0 = 0; ci0 < CC; ci0 += 8) {
    for (int idx = tid; idx < 512; idx += 256) {
      int i = idx >> 6, j = idx & 63;
      xs[i][j] = xb[(size_t)(ci0 + i) * TT + tbase + j];
    }
    for (int idx = tid; idx < 1024; idx += 256) {
      int o = idx >> 3, i = idx & 7;
      ws[i][o] = w[(size_t)o * CC + ci0 + i];
    }
    __syncthreads();
#pragma unroll
    for (int i = 0; i < 8; i++) {
      float xv[4];
#pragma unroll
      for (int v = 0; v < 4; v++) xv[v] = xs[i][ttid * 4 + v];
#pragma unroll
      for (int u = 0; u < 8; u++) {
        float wv = ws[i][otid + 16 * u];
#pragma unroll
        for (int v = 0; v < 4; v++) acc[u][v] = fmaf(wv, xv[v], acc[u][v]);
      }
    }
    __syncthreads();
  }
#pragma unroll
  for (int u = 0; u < 8; u++) {
    int g = otid + 16 * u;
    float bias = bi[g] + bh[g];
#pragma unroll
    for (int v = 0; v < 4; v++) {
      int t = tbase + ttid * 4 + v;
      xg[((size_t)(d * BB + b) * TT + t) * 128 + g] = acc[u][v] + bias;
    }
  }
}

// ---------------- LSTM recurrence: warp per batch element ----------------
__device__ __forceinline__ float sigf(float x) { return 1.0f / (1.0f + expf(-x)); }

__global__ __launch_bounds__(256) void lstm_kernel(
    const float* __restrict__ xg, const float* __restrict__ whf,
    const float* __restrict__ whb, float* __restrict__ out) {
  __shared__ float ws[32 * 128];  // ws[j*128 + row]
  int dir = blockIdx.y;
  const float* wh = dir ? whb : whf;
  int tid = threadIdx.x;
  for (int idx = tid; idx < 4096; idx += 256) {
    int j = idx >> 7, r = idx & 127;
    ws[idx] = wh[r * 32 + j];
  }
  __syncthreads();
  int warp = tid >> 5, lane = tid & 31;
  int b = blockIdx.x * 8 + warp;
  const float* xgb = xg + (size_t)(dir * BB + b) * TT * 128;
  float h = 0.f, c = 0.f;
  for (int step = 0; step < TT; step++) {
    int t = dir ? (TT - 1 - step) : step;
    const float* p = xgb + (size_t)t * 128;
    float gi = p[lane], gf = p[32 + lane], gg = p[64 + lane], go = p[96 + lane];
#pragma unroll
    for (int j = 0; j < 32; j++) {
      float hj = __shfl_sync(0xffffffffu, h, j);
      const float* wr = ws + j * 128;
      gi = fmaf(wr[lane], hj, gi);
      gf = fmaf(wr[32 + lane], hj, gf);
      gg = fmaf(wr[64 + lane], hj, gg);
      go = fmaf(wr[96 + lane], hj, go);
    }
    c = sigf(gf) * c + sigf(gi) * tanhf(gg);
    h = sigf(go) * tanhf(c);
    if (dir == 0) {
      if ((t & 7) == 7) out[((size_t)b * 24 + (t >> 3)) * 64 + lane] = h;
    } else {
      if ((t & 7) == 0) out[((size_t)b * 24 + (t >> 3)) * 64 + 32 + lane] = h;
    }
  }
}

// ---------------- launch ----------------
extern "C" void kernel_launch(void* const* d_in, const int* in_sizes, int n_in,
                              void* d_out, int out_size) {
  (void)in_sizes; (void)n_in;
  float *p_conv, *p_xbuf, *p_xg, *p_mu, *p_rsig, *p_lam;
  int* p_gi;
  cudaGetSymbolAddress((void**)&p_conv, g_conv);
  cudaGetSymbolAddress((void**)&p_xbuf, g_xbuf);
  cudaGetSymbolAddress((void**)&p_xg, g_xg);
  cudaGetSymbolAddress((void**)&p_mu, g_mu);
  cudaGetSymbolAddress((void**)&p_rsig, g_rsig);
  cudaGetSymbolAddress((void**)&p_gi, g_gi);
  cudaGetSymbolAddress((void**)&p_lam, g_lam);

  const float* x0 = (const float*)d_in[0];

  // JAX threefry keys: rng = key(42); per layer i: fold_in -> split -> randint split
  unsigned keys[3][6];
  for (int i = 0; i < 3; i++) {
    unsigned f0, f1;
    tf2x32(0u, 42u, 0u, (unsigned)i, f0, f1);         // fold_in(key, i)
    unsigned k1a, k1b, k2a, k2b;
    tf2x32(f0, f1, 0u, 0u, k1a, k1b);                 // split[0] -> uniform key
    tf2x32(f0, f1, 0u, 1u, k2a, k2b);                 // split[1] -> randint key
    unsigned ha, hb2, la, lb2;
    tf2x32(k2a, k2b, 0u, 0u, ha, hb2);                // randint higher-bits key
    tf2x32(k2a, k2b, 0u, 1u, la, lb2);                // randint lower-bits key
    keys[i][0] = k1a; keys[i][1] = k1b;
    keys[i][2] = ha;  keys[i][3] = hb2;
    keys[i][4] = la;  keys[i][5] = lb2;
  }

  for (int i = 0; i < 3; i++) {
    const float* cw = (const float*)d_in[1 + 4 * i];
    const float* cb = (const float*)d_in[2 + 4 * i];
    const float* gw = (const float*)d_in[3 + 4 * i];
    const float* gb = (const float*)d_in[4 + 4 * i];
    const float* in = (i == 0) ? x0 : p_xbuf;
    int Cin = (i == 0) ? 257 : 256;
    conv_kernel<<<dim3(3, 2, BB), 128>>>(in, cw, cb, p_conv, Cin);
    gn_stats<<<BB * 16, 128>>>(p_conv, p_mu, p_rsig);
    interp_meta<<<2, 256>>>(p_gi, p_lam, keys[i][0], keys[i][1], keys[i][2],
                            keys[i][3], keys[i][4], keys[i][5]);
    interp_apply<<<BB, 192>>>(p_conv, p_gi, p_lam, p_mu, p_rsig, gw, gb, p_xbuf);
  }
  xg_gemm<<<dim3(3, 2, BB), 256>>>(p_xbuf, (const float*)d_in[13],
                                   (const float*)d_in[17], (const float*)d_in[15],
                                   (const float*)d_in[16], (const float*)d_in[19],
                                   (const float*)d_in[20], p_xg);
  lstm_kernel<<<dim3(64, 2), 256>>>(p_xg, (const float*)d_in[14],
                                    (const float*)d_in[18], (float*)d_out);
}

// round 5
// speedup vs baseline: 2.1551x; 2.1551x over previous
#include <cuda_runtime.h>
#include <cuda_bf16.h>
#include <math.h>

#define BB 512
#define TT 192
#define CC 256
#define NCH0 17           // layer0 ci chunks of 16 (257 -> 272)
#define ASTR 18           // smem row stride (bf16) for A/B tiles

typedef unsigned int u32;

// ---------------- scratch (device globals; no allocation) ----------------
__device__ float g_conv[(size_t)BB * CC * TT];    // conv output   [B,256,192]
__device__ float g_xbuf[(size_t)BB * CC * TT];    // interp output [B,256,192] fp32
__device__ float g_xg[(size_t)2 * BB * TT * 128]; // lstm pre-gates
__device__ float g_mu[BB * 16];
__device__ float g_rsig[BB * 16];
__device__ int   g_gi[BB * TT];
__device__ float g_lam[BB * TT];
// split-bf16 x image, chunk-major: [b][chunk<17][row 0..195][ci16]; row r <-> t=r-2
__device__ __nv_bfloat16 g_xh[(size_t)BB * NCH0 * 196 * 16];
__device__ __nv_bfloat16 g_xl[(size_t)BB * NCH0 * 196 * 16];
// split weights, chunk-major: [chunk][k 5][o 256][ci16]
__device__ __nv_bfloat16 g_wh[NCH0 * 5 * 256 * 16];
__device__ __nv_bfloat16 g_wl[NCH0 * 5 * 256 * 16];

// ---------------- threefry2x32 (JAX), host + device ----------------
__host__ __device__ __forceinline__ void tf2x32(unsigned k0, unsigned k1,
                                                unsigned x0, unsigned x1,
                                                unsigned& y0, unsigned& y1) {
  unsigned ks2 = k0 ^ k1 ^ 0x1BD11BDAu;
  x0 += k0; x1 += k1;
#define TFR(r) x0 += x1; x1 = (x1 << (r)) | (x1 >> (32 - (r))); x1 ^= x0;
  TFR(13) TFR(15) TFR(26) TFR(6)
  x0 += k1;  x1 += ks2 + 1u;
  TFR(17) TFR(29) TFR(16) TFR(24)
  x0 += ks2; x1 += k0 + 2u;
  TFR(13) TFR(15) TFR(26) TFR(6)
  x0 += k0;  x1 += k1 + 3u;
  TFR(17) TFR(29) TFR(16) TFR(24)
  x0 += k1;  x1 += ks2 + 4u;
  TFR(13) TFR(15) TFR(26) TFR(6)
  x0 += ks2; x1 += k0 + 5u;
#undef TFR
  y0 = x0; y1 = x1;
}

__device__ __forceinline__ unsigned tf_bits32(unsigned k0, unsigned k1, unsigned n) {
  unsigned y0, y1;
  tf2x32(k0, k1, 0u, n, y0, y1);
  return y0 ^ y1;
}

// ---------------- mma.sync m16n8k16 bf16 ----------------
__device__ __forceinline__ void mma16816(float* c, const u32* a, const u32* b) {
  asm volatile(
      "mma.sync.aligned.m16n8k16.row.col.f32.bf16.bf16.f32 "
      "{%0,%1,%2,%3}, {%4,%5,%6,%7}, {%8,%9}, {%0,%1,%2,%3};"
      : "+f"(c[0]), "+f"(c[1]), "+f"(c[2]), "+f"(c[3])
      : "r"(a[0]), "r"(a[1]), "r"(a[2]), "r"(a[3]), "r"(b[0]), "r"(b[1]));
}

// ---------------- weight prep: split bf16, chunk-major tiles ----------------
__global__ __launch_bounds__(256) void wprep(const float* __restrict__ w,
                                             int Cin, int NCH) {
  int chunk = blockIdx.x / 5, k = blockIdx.x % 5;
  int o = threadIdx.x;
  size_t base = (size_t)((chunk * 5 + k) * 256 + o) * 16;
  for (int cl = 0; cl < 16; cl++) {
    int ci = chunk * 16 + cl;
    float v = (ci < Cin) ? w[((size_t)o * Cin + ci) * 5 + k] : 0.f;
    __nv_bfloat16 h = __float2bfloat16(v);
    g_wh[base + cl] = h;
    g_wl[base + cl] = __float2bfloat16(v - __bfloat162float(h));
  }
}

// ---------------- x0 prep: transpose + split + pad ----------------
__global__ __launch_bounds__(256) void x0prep(const float* __restrict__ x) {
  int b = blockIdx.x;
  size_t ib = (size_t)b * NCH0 * 196 * 16;
  for (int idx = threadIdx.x; idx < NCH0 * 196 * 16; idx += 256) {
    int chunk = idx / (196 * 16);
    int rem = idx - chunk * 196 * 16;
    int row = rem >> 4, cl = rem & 15;
    int t = row - 2, ci = chunk * 16 + cl;
    float v = 0.f;
    if (t >= 0 && t < TT && ci < 257) v = x[((size_t)b * 257 + ci) * TT + t];
    __nv_bfloat16 h = __float2bfloat16(v);
    g_xh[ib + idx] = h;
    g_xl[ib + idx] = __float2bfloat16(v - __bfloat162float(h));
  }
}

// ---------------- HMMA conv: CTA = (oHalf, b); 128o x 192t ----------------
// smem: sA[10][128][ASTR] (k*2+split), sB[2][196][ASTR]
#define SA_ELEMS (10 * 128 * ASTR)
#define SB_ELEMS (2 * 196 * ASTR)
#define CONV_SMEM ((SA_ELEMS + SB_ELEMS) * 2)

__global__ __launch_bounds__(256) void mma_conv(const __nv_bfloat16* __restrict__ xh,
                                                const __nv_bfloat16* __restrict__ xl,
                                                const float* __restrict__ bias,
                                                float* __restrict__ out, int NCH) {
  extern __shared__ __nv_bfloat16 sm[];
  __nv_bfloat16* sA = sm;
  __nv_bfloat16* sB = sm + SA_ELEMS;
  int oHalf = blockIdx.x, b = blockIdx.y;
  int tid = threadIdx.x;
  int warp = tid >> 5, lane = tid & 31;
  int warpO = warp & 1, warpT = warp >> 1;
  int oBaseL = warpO * 64, tBase = warpT * 48;
  int lr = lane >> 2, lc = lane & 3;

  float acc[4][6][4];
#pragma unroll
  for (int ot = 0; ot < 4; ot++)
#pragma unroll
    for (int tt = 0; tt < 6; tt++)
#pragma unroll
      for (int q = 0; q < 4; q++) acc[ot][tt][q] = 0.f;

  const __nv_bfloat16* xsrc[2] = {xh + (size_t)b * NCH0 * 196 * 16,
                                  xl + (size_t)b * NCH0 * 196 * 16};
  for (int chunk = 0; chunk < NCH; chunk++) {
    // A fill: 10 tiles (5 taps x 2 splits) of 128x16, this CTA's o-half
    for (int i = tid; i < 10240; i += 256) {      // 32b units
      int ksp = i >> 10;                          // 0..9 : k*2+split
      int rem = i & 1023;
      int o = rem >> 3, cp = rem & 7;
      int k = ksp >> 1, sp = ksp & 1;
      const __nv_bfloat16* wsrc = sp ? g_wl : g_wh;
      u32 v = *(const u32*)(wsrc + ((size_t)((chunk * 5 + k) * 256 + oHalf * 128 + o) * 16 + cp * 2));
      *(u32*)(sA + (ksp * 128 + o) * ASTR + cp * 2) = v;
    }
    // B fill: 2 splits x 196 rows x 16
    for (int i = tid; i < 3136; i += 256) {
      int sp = i >= 1568;
      int rem = sp ? i - 1568 : i;
      int row = rem >> 3, cp = rem & 7;
      u32 v = *(const u32*)(xsrc[sp] + ((size_t)(chunk * 196 + row) * 16 + cp * 2));
      *(u32*)(sB + (sp * 196 + row) * ASTR + cp * 2) = v;
    }
    __syncthreads();
#pragma unroll 1
    for (int sp = 0; sp < 3; sp++) {
      int aSel = (sp == 2) ? 1 : 0;   // hh, hl, lh
      int bSel = (sp == 1) ? 1 : 0;
#pragma unroll
      for (int k = 0; k < 5; k++) {
        const __nv_bfloat16* A = sA + (size_t)(k * 2 + aSel) * 128 * ASTR;
        u32 af[4][4];
#pragma unroll
        for (int ot = 0; ot < 4; ot++) {
          int r0 = oBaseL + ot * 16 + lr;
          af[ot][0] = *(const u32*)(A + r0 * ASTR + lc * 2);
          af[ot][1] = *(const u32*)(A + (r0 + 8) * ASTR + lc * 2);
          af[ot][2] = *(const u32*)(A + r0 * ASTR + lc * 2 + 8);
          af[ot][3] = *(const u32*)(A + (r0 + 8) * ASTR + lc * 2 + 8);
        }
        const __nv_bfloat16* Bp = sB + (size_t)bSel * 196 * ASTR + (size_t)k * ASTR;
        u32 bfr[6][2];
#pragma unroll
        for (int tt = 0; tt < 6; tt++) {
          int trow = tBase + tt * 8 + lr;
          bfr[tt][0] = *(const u32*)(Bp + trow * ASTR + lc * 2);
          bfr[tt][1] = *(const u32*)(Bp + trow * ASTR + lc * 2 + 8);
        }
#pragma unroll
        for (int ot = 0; ot < 4; ot++)
#pragma unroll
          for (int tt = 0; tt < 6; tt++) mma16816(acc[ot][tt], af[ot], bfr[tt]);
      }
    }
    __syncthreads();
  }
  // epilogue
#pragma unroll
  for (int ot = 0; ot < 4; ot++) {
    int o0 = oHalf * 128 + oBaseL + ot * 16 + lr;
    float bv0 = bias[o0], bv1 = bias[o0 + 8];
    float* r0 = out + ((size_t)b * CC + o0) * TT;
    float* r1 = out + ((size_t)b * CC + o0 + 8) * TT;
#pragma unroll
    for (int tt = 0; tt < 6; tt++) {
      int t = tBase + tt * 8 + lc * 2;
      float2 v0 = {acc[ot][tt][0] + bv0, acc[ot][tt][1] + bv0};
      float2 v1 = {acc[ot][tt][2] + bv1, acc[ot][tt][3] + bv1};
      *(float2*)(r0 + t) = v0;
      *(float2*)(r1 + t) = v1;
    }
  }
}

// ---------------- GroupNorm stats ----------------
__global__ __launch_bounds__(128) void gn_stats(const float* __restrict__ conv,
                                                float* __restrict__ mu,
                                                float* __restrict__ rsig) {
  __shared__ float ss[128], ss2[128];
  int b = blockIdx.x >> 4, g = blockIdx.x & 15;
  const float* p = conv + ((size_t)b * CC + g * 16) * TT;
  float s = 0.f, s2 = 0.f;
  for (int i = threadIdx.x; i < 16 * TT; i += 128) {
    float v = p[i];
    s += v;
    s2 = fmaf(v, v, s2);
  }
  ss[threadIdx.x] = s; ss2[threadIdx.x] = s2;
  __syncthreads();
  for (int off = 64; off > 0; off >>= 1) {
    if (threadIdx.x < off) {
      ss[threadIdx.x] += ss[threadIdx.x + off];
      ss2[threadIdx.x] += ss2[threadIdx.x + off];
    }
    __syncthreads();
  }
  if (threadIdx.x == 0) {
    float m = ss[0] * (1.0f / 3072.0f);
    float var = ss2[0] * (1.0f / 3072.0f) - m * m;
    mu[blockIdx.x] = m;
    rsig[blockIdx.x] = rsqrtf(var + 1e-5f);
  }
}

// ---------------- interp_lnr metadata ----------------
__global__ void interp_meta(int* __restrict__ gi, float* __restrict__ lam,
                            unsigned u0, unsigned u1, unsigned a0, unsigned a1,
                            unsigned c0, unsigned c1) {
  int b = blockIdx.x * blockDim.x + threadIdx.x;
  if (b >= BB) return;
  int base = b * TT;
  for (int t = 0; t < TT; t++) gi[base + t] = -1;
  int off = 0, pos = 0;
  for (int s = 0; s < 7; s++) {
    unsigned n = (unsigned)(b * 7 + s);
    unsigned ub = tf_bits32(u0, u1, n);
    float f = __uint_as_float((ub >> 9) | 0x3f800000u) - 1.0f;
    float scale = f + 0.5f;
    unsigned hb = tf_bits32(a0, a1, n);
    unsigned lb = tf_bits32(c0, c1, n);
    unsigned offt = ((hb % 13u) * 9u + lb % 13u) % 13u;
    int len = 19 + (int)offt;
    float lenm1 = (float)(len - 1);
    for (int l = 0; l < 64; l++) {
      float idx = __fdiv_rn((float)l, scale);
      float fl = floorf(idx);
      float lm = idx - fl;
      if (fl < lenm1) {
        int io = (int)fl + off;
        if (io < TT - 1) {
          if (pos < TT) { gi[base + pos] = io; lam[base + pos] = lm; }
          pos++;
        }
      }
    }
    off += len;
  }
}

// ---------------- interp apply: GN + ReLU + lerp; fp32 out + split bf16 image ----------------
__global__ __launch_bounds__(192) void interp_apply(
    const float* __restrict__ conv, const int* __restrict__ gi,
    const float* __restrict__ lam, const float* __restrict__ mu,
    const float* __restrict__ rsig, const float* __restrict__ gnw,
    const float* __restrict__ gnb, float* __restrict__ out,
    __nv_bfloat16* __restrict__ xh, __nv_bfloat16* __restrict__ xl) {
  int b = blockIdx.x, t = threadIdx.x;
  __shared__ float smu[16], srs[16];
  __shared__ int sg[TT];
  __shared__ float sl[TT];
  if (t < 16) { smu[t] = mu[b * 16 + t]; srs[t] = rsig[b * 16 + t]; }
  sg[t] = gi[b * TT + t];
  sl[t] = lam[b * TT + t];
  __syncthreads();
  int g = sg[t];
  float lm = sl[t];
  const float* cb = conv + (size_t)b * CC * TT;
  float* ob = out + (size_t)b * CC * TT;
  size_t ib = (size_t)b * NCH0 * 196 * 16;
  for (int c = 0; c < CC; c++) {
    float val = 0.f;
    if (g >= 0) {
      float m = smu[c >> 4], rs = srs[c >> 4];
      float w = gnw[c], be = gnb[c];
      float a = cb[c * TT + g], e = cb[c * TT + g + 1];
      float fa = fmaxf((a - m) * rs * w + be, 0.f);
      float fb = fmaxf((e - m) * rs * w + be, 0.f);
      val = (1.0f - lm) * fa + lm * fb;
    }
    ob[c * TT + t] = val;
    size_t xi = ib + (size_t)((c >> 4) * 196 + t + 2) * 16 + (c & 15);
    __nv_bfloat16 h = __float2bfloat16(val);
    xh[xi] = h;
    xl[xi] = __float2bfloat16(val - __bfloat162float(h));
  }
  if (t < 4) {  // zero pad rows 0,1,194,195 for all 16 chunks
    int r = (t < 2) ? t : (192 + t);
    for (int ch = 0; ch < 16; ch++) {
      size_t xi = ib + (size_t)(ch * 196 + r) * 16;
      for (int cl = 0; cl < 16; cl++) {
        xh[xi + cl] = __float2bfloat16(0.f);
        xl[xi + cl] = __float2bfloat16(0.f);
      }
    }
  }
}

// ---------------- xg pre-gate GEMM ----------------
__global__ __launch_bounds__(256) void xg_gemm(
    const float* __restrict__ x, const float* __restrict__ wf,
    const float* __restrict__ wb, const float* __restrict__ bif,
    const float* __restrict__ bhf, const float* __restrict__ bib,
    const float* __restrict__ bhb, float* __restrict__ xg) {
  __shared__ float xs[8][64];
  __shared__ float ws[8][128];
  int d = blockIdx.y, b = blockIdx.z, tbase = blockIdx.x * 64;
  const float* w = d ? wb : wf;
  const float* bi = d ? bib : bif;
  const float* bh = d ? bhb : bhf;
  int tid = threadIdx.x, otid = tid & 15, ttid = tid >> 4;
  float acc[8][4];
#pragma unroll
  for (int u = 0; u < 8; u++)
#pragma unroll
    for (int v = 0; v < 4; v++) acc[u][v] = 0.f;
  const float* xb = x + (size_t)b * CC * TT;
  for (int ci0 = 0; ci0 < CC; ci0 += 8) {
    for (int idx = tid; idx < 512; idx += 256) {
      int i = idx >> 6, j = idx & 63;
      xs[i][j] = xb[(size_t)(ci0 + i) * TT + tbase + j];
    }
    for (int idx = tid; idx < 1024; idx += 256) {
      int o = idx >> 3, i = idx & 7;
      ws[i][o] = w[(size_t)o * CC + ci0 + i];
    }
    __syncthreads();
#pragma unroll
    for (int i = 0; i < 8; i++) {
      float xv[4];
#pragma unroll
      for (int v = 0; v < 4; v++) xv[v] = xs[i][ttid * 4 + v];
#pragma unroll
      for (int u = 0; u < 8; u++) {
        float wv = ws[i][otid + 16 * u];
#pragma unroll
        for (int v = 0; v < 4; v++) acc[u][v] = fmaf(wv, xv[v], acc[u][v]);
      }
    }
    __syncthreads();
  }
#pragma unroll
  for (int u = 0; u < 8; u++) {
    int g = otid + 16 * u;
    float bias = bi[g] + bh[g];
#pragma unroll
    for (int v = 0; v < 4; v++) {
      int t = tbase + ttid * 4 + v;
      xg[((size_t)(d * BB + b) * TT + t) * 128 + g] = acc[u][v] + bias;
    }
  }
}

// ---------------- LSTM recurrence: warp per batch element ----------------
__device__ __forceinline__ float sigf(float x) { return 1.0f / (1.0f + expf(-x)); }

__global__ __launch_bounds__(256) void lstm_kernel(
    const float* __restrict__ xg, const float* __restrict__ whf,
    const float* __restrict__ whb, float* __restrict__ out) {
  __shared__ float ws[32 * 128];
  int dir = blockIdx.y;
  const float* wh = dir ? whb : whf;
  int tid = threadIdx.x;
  for (int idx = tid; idx < 4096; idx += 256) {
    int j = idx >> 7, r = idx & 127;
    ws[idx] = wh[r * 32 + j];
  }
  __syncthreads();
  int warp = tid >> 5, lane = tid & 31;
  int b = blockIdx.x * 8 + warp;
  const float* xgb = xg + (size_t)(dir * BB + b) * TT * 128;
  float h = 0.f, c = 0.f;
  for (int step = 0; step < TT; step++) {
    int t = dir ? (TT - 1 - step) : step;
    const float* p = xgb + (size_t)t * 128;
    float gi = p[lane], gf = p[32 + lane], gg = p[64 + lane], go = p[96 + lane];
#pragma unroll
    for (int j = 0; j < 32; j++) {
      float hj = __shfl_sync(0xffffffffu, h, j);
      const float* wr = ws + j * 128;
      gi = fmaf(wr[lane], hj, gi);
      gf = fmaf(wr[32 + lane], hj, gf);
      gg = fmaf(wr[64 + lane], hj, gg);
      go = fmaf(wr[96 + lane], hj, go);
    }
    c = sigf(gf) * c + sigf(gi) * tanhf(gg);
    h = sigf(go) * tanhf(c);
    if (dir == 0) {
      if ((t & 7) == 7) out[((size_t)b * 24 + (t >> 3)) * 64 + lane] = h;
    } else {
      if ((t & 7) == 0) out[((size_t)b * 24 + (t >> 3)) * 64 + 32 + lane] = h;
    }
  }
}

// ---------------- launch ----------------
extern "C" void kernel_launch(void* const* d_in, const int* in_sizes, int n_in,
                              void* d_out, int out_size) {
  (void)in_sizes; (void)n_in; (void)out_size;
  float *p_conv, *p_xbuf, *p_xg, *p_mu, *p_rsig, *p_lam;
  int* p_gi;
  __nv_bfloat16 *p_xh, *p_xl;
  cudaGetSymbolAddress((void**)&p_conv, g_conv);
  cudaGetSymbolAddress((void**)&p_xbuf, g_xbuf);
  cudaGetSymbolAddress((void**)&p_xg, g_xg);
  cudaGetSymbolAddress((void**)&p_mu, g_mu);
  cudaGetSymbolAddress((void**)&p_rsig, g_rsig);
  cudaGetSymbolAddress((void**)&p_gi, g_gi);
  cudaGetSymbolAddress((void**)&p_lam, g_lam);
  cudaGetSymbolAddress((void**)&p_xh, g_xh);
  cudaGetSymbolAddress((void**)&p_xl, g_xl);

  static int smem_set = 0;
  if (!smem_set) {
    cudaFuncSetAttribute(mma_conv, cudaFuncAttributeMaxDynamicSharedMemorySize, CONV_SMEM);
    smem_set = 1;
  }

  const float* x0 = (const float*)d_in[0];

  // JAX threefry keys: rng = key(42); per layer i: fold_in -> split -> randint split
  unsigned keys[3][6];
  for (int i = 0; i < 3; i++) {
    unsigned f0, f1;
    tf2x32(0u, 42u, 0u, (unsigned)i, f0, f1);
    unsigned k1a, k1b, k2a, k2b;
    tf2x32(f0, f1, 0u, 0u, k1a, k1b);
    tf2x32(f0, f1, 0u, 1u, k2a, k2b);
    unsigned ha, hb2, la, lb2;
    tf2x32(k2a, k2b, 0u, 0u, ha, hb2);
    tf2x32(k2a, k2b, 0u, 1u, la, lb2);
    keys[i][0] = k1a; keys[i][1] = k1b;
    keys[i][2] = ha;  keys[i][3] = hb2;
    keys[i][4] = la;  keys[i][5] = lb2;
  }

  x0prep<<<BB, 256>>>(x0);
  for (int i = 0; i < 3; i++) {
    const float* cw = (const float*)d_in[1 + 4 * i];
    const float* cb = (const float*)d_in[2 + 4 * i];
    const float* gw = (const float*)d_in[3 + 4 * i];
    const float* gb = (const float*)d_in[4 + 4 * i];
    int Cin = (i == 0) ? 257 : 256;
    int NCH = (i == 0) ? 17 : 16;
    wprep<<<NCH * 5, 256>>>(cw, Cin, NCH);
    mma_conv<<<dim3(2, BB), 256, CONV_SMEM>>>(p_xh, p_xl, cb, p_conv, NCH);
    gn_stats<<<BB * 16, 128>>>(p_conv, p_mu, p_rsig);
    interp_meta<<<2, 256>>>(p_gi, p_lam, keys[i][0], keys[i][1], keys[i][2],
                            keys[i][3], keys[i][4], keys[i][5]);
    interp_apply<<<BB, 192>>>(p_conv, p_gi, p_lam, p_mu, p_rsig, gw, gb, p_xbuf,
                              p_xh, p_xl);
  }
  xg_gemm<<<dim3(3, 2, BB), 256>>>(p_xbuf, (const float*)d_in[13],
                                   (const float*)d_in[17], (const float*)d_in[15],
                                   (const float*)d_in[16], (const float*)d_in[19],
                                   (const float*)d_in[20], p_xg);
  lstm_kernel<<<dim3(64, 2), 256>>>(p_xg, (const float*)d_in[14],
                                    (const float*)d_in[18], (float*)d_out);
}

// round 6
// speedup vs baseline: 2.3270x; 1.0798x over previous
#include <cuda_runtime.h>
#include <cuda_bf16.h>
#include <math.h>

#define BB 512
#define TT 192
#define CC 256
#define NCH0 17           // layer0 ci chunks of 16 (257 -> 272)
#define ASTR 18           // smem row stride (bf16) for A/B tiles

typedef unsigned int u32;

// ---------------- scratch (device globals; no allocation) ----------------
__device__ float g_conv[(size_t)BB * CC * TT];    // conv output   [B,256,192]
__device__ float g_xg[(size_t)2 * BB * TT * 128]; // lstm pre-gates [dir,B,T,128]
__device__ float g_mu[BB * 16];
__device__ float g_rsig[BB * 16];
__device__ int   g_gi[BB * TT];
__device__ float g_lam[BB * TT];
// split-bf16 x image, chunk-major: [b][chunk<17][row 0..195][ci16]; row r <-> t=r-2
__device__ __nv_bfloat16 g_xh[(size_t)BB * NCH0 * 196 * 16];
__device__ __nv_bfloat16 g_xl[(size_t)BB * NCH0 * 196 * 16];
// split conv weights, chunk-major: [chunk][k 5][o 256][ci16]
__device__ __nv_bfloat16 g_wh[NCH0 * 5 * 256 * 16];
__device__ __nv_bfloat16 g_wl[NCH0 * 5 * 256 * 16];
// split xg weights: [dir 2][chunk 16][g 128][ci16]
__device__ __nv_bfloat16 g_wxh[2 * 16 * 128 * 16];
__device__ __nv_bfloat16 g_wxl[2 * 16 * 128 * 16];

// ---------------- threefry2x32 (JAX), host + device ----------------
__host__ __device__ __forceinline__ void tf2x32(unsigned k0, unsigned k1,
                                                unsigned x0, unsigned x1,
                                                unsigned& y0, unsigned& y1) {
  unsigned ks2 = k0 ^ k1 ^ 0x1BD11BDAu;
  x0 += k0; x1 += k1;
#define TFR(r) x0 += x1; x1 = (x1 << (r)) | (x1 >> (32 - (r))); x1 ^= x0;
  TFR(13) TFR(15) TFR(26) TFR(6)
  x0 += k1;  x1 += ks2 + 1u;
  TFR(17) TFR(29) TFR(16) TFR(24)
  x0 += ks2; x1 += k0 + 2u;
  TFR(13) TFR(15) TFR(26) TFR(6)
  x0 += k0;  x1 += k1 + 3u;
  TFR(17) TFR(29) TFR(16) TFR(24)
  x0 += k1;  x1 += ks2 + 4u;
  TFR(13) TFR(15) TFR(26) TFR(6)
  x0 += ks2; x1 += k0 + 5u;
#undef TFR
  y0 = x0; y1 = x1;
}

__device__ __forceinline__ unsigned tf_bits32(unsigned k0, unsigned k1, unsigned n) {
  unsigned y0, y1;
  tf2x32(k0, k1, 0u, n, y0, y1);
  return y0 ^ y1;
}

// ---------------- mma.sync m16n8k16 bf16 ----------------
__device__ __forceinline__ void mma16816(float* c, const u32* a, const u32* b) {
  asm volatile(
      "mma.sync.aligned.m16n8k16.row.col.f32.bf16.bf16.f32 "
      "{%0,%1,%2,%3}, {%4,%5,%6,%7}, {%8,%9}, {%0,%1,%2,%3};"
      : "+f"(c[0]), "+f"(c[1]), "+f"(c[2]), "+f"(c[3])
      : "r"(a[0]), "r"(a[1]), "r"(a[2]), "r"(a[3]), "r"(b[0]), "r"(b[1]));
}

// ---------------- conv weight prep ----------------
__global__ __launch_bounds__(256) void wprep(const float* __restrict__ w,
                                             int Cin, int NCH) {
  int chunk = blockIdx.x / 5, k = blockIdx.x % 5;
  int o = threadIdx.x;
  size_t base = (size_t)((chunk * 5 + k) * 256 + o) * 16;
  for (int cl = 0; cl < 16; cl++) {
    int ci = chunk * 16 + cl;
    float v = (ci < Cin) ? w[((size_t)o * Cin + ci) * 5 + k] : 0.f;
    __nv_bfloat16 h = __float2bfloat16(v);
    g_wh[base + cl] = h;
    g_wl[base + cl] = __float2bfloat16(v - __bfloat162float(h));
  }
}

// ---------------- xg weight prep: [dir][chunk][g][ci] ----------------
__global__ __launch_bounds__(128) void wprep_xg(const float* __restrict__ wf,
                                                const float* __restrict__ wb) {
  int dir = blockIdx.x >> 4, chunk = blockIdx.x & 15;
  int g = threadIdx.x;
  const float* w = dir ? wb : wf;
  size_t base = (size_t)((dir * 16 + chunk) * 128 + g) * 16;
  for (int cl = 0; cl < 16; cl++) {
    float v = w[(size_t)g * CC + chunk * 16 + cl];
    __nv_bfloat16 h = __float2bfloat16(v);
    g_wxh[base + cl] = h;
    g_wxl[base + cl] = __float2bfloat16(v - __bfloat162float(h));
  }
}

// ---------------- x0 prep: transpose + split + pad ----------------
__global__ __launch_bounds__(256) void x0prep(const float* __restrict__ x) {
  int b = blockIdx.x;
  size_t ib = (size_t)b * NCH0 * 196 * 16;
  for (int idx = threadIdx.x; idx < NCH0 * 196 * 16; idx += 256) {
    int chunk = idx / (196 * 16);
    int rem = idx - chunk * 196 * 16;
    int row = rem >> 4, cl = rem & 15;
    int t = row - 2, ci = chunk * 16 + cl;
    float v = 0.f;
    if (t >= 0 && t < TT && ci < 257) v = x[((size_t)b * 257 + ci) * TT + t];
    __nv_bfloat16 h = __float2bfloat16(v);
    g_xh[ib + idx] = h;
    g_xl[ib + idx] = __float2bfloat16(v - __bfloat162float(h));
  }
}

// ---------------- HMMA conv: CTA = (oHalf, b); 128o x 192t ----------------
#define SA_ELEMS (10 * 128 * ASTR)
#define SB_ELEMS (2 * 196 * ASTR)
#define CONV_SMEM ((SA_ELEMS + SB_ELEMS) * 2)

__global__ __launch_bounds__(256) void mma_conv(const __nv_bfloat16* __restrict__ xh,
                                                const __nv_bfloat16* __restrict__ xl,
                                                const float* __restrict__ bias,
                                                float* __restrict__ out, int NCH) {
  extern __shared__ __nv_bfloat16 sm[];
  __nv_bfloat16* sA = sm;
  __nv_bfloat16* sB = sm + SA_ELEMS;
  int oHalf = blockIdx.x, b = blockIdx.y;
  int tid = threadIdx.x;
  int warp = tid >> 5, lane = tid & 31;
  int warpO = warp & 1, warpT = warp >> 1;
  int oBaseL = warpO * 64, tBase = warpT * 48;
  int lr = lane >> 2, lc = lane & 3;

  float acc[4][6][4];
#pragma unroll
  for (int ot = 0; ot < 4; ot++)
#pragma unroll
    for (int tt = 0; tt < 6; tt++)
#pragma unroll
      for (int q = 0; q < 4; q++) acc[ot][tt][q] = 0.f;

  const __nv_bfloat16* xsrc[2] = {xh + (size_t)b * NCH0 * 196 * 16,
                                  xl + (size_t)b * NCH0 * 196 * 16};
  for (int chunk = 0; chunk < NCH; chunk++) {
    for (int i = tid; i < 10240; i += 256) {
      int ksp = i >> 10;
      int rem = i & 1023;
      int o = rem >> 3, cp = rem & 7;
      int k = ksp >> 1, sp = ksp & 1;
      const __nv_bfloat16* wsrc = sp ? g_wl : g_wh;
      u32 v = *(const u32*)(wsrc + ((size_t)((chunk * 5 + k) * 256 + oHalf * 128 + o) * 16 + cp * 2));
      *(u32*)(sA + (ksp * 128 + o) * ASTR + cp * 2) = v;
    }
    for (int i = tid; i < 3136; i += 256) {
      int sp = i >= 1568;
      int rem = sp ? i - 1568 : i;
      int row = rem >> 3, cp = rem & 7;
      u32 v = *(const u32*)(xsrc[sp] + ((size_t)(chunk * 196 + row) * 16 + cp * 2));
      *(u32*)(sB + (sp * 196 + row) * ASTR + cp * 2) = v;
    }
    __syncthreads();
#pragma unroll 1
    for (int sp = 0; sp < 3; sp++) {
      int aSel = (sp == 2) ? 1 : 0;   // hh, hl, lh
      int bSel = (sp == 1) ? 1 : 0;
#pragma unroll
      for (int k = 0; k < 5; k++) {
        const __nv_bfloat16* A = sA + (size_t)(k * 2 + aSel) * 128 * ASTR;
        u32 af[4][4];
#pragma unroll
        for (int ot = 0; ot < 4; ot++) {
          int r0 = oBaseL + ot * 16 + lr;
          af[ot][0] = *(const u32*)(A + r0 * ASTR + lc * 2);
          af[ot][1] = *(const u32*)(A + (r0 + 8) * ASTR + lc * 2);
          af[ot][2] = *(const u32*)(A + r0 * ASTR + lc * 2 + 8);
          af[ot][3] = *(const u32*)(A + (r0 + 8) * ASTR + lc * 2 + 8);
        }
        const __nv_bfloat16* Bp = sB + (size_t)bSel * 196 * ASTR + (size_t)k * ASTR;
        u32 bfr[6][2];
#pragma unroll
        for (int tt = 0; tt < 6; tt++) {
          int trow = tBase + tt * 8 + lr;
          bfr[tt][0] = *(const u32*)(Bp + trow * ASTR + lc * 2);
          bfr[tt][1] = *(const u32*)(Bp + trow * ASTR + lc * 2 + 8);
        }
#pragma unroll
        for (int ot = 0; ot < 4; ot++)
#pragma unroll
          for (int tt = 0; tt < 6; tt++) mma16816(acc[ot][tt], af[ot], bfr[tt]);
      }
    }
    __syncthreads();
  }
#pragma unroll
  for (int ot = 0; ot < 4; ot++) {
    int o0 = oHalf * 128 + oBaseL + ot * 16 + lr;
    float bv0 = bias[o0], bv1 = bias[o0 + 8];
    float* r0 = out + ((size_t)b * CC + o0) * TT;
    float* r1 = out + ((size_t)b * CC + o0 + 8) * TT;
#pragma unroll
    for (int tt = 0; tt < 6; tt++) {
      int t = tBase + tt * 8 + lc * 2;
      float2 v0 = {acc[ot][tt][0] + bv0, acc[ot][tt][1] + bv0};
      float2 v1 = {acc[ot][tt][2] + bv1, acc[ot][tt][3] + bv1};
      *(float2*)(r0 + t) = v0;
      *(float2*)(r1 + t) = v1;
    }
  }
}

// ---------------- HMMA xg GEMM: CTA = (dir, b); 128g x 192t, K=256 ----------------
#define XA_ELEMS (2 * 128 * ASTR)
#define XB_ELEMS (2 * 192 * ASTR)
#define XG_SMEM_MAIN ((XA_ELEMS + XB_ELEMS) * 2)
#define XG_SMEM_STAGE (48 * 132 * 4)
#define XG_SMEM (XG_SMEM_MAIN > XG_SMEM_STAGE ? XG_SMEM_MAIN : XG_SMEM_STAGE)

__global__ __launch_bounds__(256) void xg_mma(
    const __nv_bfloat16* __restrict__ xh, const __nv_bfloat16* __restrict__ xl,
    const float* __restrict__ bif, const float* __restrict__ bhf,
    const float* __restrict__ bib, const float* __restrict__ bhb,
    float* __restrict__ xg) {
  extern __shared__ char xsm[];
  __nv_bfloat16* sA = (__nv_bfloat16*)xsm;            // [2][128][ASTR]
  __nv_bfloat16* sB = sA + XA_ELEMS;                  // [2][192][ASTR]
  float* stage = (float*)xsm;                         // [48][132], reused
  int dir = blockIdx.x, b = blockIdx.y;
  const float* bi = dir ? bib : bif;
  const float* bh = dir ? bhb : bhf;
  int tid = threadIdx.x;
  int warp = tid >> 5, lane = tid & 31;
  int warpO = warp & 1, warpT = warp >> 1;
  int oBaseL = warpO * 64, tBase = warpT * 48;
  int lr = lane >> 2, lc = lane & 3;

  float acc[4][6][4];
#pragma unroll
  for (int ot = 0; ot < 4; ot++)
#pragma unroll
    for (int tt = 0; tt < 6; tt++)
#pragma unroll
      for (int q = 0; q < 4; q++) acc[ot][tt][q] = 0.f;

  const __nv_bfloat16* xsrc[2] = {xh + (size_t)b * NCH0 * 196 * 16,
                                  xl + (size_t)b * NCH0 * 196 * 16};
  for (int chunk = 0; chunk < 16; chunk++) {
    // A: 2 splits x 128 g x 16ci
    for (int i = tid; i < 2048; i += 256) {
      int sp = i >> 10;
      int rem = i & 1023;
      int o = rem >> 3, cp = rem & 7;
      const __nv_bfloat16* wsrc = sp ? g_wxl : g_wxh;
      u32 v = *(const u32*)(wsrc + ((size_t)((dir * 16 + chunk) * 128 + o) * 16 + cp * 2));
      *(u32*)(sA + (sp * 128 + o) * ASTR + cp * 2) = v;
    }
    // B: 2 splits x 192 rows (image rows 2..193) x 16
    for (int i = tid; i < 3072; i += 256) {
      int sp = i >= 1536;
      int rem = sp ? i - 1536 : i;
      int row = rem >> 3, cp = rem & 7;
      u32 v = *(const u32*)(xsrc[sp] + ((size_t)(chunk * 196 + 2 + row) * 16 + cp * 2));
      *(u32*)(sB + (sp * 192 + row) * ASTR + cp * 2) = v;
    }
    __syncthreads();
#pragma unroll 1
    for (int sp = 0; sp < 3; sp++) {
      int aSel = (sp == 2) ? 1 : 0;
      int bSel = (sp == 1) ? 1 : 0;
      const __nv_bfloat16* A = sA + (size_t)aSel * 128 * ASTR;
      u32 af[4][4];
#pragma unroll
      for (int ot = 0; ot < 4; ot++) {
        int r0 = oBaseL + ot * 16 + lr;
        af[ot][0] = *(const u32*)(A + r0 * ASTR + lc * 2);
        af[ot][1] = *(const u32*)(A + (r0 + 8) * ASTR + lc * 2);
        af[ot][2] = *(const u32*)(A + r0 * ASTR + lc * 2 + 8);
        af[ot][3] = *(const u32*)(A + (r0 + 8) * ASTR + lc * 2 + 8);
      }
      const __nv_bfloat16* Bp = sB + (size_t)bSel * 192 * ASTR;
      u32 bfr[6][2];
#pragma unroll
      for (int tt = 0; tt < 6; tt++) {
        int trow = tBase + tt * 8 + lr;
        bfr[tt][0] = *(const u32*)(Bp + trow * ASTR + lc * 2);
        bfr[tt][1] = *(const u32*)(Bp + trow * ASTR + lc * 2 + 8);
      }
#pragma unroll
      for (int ot = 0; ot < 4; ot++)
#pragma unroll
        for (int tt = 0; tt < 6; tt++) mma16816(acc[ot][tt], af[ot], bfr[tt]);
    }
    __syncthreads();
  }
  // epilogue: smem-transposed coalesced stores into [t][128] layout
  float* xgb = xg + (size_t)(dir * BB + b) * TT * 128;
  for (int q = 0; q < 4; q++) {
    __syncthreads();
    if (warpT == q) {
#pragma unroll
      for (int ot = 0; ot < 4; ot++) {
        int o0 = oBaseL + ot * 16 + lr;
#pragma unroll
        for (int tt = 0; tt < 6; tt++) {
          int tl = tt * 8 + lc * 2;
          stage[tl * 132 + o0] = acc[ot][tt][0];
          stage[(tl + 1) * 132 + o0] = acc[ot][tt][1];
          stage[tl * 132 + o0 + 8] = acc[ot][tt][2];
          stage[(tl + 1) * 132 + o0 + 8] = acc[ot][tt][3];
        }
      }
    }
    __syncthreads();
    for (int i = tid; i < 6144; i += 256) {
      int tl = i >> 7, g = i & 127;
      xgb[(size_t)(q * 48 + tl) * 128 + g] =
          stage[tl * 132 + g] + __ldg(bi + g) + __ldg(bh + g);
    }
  }
}

// ---------------- GroupNorm stats ----------------
__global__ __launch_bounds__(128) void gn_stats(const float* __restrict__ conv,
                                                float* __restrict__ mu,
                                                float* __restrict__ rsig) {
  __shared__ float ss[128], ss2[128];
  int b = blockIdx.x >> 4, g = blockIdx.x & 15;
  const float* p = conv + ((size_t)b * CC + g * 16) * TT;
  float s = 0.f, s2 = 0.f;
  for (int i = threadIdx.x; i < 16 * TT; i += 128) {
    float v = p[i];
    s += v;
    s2 = fmaf(v, v, s2);
  }
  ss[threadIdx.x] = s; ss2[threadIdx.x] = s2;
  __syncthreads();
  for (int off = 64; off > 0; off >>= 1) {
    if (threadIdx.x < off) {
      ss[threadIdx.x] += ss[threadIdx.x + off];
      ss2[threadIdx.x] += ss2[threadIdx.x + off];
    }
    __syncthreads();
  }
  if (threadIdx.x == 0) {
    float m = ss[0] * (1.0f / 3072.0f);
    float var = ss2[0] * (1.0f / 3072.0f) - m * m;
    mu[blockIdx.x] = m;
    rsig[blockIdx.x] = rsqrtf(var + 1e-5f);
  }
}

// ---------------- interp_lnr metadata ----------------
__global__ void interp_meta(int* __restrict__ gi, float* __restrict__ lam,
                            unsigned u0, unsigned u1, unsigned a0, unsigned a1,
                            unsigned c0, unsigned c1) {
  int b = blockIdx.x * blockDim.x + threadIdx.x;
  if (b >= BB) return;
  int base = b * TT;
  for (int t = 0; t < TT; t++) gi[base + t] = -1;
  int off = 0, pos = 0;
  for (int s = 0; s < 7; s++) {
    unsigned n = (unsigned)(b * 7 + s);
    unsigned ub = tf_bits32(u0, u1, n);
    float f = __uint_as_float((ub >> 9) | 0x3f800000u) - 1.0f;
    float scale = f + 0.5f;
    unsigned hb = tf_bits32(a0, a1, n);
    unsigned lb = tf_bits32(c0, c1, n);
    unsigned offt = ((hb % 13u) * 9u + lb % 13u) % 13u;
    int len = 19 + (int)offt;
    float lenm1 = (float)(len - 1);
    for (int l = 0; l < 64; l++) {
      float idx = __fdiv_rn((float)l, scale);
      float fl = floorf(idx);
      float lm = idx - fl;
      if (fl < lenm1) {
        int io = (int)fl + off;
        if (io < TT - 1) {
          if (pos < TT) { gi[base + pos] = io; lam[base + pos] = lm; }
          pos++;
        }
      }
    }
    off += len;
  }
}

// ---------------- interp apply: GN + ReLU + lerp -> split bf16 image ----------------
// grid (BB, 4): 64 channels per block for latency hiding
__global__ __launch_bounds__(192) void interp_apply(
    const float* __restrict__ conv, const int* __restrict__ gi,
    const float* __restrict__ lam, const float* __restrict__ mu,
    const float* __restrict__ rsig, const float* __restrict__ gnw,
    const float* __restrict__ gnb,
    __nv_bfloat16* __restrict__ xh, __nv_bfloat16* __restrict__ xl) {
  int b = blockIdx.x, t = threadIdx.x;
  int cbase = blockIdx.y * 64;
  __shared__ float smu[16], srs[16];
  __shared__ int sg[TT];
  __shared__ float sl[TT];
  if (t < 16) { smu[t] = mu[b * 16 + t]; srs[t] = rsig[b * 16 + t]; }
  sg[t] = gi[b * TT + t];
  sl[t] = lam[b * TT + t];
  __syncthreads();
  int g = sg[t];
  float lm = sl[t];
  const float* cb = conv + (size_t)b * CC * TT;
  size_t ib = (size_t)b * NCH0 * 196 * 16;
  for (int cc = 0; cc < 64; cc++) {
    int c = cbase + cc;
    float val = 0.f;
    if (g >= 0) {
      float m = smu[c >> 4], rs = srs[c >> 4];
      float w = gnw[c], be = gnb[c];
      float a = cb[c * TT + g], e = cb[c * TT + g + 1];
      float fa = fmaxf((a - m) * rs * w + be, 0.f);
      float fb = fmaxf((e - m) * rs * w + be, 0.f);
      val = (1.0f - lm) * fa + lm * fb;
    }
    size_t xi = ib + (size_t)((c >> 4) * 196 + t + 2) * 16 + (c & 15);
    __nv_bfloat16 h = __float2bfloat16(val);
    xh[xi] = h;
    xl[xi] = __float2bfloat16(val - __bfloat162float(h));
  }
  if (blockIdx.y == 0 && t < 4) {  // zero pad rows 0,1,194,195 for 16 chunks
    int r = (t < 2) ? t : (192 + t);
    for (int ch = 0; ch < 16; ch++) {
      size_t xi = ib + (size_t)(ch * 196 + r) * 16;
      for (int cl = 0; cl < 16; cl++) {
        xh[xi + cl] = __float2bfloat16(0.f);
        xl[xi + cl] = __float2bfloat16(0.f);
      }
    }
  }
}

// ---------------- LSTM recurrence: warp per batch element ----------------
__device__ __forceinline__ float sigf(float x) { return 1.0f / (1.0f + expf(-x)); }

__global__ __launch_bounds__(256) void lstm_kernel(
    const float* __restrict__ xg, const float* __restrict__ whf,
    const float* __restrict__ whb, float* __restrict__ out) {
  __shared__ float ws[32 * 128];
  int dir = blockIdx.y;
  const float* wh = dir ? whb : whf;
  int tid = threadIdx.x;
  for (int idx = tid; idx < 4096; idx += 256) {
    int j = idx >> 7, r = idx & 127;
    ws[idx] = wh[r * 32 + j];
  }
  __syncthreads();
  int warp = tid >> 5, lane = tid & 31;
  int b = blockIdx.x * 8 + warp;
  const float* xgb = xg + (size_t)(dir * BB + b) * TT * 128;
  float h = 0.f, c = 0.f;
  for (int step = 0; step < TT; step++) {
    int t = dir ? (TT - 1 - step) : step;
    const float* p = xgb + (size_t)t * 128;
    float gi = p[lane], gf = p[32 + lane], gg = p[64 + lane], go = p[96 + lane];
#pragma unroll
    for (int j = 0; j < 32; j++) {
      float hj = __shfl_sync(0xffffffffu, h, j);
      const float* wr = ws + j * 128;
      gi = fmaf(wr[lane], hj, gi);
      gf = fmaf(wr[32 + lane], hj, gf);
      gg = fmaf(wr[64 + lane], hj, gg);
      go = fmaf(wr[96 + lane], hj, go);
    }
    c = sigf(gf) * c + sigf(gi) * tanhf(gg);
    h = sigf(go) * tanhf(c);
    if (dir == 0) {
      if ((t & 7) == 7) out[((size_t)b * 24 + (t >> 3)) * 64 + lane] = h;
    } else {
      if ((t & 7) == 0) out[((size_t)b * 24 + (t >> 3)) * 64 + 32 + lane] = h;
    }
  }
}

// ---------------- launch ----------------
extern "C" void kernel_launch(void* const* d_in, const int* in_sizes, int n_in,
                              void* d_out, int out_size) {
  (void)in_sizes; (void)n_in; (void)out_size;
  float *p_conv, *p_xg, *p_mu, *p_rsig, *p_lam;
  int* p_gi;
  __nv_bfloat16 *p_xh, *p_xl;
  cudaGetSymbolAddress((void**)&p_conv, g_conv);
  cudaGetSymbolAddress((void**)&p_xg, g_xg);
  cudaGetSymbolAddress((void**)&p_mu, g_mu);
  cudaGetSymbolAddress((void**)&p_rsig, g_rsig);
  cudaGetSymbolAddress((void**)&p_gi, g_gi);
  cudaGetSymbolAddress((void**)&p_lam, g_lam);
  cudaGetSymbolAddress((void**)&p_xh, g_xh);
  cudaGetSymbolAddress((void**)&p_xl, g_xl);

  static int smem_set = 0;
  if (!smem_set) {
    cudaFuncSetAttribute(mma_conv, cudaFuncAttributeMaxDynamicSharedMemorySize, CONV_SMEM);
    cudaFuncSetAttribute(xg_mma, cudaFuncAttributeMaxDynamicSharedMemorySize, XG_SMEM);
    smem_set = 1;
  }

  const float* x0 = (const float*)d_in[0];

  // JAX threefry keys: rng = key(42); per layer i: fold_in -> split -> randint split
  unsigned keys[3][6];
  for (int i = 0; i < 3; i++) {
    unsigned f0, f1;
    tf2x32(0u, 42u, 0u, (unsigned)i, f0, f1);
    unsigned k1a, k1b, k2a, k2b;
    tf2x32(f0, f1, 0u, 0u, k1a, k1b);
    tf2x32(f0, f1, 0u, 1u, k2a, k2b);
    unsigned ha, hb2, la, lb2;
    tf2x32(k2a, k2b, 0u, 0u, ha, hb2);
    tf2x32(k2a, k2b, 0u, 1u, la, lb2);
    keys[i][0] = k1a; keys[i][1] = k1b;
    keys[i][2] = ha;  keys[i][3] = hb2;
    keys[i][4] = la;  keys[i][5] = lb2;
  }

  x0prep<<<BB, 256>>>(x0);
  wprep_xg<<<32, 128>>>((const float*)d_in[13], (const float*)d_in[17]);
  for (int i = 0; i < 3; i++) {
    const float* cw = (const float*)d_in[1 + 4 * i];
    const float* cb = (const float*)d_in[2 + 4 * i];
    const float* gw = (const float*)d_in[3 + 4 * i];
    const float* gb = (const float*)d_in[4 + 4 * i];
    int Cin = (i == 0) ? 257 : 256;
    int NCH = (i == 0) ? 17 : 16;
    wprep<<<NCH * 5, 256>>>(cw, Cin, NCH);
    mma_conv<<<dim3(2, BB), 256, CONV_SMEM>>>(p_xh, p_xl, cb, p_conv, NCH);
    gn_stats<<<BB * 16, 128>>>(p_conv, p_mu, p_rsig);
    interp_meta<<<2, 256>>>(p_gi, p_lam, keys[i][0], keys[i][1], keys[i][2],
                            keys[i][3], keys[i][4], keys[i][5]);
    interp_apply<<<dim3(BB, 4), 192>>>(p_conv, p_gi, p_lam, p_mu, p_rsig, gw, gb,
                                       p_xh, p_xl);
  }
  xg_mma<<<dim3(2, BB), 256, XG_SMEM>>>(p_xh, p_xl, (const float*)d_in[15],
                                        (const float*)d_in[16], (const float*)d_in[19],
                                        (const float*)d_in[20], p_xg);
  lstm_kernel<<<dim3(64, 2), 256>>>(p_xg, (const float*)d_in[14],
                                    (const float*)d_in[18], (float*)d_out);
}

// round 7
// speedup vs baseline: 2.6885x; 1.1553x over previous
#include <cuda_runtime.h>
#include <cuda_bf16.h>
#include <math.h>

#define BB 512
#define TT 192
#define CC 256
#define NCH0 17           // layer0 ci chunks of 16 (257 -> 272)
#define ASTR 24           // smem row stride (bf16); 48B rows, 16B-aligned, LDSM-conflict-free

typedef unsigned int u32;

// ---------------- scratch (device globals; no allocation) ----------------
__device__ float g_conv[(size_t)BB * CC * TT];    // conv output   [B,256,192]
__device__ float g_xg[(size_t)2 * BB * TT * 128]; // lstm pre-gates [dir,B,T,128]
__device__ float g_mu[BB * 16];
__device__ float g_rsig[BB * 16];
__device__ int   g_gi[BB * TT];
__device__ float g_lam[BB * TT];
// split-bf16 x image, chunk-major: [b][chunk<17][row 0..195][ci16]; row r <-> t=r-2
__device__ __nv_bfloat16 g_xh[(size_t)BB * NCH0 * 196 * 16];
__device__ __nv_bfloat16 g_xl[(size_t)BB * NCH0 * 196 * 16];
// split conv weights, chunk-major: [chunk][k 5][o 256][ci16]
__device__ __nv_bfloat16 g_wh[NCH0 * 5 * 256 * 16];
__device__ __nv_bfloat16 g_wl[NCH0 * 5 * 256 * 16];
// split xg weights: [dir 2][chunk 16][g 128][ci16]
__device__ __nv_bfloat16 g_wxh[2 * 16 * 128 * 16];
__device__ __nv_bfloat16 g_wxl[2 * 16 * 128 * 16];

// ---------------- threefry2x32 (JAX), host + device ----------------
__host__ __device__ __forceinline__ void tf2x32(unsigned k0, unsigned k1,
                                                unsigned x0, unsigned x1,
                                                unsigned& y0, unsigned& y1) {
  unsigned ks2 = k0 ^ k1 ^ 0x1BD11BDAu;
  x0 += k0; x1 += k1;
#define TFR(r) x0 += x1; x1 = (x1 << (r)) | (x1 >> (32 - (r))); x1 ^= x0;
  TFR(13) TFR(15) TFR(26) TFR(6)
  x0 += k1;  x1 += ks2 + 1u;
  TFR(17) TFR(29) TFR(16) TFR(24)
  x0 += ks2; x1 += k0 + 2u;
  TFR(13) TFR(15) TFR(26) TFR(6)
  x0 += k0;  x1 += k1 + 3u;
  TFR(17) TFR(29) TFR(16) TFR(24)
  x0 += k1;  x1 += ks2 + 4u;
  TFR(13) TFR(15) TFR(26) TFR(6)
  x0 += ks2; x1 += k0 + 5u;
#undef TFR
  y0 = x0; y1 = x1;
}

__device__ __forceinline__ unsigned tf_bits32(unsigned k0, unsigned k1, unsigned n) {
  unsigned y0, y1;
  tf2x32(k0, k1, 0u, n, y0, y1);
  return y0 ^ y1;
}

// ---------------- mma.sync + ldmatrix ----------------
__device__ __forceinline__ void mma16816(float* c, const u32* a, const u32* b) {
  asm volatile(
      "mma.sync.aligned.m16n8k16.row.col.f32.bf16.bf16.f32 "
      "{%0,%1,%2,%3}, {%4,%5,%6,%7}, {%8,%9}, {%0,%1,%2,%3};"
      : "+f"(c[0]), "+f"(c[1]), "+f"(c[2]), "+f"(c[3])
      : "r"(a[0]), "r"(a[1]), "r"(a[2]), "r"(a[3]), "r"(b[0]), "r"(b[1]));
}

__device__ __forceinline__ void ldsm4(u32* r, unsigned addr) {
  asm volatile("ldmatrix.sync.aligned.m8n8.x4.shared.b16 {%0,%1,%2,%3}, [%4];"
               : "=r"(r[0]), "=r"(r[1]), "=r"(r[2]), "=r"(r[3]) : "r"(addr));
}

// ---------------- conv weight prep ----------------
__global__ __launch_bounds__(256) void wprep(const float* __restrict__ w,
                                             int Cin, int NCH) {
  int chunk = blockIdx.x / 5, k = blockIdx.x % 5;
  int o = threadIdx.x;
  size_t base = (size_t)((chunk * 5 + k) * 256 + o) * 16;
  for (int cl = 0; cl < 16; cl++) {
    int ci = chunk * 16 + cl;
    float v = (ci < Cin) ? w[((size_t)o * Cin + ci) * 5 + k] : 0.f;
    __nv_bfloat16 h = __float2bfloat16(v);
    g_wh[base + cl] = h;
    g_wl[base + cl] = __float2bfloat16(v - __bfloat162float(h));
  }
}

// ---------------- xg weight prep: [dir][chunk][g][ci] ----------------
__global__ __launch_bounds__(128) void wprep_xg(const float* __restrict__ wf,
                                                const float* __restrict__ wb) {
  int dir = blockIdx.x >> 4, chunk = blockIdx.x & 15;
  int g = threadIdx.x;
  const float* w = dir ? wb : wf;
  size_t base = (size_t)((dir * 16 + chunk) * 128 + g) * 16;
  for (int cl = 0; cl < 16; cl++) {
    float v = w[(size_t)g * CC + chunk * 16 + cl];
    __nv_bfloat16 h = __float2bfloat16(v);
    g_wxh[base + cl] = h;
    g_wxl[base + cl] = __float2bfloat16(v - __bfloat162float(h));
  }
}

// ---------------- x0 prep: transpose + split + pad ----------------
__global__ __launch_bounds__(256) void x0prep(const float* __restrict__ x) {
  int b = blockIdx.x;
  size_t ib = (size_t)b * NCH0 * 196 * 16;
  for (int idx = threadIdx.x; idx < NCH0 * 196 * 16; idx += 256) {
    int chunk = idx / (196 * 16);
    int rem = idx - chunk * 196 * 16;
    int row = rem >> 4, cl = rem & 15;
    int t = row - 2, ci = chunk * 16 + cl;
    float v = 0.f;
    if (t >= 0 && t < TT && ci < 257) v = x[((size_t)b * 257 + ci) * TT + t];
    __nv_bfloat16 h = __float2bfloat16(v);
    g_xh[ib + idx] = h;
    g_xl[ib + idx] = __float2bfloat16(v - __bfloat162float(h));
  }
}

// ---------------- HMMA conv: CTA = (oHalf, b); 128o x 192t ----------------
#define SA_ELEMS (10 * 128 * ASTR)
#define SB_ELEMS (2 * 196 * ASTR)
#define CONV_SMEM ((SA_ELEMS + SB_ELEMS) * 2)

__global__ __launch_bounds__(256, 2) void mma_conv(
    const __nv_bfloat16* __restrict__ xh, const __nv_bfloat16* __restrict__ xl,
    const float* __restrict__ bias, float* __restrict__ out, int NCH) {
  extern __shared__ __nv_bfloat16 sm[];
  __nv_bfloat16* sA = sm;
  __nv_bfloat16* sB = sm + SA_ELEMS;
  int oHalf = blockIdx.x, b = blockIdx.y;
  int tid = threadIdx.x;
  int warp = tid >> 5, lane = tid & 31;
  int warpO = warp & 1, warpT = warp >> 1;
  int oBaseL = warpO * 64, tBase = warpT * 48;
  int lr = lane >> 2, lc = lane & 3;

  unsigned sbA = (unsigned)__cvta_generic_to_shared(sA);
  unsigned sbB = (unsigned)__cvta_generic_to_shared(sB);
  // per-lane ldmatrix offsets (bytes)
  unsigned rowA_off = ((oBaseL + (lane & 7) + ((lane >> 3) & 1) * 8) * ASTR +
                       ((lane >> 4) & 1) * 8) * 2;
  unsigned rowB_off = ((tBase + (lane & 7) + ((lane >> 4) & 1) * 8) * ASTR +
                       ((lane >> 3) & 1) * 8) * 2;

  float acc[4][6][4];
#pragma unroll
  for (int ot = 0; ot < 4; ot++)
#pragma unroll
    for (int tt = 0; tt < 6; tt++)
#pragma unroll
      for (int q = 0; q < 4; q++) acc[ot][tt][q] = 0.f;

  const __nv_bfloat16* xsrc[2] = {xh + (size_t)b * NCH0 * 196 * 16,
                                  xl + (size_t)b * NCH0 * 196 * 16};
  for (int chunk = 0; chunk < NCH; chunk++) {
    for (int i = tid; i < 10240; i += 256) {
      int ksp = i >> 10;
      int rem = i & 1023;
      int o = rem >> 3, cp = rem & 7;
      int k = ksp >> 1, sp = ksp & 1;
      const __nv_bfloat16* wsrc = sp ? g_wl : g_wh;
      u32 v = *(const u32*)(wsrc + ((size_t)((chunk * 5 + k) * 256 + oHalf * 128 + o) * 16 + cp * 2));
      *(u32*)(sA + (ksp * 128 + o) * ASTR + cp * 2) = v;
    }
    for (int i = tid; i < 3136; i += 256) {
      int sp = i >= 1568;
      int rem = sp ? i - 1568 : i;
      int row = rem >> 3, cp = rem & 7;
      u32 v = *(const u32*)(xsrc[sp] + ((size_t)(chunk * 196 + row) * 16 + cp * 2));
      *(u32*)(sB + (sp * 196 + row) * ASTR + cp * 2) = v;
    }
    __syncthreads();
#pragma unroll 1
    for (int sp = 0; sp < 3; sp++) {
      int aSel = (sp == 2) ? 1 : 0;   // hh, hl, lh
      int bSel = (sp == 1) ? 1 : 0;
      unsigned baseB = sbB + (unsigned)(bSel * 196 * ASTR * 2) + rowB_off;
#pragma unroll
      for (int k = 0; k < 5; k++) {
        u32 bfr[6][2];
#pragma unroll
        for (int q = 0; q < 3; q++)
          ldsm4(&bfr[2 * q][0], baseB + (unsigned)((q * 16 + k) * ASTR * 2));
        unsigned baseA = sbA + (unsigned)((k * 2 + aSel) * 128 * ASTR * 2) + rowA_off;
#pragma unroll
        for (int ot = 0; ot < 4; ot++) {
          u32 af[4];
          ldsm4(af, baseA + (unsigned)(ot * 16 * ASTR * 2));
#pragma unroll
          for (int tt = 0; tt < 6; tt++) mma16816(acc[ot][tt], af, bfr[tt]);
        }
      }
    }
    __syncthreads();
  }
#pragma unroll
  for (int ot = 0; ot < 4; ot++) {
    int o0 = oHalf * 128 + oBaseL + ot * 16 + lr;
    float bv0 = bias[o0], bv1 = bias[o0 + 8];
    float* r0 = out + ((size_t)b * CC + o0) * TT;
    float* r1 = out + ((size_t)b * CC + o0 + 8) * TT;
#pragma unroll
    for (int tt = 0; tt < 6; tt++) {
      int t = tBase + tt * 8 + lc * 2;
      float2 v0 = {acc[ot][tt][0] + bv0, acc[ot][tt][1] + bv0};
      float2 v1 = {acc[ot][tt][2] + bv1, acc[ot][tt][3] + bv1};
      *(float2*)(r0 + t) = v0;
      *(float2*)(r1 + t) = v1;
    }
  }
}

// ---------------- HMMA xg GEMM: CTA = (dir, b); 128g x 192t, K=256 ----------------
#define XA_ELEMS (2 * 128 * ASTR)
#define XB_ELEMS (2 * 192 * ASTR)
#define XG_SMEM_MAIN ((XA_ELEMS + XB_ELEMS) * 2)
#define XG_SMEM_STAGE (48 * 132 * 4)
#define XG_SMEM (XG_SMEM_MAIN > XG_SMEM_STAGE ? XG_SMEM_MAIN : XG_SMEM_STAGE)

__global__ __launch_bounds__(256) void xg_mma(
    const __nv_bfloat16* __restrict__ xh, const __nv_bfloat16* __restrict__ xl,
    const float* __restrict__ bif, const float* __restrict__ bhf,
    const float* __restrict__ bib, const float* __restrict__ bhb,
    float* __restrict__ xg) {
  extern __shared__ char xsm[];
  __nv_bfloat16* sA = (__nv_bfloat16*)xsm;            // [2][128][ASTR]
  __nv_bfloat16* sB = sA + XA_ELEMS;                  // [2][192][ASTR]
  float* stage = (float*)xsm;                         // [48][132], reused
  int dir = blockIdx.x, b = blockIdx.y;
  const float* bi = dir ? bib : bif;
  const float* bh = dir ? bhb : bhf;
  int tid = threadIdx.x;
  int warp = tid >> 5, lane = tid & 31;
  int warpO = warp & 1, warpT = warp >> 1;
  int oBaseL = warpO * 64, tBase = warpT * 48;
  int lr = lane >> 2, lc = lane & 3;

  unsigned sbA = (unsigned)__cvta_generic_to_shared(sA);
  unsigned sbB = (unsigned)__cvta_generic_to_shared(sB);
  unsigned rowA_off = ((oBaseL + (lane & 7) + ((lane >> 3) & 1) * 8) * ASTR +
                       ((lane >> 4) & 1) * 8) * 2;
  unsigned rowB_off = ((tBase + (lane & 7) + ((lane >> 4) & 1) * 8) * ASTR +
                       ((lane >> 3) & 1) * 8) * 2;

  float acc[4][6][4];
#pragma unroll
  for (int ot = 0; ot < 4; ot++)
#pragma unroll
    for (int tt = 0; tt < 6; tt++)
#pragma unroll
      for (int q = 0; q < 4; q++) acc[ot][tt][q] = 0.f;

  const __nv_bfloat16* xsrc[2] = {xh + (size_t)b * NCH0 * 196 * 16,
                                  xl + (size_t)b * NCH0 * 196 * 16};
  for (int chunk = 0; chunk < 16; chunk++) {
    for (int i = tid; i < 2048; i += 256) {
      int sp = i >> 10;
      int rem = i & 1023;
      int o = rem >> 3, cp = rem & 7;
      const __nv_bfloat16* wsrc = sp ? g_wxl : g_wxh;
      u32 v = *(const u32*)(wsrc + ((size_t)((dir * 16 + chunk) * 128 + o) * 16 + cp * 2));
      *(u32*)(sA + (sp * 128 + o) * ASTR + cp * 2) = v;
    }
    for (int i = tid; i < 3072; i += 256) {
      int sp = i >= 1536;
      int rem = sp ? i - 1536 : i;
      int row = rem >> 3, cp = rem & 7;
      u32 v = *(const u32*)(xsrc[sp] + ((size_t)(chunk * 196 + 2 + row) * 16 + cp * 2));
      *(u32*)(sB + (sp * 192 + row) * ASTR + cp * 2) = v;
    }
    __syncthreads();
#pragma unroll 1
    for (int sp = 0; sp < 3; sp++) {
      int aSel = (sp == 2) ? 1 : 0;
      int bSel = (sp == 1) ? 1 : 0;
      u32 bfr[6][2];
      unsigned baseB = sbB + (unsigned)(bSel * 192 * ASTR * 2) + rowB_off;
#pragma unroll
      for (int q = 0; q < 3; q++)
        ldsm4(&bfr[2 * q][0], baseB + (unsigned)(q * 16 * ASTR * 2));
      unsigned baseA = sbA + (unsigned)(aSel * 128 * ASTR * 2) + rowA_off;
#pragma unroll
      for (int ot = 0; ot < 4; ot++) {
        u32 af[4];
        ldsm4(af, baseA + (unsigned)(ot * 16 * ASTR * 2));
#pragma unroll
        for (int tt = 0; tt < 6; tt++) mma16816(acc[ot][tt], af, bfr[tt]);
      }
    }
    __syncthreads();
  }
  // epilogue: smem-transposed coalesced stores into [t][128] layout
  float* xgb = xg + (size_t)(dir * BB + b) * TT * 128;
  for (int q = 0; q < 4; q++) {
    __syncthreads();
    if (warpT == q) {
#pragma unroll
      for (int ot = 0; ot < 4; ot++) {
        int o0 = oBaseL + ot * 16 + lr;
#pragma unroll
        for (int tt = 0; tt < 6; tt++) {
          int tl = tt * 8 + lc * 2;
          stage[tl * 132 + o0] = acc[ot][tt][0];
          stage[(tl + 1) * 132 + o0] = acc[ot][tt][1];
          stage[tl * 132 + o0 + 8] = acc[ot][tt][2];
          stage[(tl + 1) * 132 + o0 + 8] = acc[ot][tt][3];
        }
      }
    }
    __syncthreads();
    for (int i = tid; i < 6144; i += 256) {
      int tl = i >> 7, g = i & 127;
      xgb[(size_t)(q * 48 + tl) * 128 + g] =
          stage[tl * 132 + g] + __ldg(bi + g) + __ldg(bh + g);
    }
  }
}

// ---------------- GroupNorm stats ----------------
__global__ __launch_bounds__(128) void gn_stats(const float* __restrict__ conv,
                                                float* __restrict__ mu,
                                                float* __restrict__ rsig) {
  __shared__ float ss[128], ss2[128];
  int b = blockIdx.x >> 4, g = blockIdx.x & 15;
  const float* p = conv + ((size_t)b * CC + g * 16) * TT;
  float s = 0.f, s2 = 0.f;
  for (int i = threadIdx.x; i < 16 * TT; i += 128) {
    float v = p[i];
    s += v;
    s2 = fmaf(v, v, s2);
  }
  ss[threadIdx.x] = s; ss2[threadIdx.x] = s2;
  __syncthreads();
  for (int off = 64; off > 0; off >>= 1) {
    if (threadIdx.x < off) {
      ss[threadIdx.x] += ss[threadIdx.x + off];
      ss2[threadIdx.x] += ss2[threadIdx.x + off];
    }
    __syncthreads();
  }
  if (threadIdx.x == 0) {
    float m = ss[0] * (1.0f / 3072.0f);
    float var = ss2[0] * (1.0f / 3072.0f) - m * m;
    mu[blockIdx.x] = m;
    rsig[blockIdx.x] = rsqrtf(var + 1e-5f);
  }
}

// ---------------- interp_lnr metadata ----------------
__global__ void interp_meta(int* __restrict__ gi, float* __restrict__ lam,
                            unsigned u0, unsigned u1, unsigned a0, unsigned a1,
                            unsigned c0, unsigned c1) {
  int b = blockIdx.x * blockDim.x + threadIdx.x;
  if (b >= BB) return;
  int base = b * TT;
  for (int t = 0; t < TT; t++) gi[base + t] = -1;
  int off = 0, pos = 0;
  for (int s = 0; s < 7; s++) {
    unsigned n = (unsigned)(b * 7 + s);
    unsigned ub = tf_bits32(u0, u1, n);
    float f = __uint_as_float((ub >> 9) | 0x3f800000u) - 1.0f;
    float scale = f + 0.5f;
    unsigned hb = tf_bits32(a0, a1, n);
    unsigned lb = tf_bits32(c0, c1, n);
    unsigned offt = ((hb % 13u) * 9u + lb % 13u) % 13u;
    int len = 19 + (int)offt;
    float lenm1 = (float)(len - 1);
    for (int l = 0; l < 64; l++) {
      float idx = __fdiv_rn((float)l, scale);
      float fl = floorf(idx);
      float lm = idx - fl;
      if (fl < lenm1) {
        int io = (int)fl + off;
        if (io < TT - 1) {
          if (pos < TT) { gi[base + pos] = io; lam[base + pos] = lm; }
          pos++;
        }
      }
    }
    off += len;
  }
}

// ---------------- interp apply: GN + ReLU + lerp -> split bf16 image ----------------
__global__ __launch_bounds__(192) void interp_apply(
    const float* __restrict__ conv, const int* __restrict__ gi,
    const float* __restrict__ lam, const float* __restrict__ mu,
    const float* __restrict__ rsig, const float* __restrict__ gnw,
    const float* __restrict__ gnb,
    __nv_bfloat16* __restrict__ xh, __nv_bfloat16* __restrict__ xl) {
  int b = blockIdx.x, t = threadIdx.x;
  int cbase = blockIdx.y * 64;
  __shared__ float smu[16], srs[16];
  __shared__ int sg[TT];
  __shared__ float sl[TT];
  if (t < 16) { smu[t] = mu[b * 16 + t]; srs[t] = rsig[b * 16 + t]; }
  sg[t] = gi[b * TT + t];
  sl[t] = lam[b * TT + t];
  __syncthreads();
  int g = sg[t];
  float lm = sl[t];
  const float* cb = conv + (size_t)b * CC * TT;
  size_t ib = (size_t)b * NCH0 * 196 * 16;
  for (int cc = 0; cc < 64; cc++) {
    int c = cbase + cc;
    float val = 0.f;
    if (g >= 0) {
      float m = smu[c >> 4], rs = srs[c >> 4];
      float w = gnw[c], be = gnb[c];
      float a = cb[c * TT + g], e = cb[c * TT + g + 1];
      float fa = fmaxf((a - m) * rs * w + be, 0.f);
      float fb = fmaxf((e - m) * rs * w + be, 0.f);
      val = (1.0f - lm) * fa + lm * fb;
    }
    size_t xi = ib + (size_t)((c >> 4) * 196 + t + 2) * 16 + (c & 15);
    __nv_bfloat16 h = __float2bfloat16(val);
    xh[xi] = h;
    xl[xi] = __float2bfloat16(val - __bfloat162float(h));
  }
  if (blockIdx.y == 0 && t < 4) {  // zero pad rows 0,1,194,195 for 16 chunks
    int r = (t < 2) ? t : (192 + t);
    for (int ch = 0; ch < 16; ch++) {
      size_t xi = ib + (size_t)(ch * 196 + r) * 16;
      for (int cl = 0; cl < 16; cl++) {
        xh[xi + cl] = __float2bfloat16(0.f);
        xl[xi + cl] = __float2bfloat16(0.f);
      }
    }
  }
}

// ---------------- LSTM recurrence: warp per batch element ----------------
__device__ __forceinline__ float sigf(float x) { return 1.0f / (1.0f + expf(-x)); }

__global__ __launch_bounds__(256) void lstm_kernel(
    const float* __restrict__ xg, const float* __restrict__ whf,
    const float* __restrict__ whb, float* __restrict__ out) {
  __shared__ float ws[32 * 128];
  int dir = blockIdx.y;
  const float* wh = dir ? whb : whf;
  int tid = threadIdx.x;
  for (int idx = tid; idx < 4096; idx += 256) {
    int j = idx >> 7, r = idx & 127;
    ws[idx] = wh[r * 32 + j];
  }
  __syncthreads();
  int warp = tid >> 5, lane = tid & 31;
  int b = blockIdx.x * 8 + warp;
  const float* xgb = xg + (size_t)(dir * BB + b) * TT * 128;
  float h = 0.f, c = 0.f;
  for (int step = 0; step < TT; step++) {
    int t = dir ? (TT - 1 - step) : step;
    const float* p = xgb + (size_t)t * 128;
    float gi = p[lane], gf = p[32 + lane], gg = p[64 + lane], go = p[96 + lane];
#pragma unroll
    for (int j = 0; j < 32; j++) {
      float hj = __shfl_sync(0xffffffffu, h, j);
      const float* wr = ws + j * 128;
      gi = fmaf(wr[lane], hj, gi);
      gf = fmaf(wr[32 + lane], hj, gf);
      gg = fmaf(wr[64 + lane], hj, gg);
      go = fmaf(wr[96 + lane], hj, go);
    }
    c = sigf(gf) * c + sigf(gi) * tanhf(gg);
    h = sigf(go) * tanhf(c);
    if (dir == 0) {
      if ((t & 7) == 7) out[((size_t)b * 24 + (t >> 3)) * 64 + lane] = h;
    } else {
      if ((t & 7) == 0) out[((size_t)b * 24 + (t >> 3)) * 64 + 32 + lane] = h;
    }
  }
}

// ---------------- launch ----------------
extern "C" void kernel_launch(void* const* d_in, const int* in_sizes, int n_in,
                              void* d_out, int out_size) {
  (void)in_sizes; (void)n_in; (void)out_size;
  float *p_conv, *p_xg, *p_mu, *p_rsig, *p_lam;
  int* p_gi;
  __nv_bfloat16 *p_xh, *p_xl;
  cudaGetSymbolAddress((void**)&p_conv, g_conv);
  cudaGetSymbolAddress((void**)&p_xg, g_xg);
  cudaGetSymbolAddress((void**)&p_mu, g_mu);
  cudaGetSymbolAddress((void**)&p_rsig, g_rsig);
  cudaGetSymbolAddress((void**)&p_gi, g_gi);
  cudaGetSymbolAddress((void**)&p_lam, g_lam);
  cudaGetSymbolAddress((void**)&p_xh, g_xh);
  cudaGetSymbolAddress((void**)&p_xl, g_xl);

  static int smem_set = 0;
  if (!smem_set) {
    cudaFuncSetAttribute(mma_conv, cudaFuncAttributeMaxDynamicSharedMemorySize, CONV_SMEM);
    cudaFuncSetAttribute(xg_mma, cudaFuncAttributeMaxDynamicSharedMemorySize, XG_SMEM);
    smem_set = 1;
  }

  const float* x0 = (const float*)d_in[0];

  // JAX threefry keys: rng = key(42); per layer i: fold_in -> split -> randint split
  unsigned keys[3][6];
  for (int i = 0; i < 3; i++) {
    unsigned f0, f1;
    tf2x32(0u, 42u, 0u, (unsigned)i, f0, f1);
    unsigned k1a, k1b, k2a, k2b;
    tf2x32(f0, f1, 0u, 0u, k1a, k1b);
    tf2x32(f0, f1, 0u, 1u, k2a, k2b);
    unsigned ha, hb2, la, lb2;
    tf2x32(k2a, k2b, 0u, 0u, ha, hb2);
    tf2x32(k2a, k2b, 0u, 1u, la, lb2);
    keys[i][0] = k1a; keys[i][1] = k1b;
    keys[i][2] = ha;  keys[i][3] = hb2;
    keys[i][4] = la;  keys[i][5] = lb2;
  }

  x0prep<<<BB, 256>>>(x0);
  wprep_xg<<<32, 128>>>((const float*)d_in[13], (const float*)d_in[17]);
  for (int i = 0; i < 3; i++) {
    const float* cw = (const float*)d_in[1 + 4 * i];
    const float* cb = (const float*)d_in[2 + 4 * i];
    const float* gw = (const float*)d_in[3 + 4 * i];
    const float* gb = (const float*)d_in[4 + 4 * i];
    int Cin = (i == 0) ? 257 : 256;
    int NCH = (i == 0) ? 17 : 16;
    wprep<<<NCH * 5, 256>>>(cw, Cin, NCH);
    mma_conv<<<dim3(2, BB), 256, CONV_SMEM>>>(p_xh, p_xl, cb, p_conv, NCH);
    gn_stats<<<BB * 16, 128>>>(p_conv, p_mu, p_rsig);
    interp_meta<<<2, 256>>>(p_gi, p_lam, keys[i][0], keys[i][1], keys[i][2],
                            keys[i][3], keys[i][4], keys[i][5]);
    interp_apply<<<dim3(BB, 4), 192>>>(p_conv, p_gi, p_lam, p_mu, p_rsig, gw, gb,
                                       p_xh, p_xl);
  }
  xg_mma<<<dim3(2, BB), 256, XG_SMEM>>>(p_xh, p_xl, (const float*)d_in[15],
                                        (const float*)d_in[16], (const float*)d_in[19],
                                        (const float*)d_in[20], p_xg);
  lstm_kernel<<<dim3(64, 2), 256>>>(p_xg, (const float*)d_in[14],
                                    (const float*)d_in[18], (float*)d_out);
}

// round 8
// speedup vs baseline: 3.1609x; 1.1757x over previous
#include <cuda_runtime.h>
#include <cuda_bf16.h>
#include <math.h>

#define BB 512
#define TT 192
#define CC 256
#define NCH0 17           // layer0 ci chunks of 16 (257 -> 272)
#define ASTR 24           // smem row stride (bf16); 48B rows, 16B-aligned, LDSM-conflict-free

typedef unsigned int u32;

// ---------------- scratch (device globals; no allocation) ----------------
__device__ float g_conv[(size_t)BB * CC * TT];    // conv output   [B,256,192]
__device__ float g_xg[(size_t)2 * BB * TT * 128]; // lstm pre-gates [dir,B,T,128]
__device__ float g_mu[BB * 16];
__device__ float g_rsig[BB * 16];
__device__ int   g_gi[BB * TT];
__device__ float g_lam[BB * TT];
// split-bf16 x image, chunk-major: [b][chunk<17][row 0..195][ci16]; row r <-> t=r-2
__device__ __nv_bfloat16 g_xh[(size_t)BB * NCH0 * 196 * 16];
__device__ __nv_bfloat16 g_xl[(size_t)BB * NCH0 * 196 * 16];
// split conv weights, chunk-major: [chunk][k 5][o 256][ci16]
__device__ __nv_bfloat16 g_wh[NCH0 * 5 * 256 * 16];
__device__ __nv_bfloat16 g_wl[NCH0 * 5 * 256 * 16];
// split xg weights: [dir 2][chunk 16][g 128][ci16]
__device__ __nv_bfloat16 g_wxh[2 * 16 * 128 * 16];
__device__ __nv_bfloat16 g_wxl[2 * 16 * 128 * 16];

// ---------------- threefry2x32 (JAX), host + device ----------------
__host__ __device__ __forceinline__ void tf2x32(unsigned k0, unsigned k1,
                                                unsigned x0, unsigned x1,
                                                unsigned& y0, unsigned& y1) {
  unsigned ks2 = k0 ^ k1 ^ 0x1BD11BDAu;
  x0 += k0; x1 += k1;
#define TFR(r) x0 += x1; x1 = (x1 << (r)) | (x1 >> (32 - (r))); x1 ^= x0;
  TFR(13) TFR(15) TFR(26) TFR(6)
  x0 += k1;  x1 += ks2 + 1u;
  TFR(17) TFR(29) TFR(16) TFR(24)
  x0 += ks2; x1 += k0 + 2u;
  TFR(13) TFR(15) TFR(26) TFR(6)
  x0 += k0;  x1 += k1 + 3u;
  TFR(17) TFR(29) TFR(16) TFR(24)
  x0 += k1;  x1 += ks2 + 4u;
  TFR(13) TFR(15) TFR(26) TFR(6)
  x0 += ks2; x1 += k0 + 5u;
#undef TFR
  y0 = x0; y1 = x1;
}

__device__ __forceinline__ unsigned tf_bits32(unsigned k0, unsigned k1, unsigned n) {
  unsigned y0, y1;
  tf2x32(k0, k1, 0u, n, y0, y1);
  return y0 ^ y1;
}

// ---------------- mma.sync + ldmatrix + cp.async ----------------
__device__ __forceinline__ void mma16816(float* c, const u32* a, const u32* b) {
  asm volatile(
      "mma.sync.aligned.m16n8k16.row.col.f32.bf16.bf16.f32 "
      "{%0,%1,%2,%3}, {%4,%5,%6,%7}, {%8,%9}, {%0,%1,%2,%3};"
      : "+f"(c[0]), "+f"(c[1]), "+f"(c[2]), "+f"(c[3])
      : "r"(a[0]), "r"(a[1]), "r"(a[2]), "r"(a[3]), "r"(b[0]), "r"(b[1]));
}

__device__ __forceinline__ void ldsm4(u32* r, unsigned addr) {
  asm volatile("ldmatrix.sync.aligned.m8n8.x4.shared.b16 {%0,%1,%2,%3}, [%4];"
               : "=r"(r[0]), "=r"(r[1]), "=r"(r[2]), "=r"(r[3]) : "r"(addr));
}

__device__ __forceinline__ void cpasync16(unsigned d, const void* g) {
  asm volatile("cp.async.cg.shared.global [%0], [%1], 16;" :: "r"(d), "l"(g));
}
#define CP_COMMIT() asm volatile("cp.async.commit_group;" ::: "memory")

// ---------------- conv weight prep ----------------
__global__ __launch_bounds__(256) void wprep(const float* __restrict__ w,
                                             int Cin, int NCH) {
  int chunk = blockIdx.x / 5, k = blockIdx.x % 5;
  int o = threadIdx.x;
  size_t base = (size_t)((chunk * 5 + k) * 256 + o) * 16;
  for (int cl = 0; cl < 16; cl++) {
    int ci = chunk * 16 + cl;
    float v = (ci < Cin) ? w[((size_t)o * Cin + ci) * 5 + k] : 0.f;
    __nv_bfloat16 h = __float2bfloat16(v);
    g_wh[base + cl] = h;
    g_wl[base + cl] = __float2bfloat16(v - __bfloat162float(h));
  }
}

// ---------------- xg weight prep: [dir][chunk][g][ci] ----------------
__global__ __launch_bounds__(128) void wprep_xg(const float* __restrict__ wf,
                                                const float* __restrict__ wb) {
  int dir = blockIdx.x >> 4, chunk = blockIdx.x & 15;
  int g = threadIdx.x;
  const float* w = dir ? wb : wf;
  size_t base = (size_t)((dir * 16 + chunk) * 128 + g) * 16;
  for (int cl = 0; cl < 16; cl++) {
    float v = w[(size_t)g * CC + chunk * 16 + cl];
    __nv_bfloat16 h = __float2bfloat16(v);
    g_wxh[base + cl] = h;
    g_wxl[base + cl] = __float2bfloat16(v - __bfloat162float(h));
  }
}

// ---------------- x0 prep: transpose + split + pad ----------------
__global__ __launch_bounds__(256) void x0prep(const float* __restrict__ x) {
  int b = blockIdx.x;
  size_t ib = (size_t)b * NCH0 * 196 * 16;
  for (int idx = threadIdx.x; idx < NCH0 * 196 * 16; idx += 256) {
    int chunk = idx / (196 * 16);
    int rem = idx - chunk * 196 * 16;
    int row = rem >> 4, cl = rem & 15;
    int t = row - 2, ci = chunk * 16 + cl;
    float v = 0.f;
    if (t >= 0 && t < TT && ci < 257) v = x[((size_t)b * 257 + ci) * TT + t];
    __nv_bfloat16 h = __float2bfloat16(v);
    g_xh[ib + idx] = h;
    g_xl[ib + idx] = __float2bfloat16(v - __bfloat162float(h));
  }
}

// ---------------- HMMA conv: CTA = (oHalf, b); 128o x 192t; 2-stage cp.async ----------------
#define SA_ELEMS (10 * 128 * ASTR)
#define SB_ELEMS (2 * 196 * ASTR)
#define STAGE_ELEMS (SA_ELEMS + SB_ELEMS)
#define CONV_SMEM (STAGE_ELEMS * 2 * 2)

__device__ __forceinline__ void conv_fill(int chunk, unsigned sstage, int oHalf,
                                          const __nv_bfloat16* xbh,
                                          const __nv_bfloat16* xbl, int tid) {
  // A: 10 tiles (k*2+sp) x 128 o x 16 ci = 2560 16B-chunks
  for (int i = tid; i < 2560; i += 256) {
    int ksp = i >> 8;
    int rem = i & 255;
    int o = rem >> 1, half = rem & 1;
    int k = ksp >> 1, sp = ksp & 1;
    const __nv_bfloat16* wsrc = sp ? g_wl : g_wh;
    const void* g = wsrc + ((size_t)((chunk * 5 + k) * 256 + oHalf * 128 + o) * 16 + half * 8);
    unsigned d = sstage + (unsigned)(((ksp * 128 + o) * ASTR + half * 8) * 2);
    cpasync16(d, g);
  }
  // B: 2 splits x 196 rows x 16 = 784 16B-chunks
  for (int i = tid; i < 784; i += 256) {
    int sp = i >= 392;
    int rem = sp ? i - 392 : i;
    int row = rem >> 1, half = rem & 1;
    const __nv_bfloat16* xs = sp ? xbl : xbh;
    const void* g = xs + ((size_t)(chunk * 196 + row) * 16 + half * 8);
    unsigned d = sstage + (unsigned)((SA_ELEMS + (sp * 196 + row) * ASTR + half * 8) * 2);
    cpasync16(d, g);
  }
}

__global__ __launch_bounds__(256, 1) void mma_conv(
    const __nv_bfloat16* __restrict__ xh, const __nv_bfloat16* __restrict__ xl,
    const float* __restrict__ bias, float* __restrict__ out, int NCH) {
  extern __shared__ __nv_bfloat16 sm[];
  int oHalf = blockIdx.x, b = blockIdx.y;
  int tid = threadIdx.x;
  int warp = tid >> 5, lane = tid & 31;
  int warpO = warp & 1, warpT = warp >> 1;
  int oBaseL = warpO * 64, tBase = warpT * 48;
  int lr = lane >> 2, lc = lane & 3;

  unsigned sb0 = (unsigned)__cvta_generic_to_shared(sm);
  // per-lane ldmatrix offsets (bytes, relative to sA/sB stage base)
  unsigned rowA_off = ((oBaseL + (lane & 7) + ((lane >> 3) & 1) * 8) * ASTR +
                       ((lane >> 4) & 1) * 8) * 2;
  unsigned rowB_off = ((tBase + (lane & 7) + ((lane >> 4) & 1) * 8) * ASTR +
                       ((lane >> 3) & 1) * 8) * 2;

  float acc[4][6][4];
#pragma unroll
  for (int ot = 0; ot < 4; ot++)
#pragma unroll
    for (int tt = 0; tt < 6; tt++)
#pragma unroll
      for (int q = 0; q < 4; q++) acc[ot][tt][q] = 0.f;

  const __nv_bfloat16* xbh = xh + (size_t)b * NCH0 * 196 * 16;
  const __nv_bfloat16* xbl = xl + (size_t)b * NCH0 * 196 * 16;

  conv_fill(0, sb0, oHalf, xbh, xbl, tid);
  CP_COMMIT();

  for (int it = 0; it < NCH; it++) {
    int s = it & 1;
    if (it + 1 < NCH) {
      conv_fill(it + 1, sb0 + (unsigned)((s ^ 1) * STAGE_ELEMS * 2), oHalf, xbh, xbl, tid);
      CP_COMMIT();
      asm volatile("cp.async.wait_group 1;" ::: "memory");
    } else {
      asm volatile("cp.async.wait_group 0;" ::: "memory");
    }
    __syncthreads();
    unsigned sbA = sb0 + (unsigned)(s * STAGE_ELEMS * 2);
    unsigned sbB = sbA + (unsigned)(SA_ELEMS * 2);
#pragma unroll 1
    for (int sp = 0; sp < 3; sp++) {
      int aSel = (sp == 2) ? 1 : 0;   // hh, hl, lh
      int bSel = (sp == 1) ? 1 : 0;
      unsigned baseB = sbB + (unsigned)(bSel * 196 * ASTR * 2) + rowB_off;
#pragma unroll
      for (int k = 0; k < 5; k++) {
        u32 bfr[6][2];
#pragma unroll
        for (int q = 0; q < 3; q++)
          ldsm4(&bfr[2 * q][0], baseB + (unsigned)((q * 16 + k) * ASTR * 2));
        unsigned baseA = sbA + (unsigned)((k * 2 + aSel) * 128 * ASTR * 2) + rowA_off;
#pragma unroll
        for (int ot = 0; ot < 4; ot++) {
          u32 af[4];
          ldsm4(af, baseA + (unsigned)(ot * 16 * ASTR * 2));
#pragma unroll
          for (int tt = 0; tt < 6; tt++) mma16816(acc[ot][tt], af, bfr[tt]);
        }
      }
    }
    __syncthreads();
  }
#pragma unroll
  for (int ot = 0; ot < 4; ot++) {
    int o0 = oHalf * 128 + oBaseL + ot * 16 + lr;
    float bv0 = bias[o0], bv1 = bias[o0 + 8];
    float* r0 = out + ((size_t)b * CC + o0) * TT;
    float* r1 = out + ((size_t)b * CC + o0 + 8) * TT;
#pragma unroll
    for (int tt = 0; tt < 6; tt++) {
      int t = tBase + tt * 8 + lc * 2;
      float2 v0 = {acc[ot][tt][0] + bv0, acc[ot][tt][1] + bv0};
      float2 v1 = {acc[ot][tt][2] + bv1, acc[ot][tt][3] + bv1};
      *(float2*)(r0 + t) = v0;
      *(float2*)(r1 + t) = v1;
    }
  }
}

// ---------------- HMMA xg GEMM: CTA = (dir, b); 128g x 192t, K=256 ----------------
#define XA_ELEMS (2 * 128 * ASTR)
#define XB_ELEMS (2 * 192 * ASTR)
#define XG_SMEM_MAIN ((XA_ELEMS + XB_ELEMS) * 2)
#define XG_SMEM_STAGE (48 * 132 * 4)
#define XG_SMEM (XG_SMEM_MAIN > XG_SMEM_STAGE ? XG_SMEM_MAIN : XG_SMEM_STAGE)

__global__ __launch_bounds__(256) void xg_mma(
    const __nv_bfloat16* __restrict__ xh, const __nv_bfloat16* __restrict__ xl,
    const float* __restrict__ bif, const float* __restrict__ bhf,
    const float* __restrict__ bib, const float* __restrict__ bhb,
    float* __restrict__ xg) {
  extern __shared__ char xsm[];
  __nv_bfloat16* sA = (__nv_bfloat16*)xsm;            // [2][128][ASTR]
  __nv_bfloat16* sB = sA + XA_ELEMS;                  // [2][192][ASTR]
  float* stage = (float*)xsm;                         // [48][132], reused
  int dir = blockIdx.x, b = blockIdx.y;
  const float* bi = dir ? bib : bif;
  const float* bh = dir ? bhb : bhf;
  int tid = threadIdx.x;
  int warp = tid >> 5, lane = tid & 31;
  int warpO = warp & 1, warpT = warp >> 1;
  int oBaseL = warpO * 64, tBase = warpT * 48;
  int lr = lane >> 2, lc = lane & 3;

  unsigned sbA = (unsigned)__cvta_generic_to_shared(sA);
  unsigned sbB = (unsigned)__cvta_generic_to_shared(sB);
  unsigned rowA_off = ((oBaseL + (lane & 7) + ((lane >> 3) & 1) * 8) * ASTR +
                       ((lane >> 4) & 1) * 8) * 2;
  unsigned rowB_off = ((tBase + (lane & 7) + ((lane >> 4) & 1) * 8) * ASTR +
                       ((lane >> 3) & 1) * 8) * 2;

  float acc[4][6][4];
#pragma unroll
  for (int ot = 0; ot < 4; ot++)
#pragma unroll
    for (int tt = 0; tt < 6; tt++)
#pragma unroll
      for (int q = 0; q < 4; q++) acc[ot][tt][q] = 0.f;

  const __nv_bfloat16* xsrc[2] = {xh + (size_t)b * NCH0 * 196 * 16,
                                  xl + (size_t)b * NCH0 * 196 * 16};
  for (int chunk = 0; chunk < 16; chunk++) {
    for (int i = tid; i < 2048; i += 256) {
      int sp = i >> 10;
      int rem = i & 1023;
      int o = rem >> 3, cp = rem & 7;
      const __nv_bfloat16* wsrc = sp ? g_wxl : g_wxh;
      u32 v = *(const u32*)(wsrc + ((size_t)((dir * 16 + chunk) * 128 + o) * 16 + cp * 2));
      *(u32*)(sA + (sp * 128 + o) * ASTR + cp * 2) = v;
    }
    for (int i = tid; i < 3072; i += 256) {
      int sp = i >= 1536;
      int rem = sp ? i - 1536 : i;
      int row = rem >> 3, cp = rem & 7;
      u32 v = *(const u32*)(xsrc[sp] + ((size_t)(chunk * 196 + 2 + row) * 16 + cp * 2));
      *(u32*)(sB + (sp * 192 + row) * ASTR + cp * 2) = v;
    }
    __syncthreads();
#pragma unroll 1
    for (int sp = 0; sp < 3; sp++) {
      int aSel = (sp == 2) ? 1 : 0;
      int bSel = (sp == 1) ? 1 : 0;
      u32 bfr[6][2];
      unsigned baseB = sbB + (unsigned)(bSel * 192 * ASTR * 2) + rowB_off;
#pragma unroll
      for (int q = 0; q < 3; q++)
        ldsm4(&bfr[2 * q][0], baseB + (unsigned)(q * 16 * ASTR * 2));
      unsigned baseA = sbA + (unsigned)(aSel * 128 * ASTR * 2) + rowA_off;
#pragma unroll
      for (int ot = 0; ot < 4; ot++) {
        u32 af[4];
        ldsm4(af, baseA + (unsigned)(ot * 16 * ASTR * 2));
#pragma unroll
        for (int tt = 0; tt < 6; tt++) mma16816(acc[ot][tt], af, bfr[tt]);
      }
    }
    __syncthreads();
  }
  // epilogue: smem-transposed coalesced stores into [t][128] layout
  float* xgb = xg + (size_t)(dir * BB + b) * TT * 128;
  for (int q = 0; q < 4; q++) {
    __syncthreads();
    if (warpT == q) {
#pragma unroll
      for (int ot = 0; ot < 4; ot++) {
        int o0 = oBaseL + ot * 16 + lr;
#pragma unroll
        for (int tt = 0; tt < 6; tt++) {
          int tl = tt * 8 + lc * 2;
          stage[tl * 132 + o0] = acc[ot][tt][0];
          stage[(tl + 1) * 132 + o0] = acc[ot][tt][1];
          stage[tl * 132 + o0 + 8] = acc[ot][tt][2];
          stage[(tl + 1) * 132 + o0 + 8] = acc[ot][tt][3];
        }
      }
    }
    __syncthreads();
    for (int i = tid; i < 6144; i += 256) {
      int tl = i >> 7, g = i & 127;
      xgb[(size_t)(q * 48 + tl) * 128 + g] =
          stage[tl * 132 + g] + __ldg(bi + g) + __ldg(bh + g);
    }
  }
}

// ---------------- GroupNorm stats ----------------
__global__ __launch_bounds__(128) void gn_stats(const float* __restrict__ conv,
                                                float* __restrict__ mu,
                                                float* __restrict__ rsig) {
  __shared__ float ss[128], ss2[128];
  int b = blockIdx.x >> 4, g = blockIdx.x & 15;
  const float* p = conv + ((size_t)b * CC + g * 16) * TT;
  float s = 0.f, s2 = 0.f;
  for (int i = threadIdx.x; i < 16 * TT; i += 128) {
    float v = p[i];
    s += v;
    s2 = fmaf(v, v, s2);
  }
  ss[threadIdx.x] = s; ss2[threadIdx.x] = s2;
  __syncthreads();
  for (int off = 64; off > 0; off >>= 1) {
    if (threadIdx.x < off) {
      ss[threadIdx.x] += ss[threadIdx.x + off];
      ss2[threadIdx.x] += ss2[threadIdx.x + off];
    }
    __syncthreads();
  }
  if (threadIdx.x == 0) {
    float m = ss[0] * (1.0f / 3072.0f);
    float var = ss2[0] * (1.0f / 3072.0f) - m * m;
    mu[blockIdx.x] = m;
    rsig[blockIdx.x] = rsqrtf(var + 1e-5f);
  }
}

// ---------------- interp_lnr metadata ----------------
__global__ void interp_meta(int* __restrict__ gi, float* __restrict__ lam,
                            unsigned u0, unsigned u1, unsigned a0, unsigned a1,
                            unsigned c0, unsigned c1) {
  int b = blockIdx.x * blockDim.x + threadIdx.x;
  if (b >= BB) return;
  int base = b * TT;
  for (int t = 0; t < TT; t++) gi[base + t] = -1;
  int off = 0, pos = 0;
  for (int s = 0; s < 7; s++) {
    unsigned n = (unsigned)(b * 7 + s);
    unsigned ub = tf_bits32(u0, u1, n);
    float f = __uint_as_float((ub >> 9) | 0x3f800000u) - 1.0f;
    float scale = f + 0.5f;
    unsigned hb = tf_bits32(a0, a1, n);
    unsigned lb = tf_bits32(c0, c1, n);
    unsigned offt = ((hb % 13u) * 9u + lb % 13u) % 13u;
    int len = 19 + (int)offt;
    float lenm1 = (float)(len - 1);
    for (int l = 0; l < 64; l++) {
      float idx = __fdiv_rn((float)l, scale);
      float fl = floorf(idx);
      float lm = idx - fl;
      if (fl < lenm1) {
        int io = (int)fl + off;
        if (io < TT - 1) {
          if (pos < TT) { gi[base + pos] = io; lam[base + pos] = lm; }
          pos++;
        }
      }
    }
    off += len;
  }
}

// ---------------- interp apply: GN + ReLU + lerp -> split bf16 image ----------------
__global__ __launch_bounds__(192) void interp_apply(
    const float* __restrict__ conv, const int* __restrict__ gi,
    const float* __restrict__ lam, const float* __restrict__ mu,
    const float* __restrict__ rsig, const float* __restrict__ gnw,
    const float* __restrict__ gnb,
    __nv_bfloat16* __restrict__ xh, __nv_bfloat16* __restrict__ xl) {
  int b = blockIdx.x, t = threadIdx.x;
  int cbase = blockIdx.y * 64;
  __shared__ float smu[16], srs[16];
  __shared__ int sg[TT];
  __shared__ float sl[TT];
  if (t < 16) { smu[t] = mu[b * 16 + t]; srs[t] = rsig[b * 16 + t]; }
  sg[t] = gi[b * TT + t];
  sl[t] = lam[b * TT + t];
  __syncthreads();
  int g = sg[t];
  float lm = sl[t];
  const float* cb = conv + (size_t)b * CC * TT;
  size_t ib = (size_t)b * NCH0 * 196 * 16;
  for (int cc = 0; cc < 64; cc++) {
    int c = cbase + cc;
    float val = 0.f;
    if (g >= 0) {
      float m = smu[c >> 4], rs = srs[c >> 4];
      float w = gnw[c], be = gnb[c];
      float a = cb[c * TT + g], e = cb[c * TT + g + 1];
      float fa = fmaxf((a - m) * rs * w + be, 0.f);
      float fb = fmaxf((e - m) * rs * w + be, 0.f);
      val = (1.0f - lm) * fa + lm * fb;
    }
    size_t xi = ib + (size_t)((c >> 4) * 196 + t + 2) * 16 + (c & 15);
    __nv_bfloat16 h = __float2bfloat16(val);
    xh[xi] = h;
    xl[xi] = __float2bfloat16(val - __bfloat162float(h));
  }
  if (blockIdx.y == 0 && t < 4) {  // zero pad rows 0,1,194,195 for 16 chunks
    int r = (t < 2) ? t : (192 + t);
    for (int ch = 0; ch < 16; ch++) {
      size_t xi = ib + (size_t)(ch * 196 + r) * 16;
      for (int cl = 0; cl < 16; cl++) {
        xh[xi + cl] = __float2bfloat16(0.f);
        xl[xi + cl] = __float2bfloat16(0.f);
      }
    }
  }
}

// ---------------- LSTM recurrence: warp per batch element ----------------
__device__ __forceinline__ float sigf(float x) { return 1.0f / (1.0f + expf(-x)); }

__global__ __launch_bounds__(256) void lstm_kernel(
    const float* __restrict__ xg, const float* __restrict__ whf,
    const float* __restrict__ whb, float* __restrict__ out) {
  __shared__ float ws[32 * 128];
  int dir = blockIdx.y;
  const float* wh = dir ? whb : whf;
  int tid = threadIdx.x;
  for (int idx = tid; idx < 4096; idx += 256) {
    int j = idx >> 7, r = idx & 127;
    ws[idx] = wh[r * 32 + j];
  }
  __syncthreads();
  int warp = tid >> 5, lane = tid & 31;
  int b = blockIdx.x * 8 + warp;
  const float* xgb = xg + (size_t)(dir * BB + b) * TT * 128;
  float h = 0.f, c = 0.f;
  for (int step = 0; step < TT; step++) {
    int t = dir ? (TT - 1 - step) : step;
    const float* p = xgb + (size_t)t * 128;
    float gi = p[lane], gf = p[32 + lane], gg = p[64 + lane], go = p[96 + lane];
#pragma unroll
    for (int j = 0; j < 32; j++) {
      float hj = __shfl_sync(0xffffffffu, h, j);
      const float* wr = ws + j * 128;
      gi = fmaf(wr[lane], hj, gi);
      gf = fmaf(wr[32 + lane], hj, gf);
      gg = fmaf(wr[64 + lane], hj, gg);
      go = fmaf(wr[96 + lane], hj, go);
    }
    c = sigf(gf) * c + sigf(gi) * tanhf(gg);
    h = sigf(go) * tanhf(c);
    if (dir == 0) {
      if ((t & 7) == 7) out[((size_t)b * 24 + (t >> 3)) * 64 + lane] = h;
    } else {
      if ((t & 7) == 0) out[((size_t)b * 24 + (t >> 3)) * 64 + 32 + lane] = h;
    }
  }
}

// ---------------- launch ----------------
extern "C" void kernel_launch(void* const* d_in, const int* in_sizes, int n_in,
                              void* d_out, int out_size) {
  (void)in_sizes; (void)n_in; (void)out_size;
  float *p_conv, *p_xg, *p_mu, *p_rsig, *p_lam;
  int* p_gi;
  __nv_bfloat16 *p_xh, *p_xl;
  cudaGetSymbolAddress((void**)&p_conv, g_conv);
  cudaGetSymbolAddress((void**)&p_xg, g_xg);
  cudaGetSymbolAddress((void**)&p_mu, g_mu);
  cudaGetSymbolAddress((void**)&p_rsig, g_rsig);
  cudaGetSymbolAddress((void**)&p_gi, g_gi);
  cudaGetSymbolAddress((void**)&p_lam, g_lam);
  cudaGetSymbolAddress((void**)&p_xh, g_xh);
  cudaGetSymbolAddress((void**)&p_xl, g_xl);

  static int smem_set = 0;
  if (!smem_set) {
    cudaFuncSetAttribute(mma_conv, cudaFuncAttributeMaxDynamicSharedMemorySize, CONV_SMEM);
    cudaFuncSetAttribute(xg_mma, cudaFuncAttributeMaxDynamicSharedMemorySize, XG_SMEM);
    smem_set = 1;
  }

  const float* x0 = (const float*)d_in[0];

  // JAX threefry keys: rng = key(42); per layer i: fold_in -> split -> randint split
  unsigned keys[3][6];
  for (int i = 0; i < 3; i++) {
    unsigned f0, f1;
    tf2x32(0u, 42u, 0u, (unsigned)i, f0, f1);
    unsigned k1a, k1b, k2a, k2b;
    tf2x32(f0, f1, 0u, 0u, k1a, k1b);
    tf2x32(f0, f1, 0u, 1u, k2a, k2b);
    unsigned ha, hb2, la, lb2;
    tf2x32(k2a, k2b, 0u, 0u, ha, hb2);
    tf2x32(k2a, k2b, 0u, 1u, la, lb2);
    keys[i][0] = k1a; keys[i][1] = k1b;
    keys[i][2] = ha;  keys[i][3] = hb2;
    keys[i][4] = la;  keys[i][5] = lb2;
  }

  x0prep<<<BB, 256>>>(x0);
  wprep_xg<<<32, 128>>>((const float*)d_in[13], (const float*)d_in[17]);
  for (int i = 0; i < 3; i++) {
    const float* cw = (const float*)d_in[1 + 4 * i];
    const float* cb = (const float*)d_in[2 + 4 * i];
    const float* gw = (const float*)d_in[3 + 4 * i];
    const float* gb = (const float*)d_in[4 + 4 * i];
    int Cin = (i == 0) ? 257 : 256;
    int NCH = (i == 0) ? 17 : 16;
    wprep<<<NCH * 5, 256>>>(cw, Cin, NCH);
    mma_conv<<<dim3(2, BB), 256, CONV_SMEM>>>(p_xh, p_xl, cb, p_conv, NCH);
    gn_stats<<<BB * 16, 128>>>(p_conv, p_mu, p_rsig);
    interp_meta<<<2, 256>>>(p_gi, p_lam, keys[i][0], keys[i][1], keys[i][2],
                            keys[i][3], keys[i][4], keys[i][5]);
    interp_apply<<<dim3(BB, 4), 192>>>(p_conv, p_gi, p_lam, p_mu, p_rsig, gw, gb,
                                       p_xh, p_xl);
  }
  xg_mma<<<dim3(2, BB), 256, XG_SMEM>>>(p_xh, p_xl, (const float*)d_in[15],
                                        (const float*)d_in[16], (const float*)d_in[19],
                                        (const float*)d_in[20], p_xg);
  lstm_kernel<<<dim3(64, 2), 256>>>(p_xg, (const float*)d_in[14],
                                    (const float*)d_in[18], (float*)d_out);
}

// round 9
// speedup vs baseline: 4.1819x; 1.3230x over previous
#include <cuda_runtime.h>
#include <cuda_bf16.h>
#include <math.h>

#define BB 512
#define TT 192
#define CC 256
#define NCH0 17           // layer0 ci chunks of 16 (257 -> 272)
#define CSTR 16           // conv smem row stride (bf16): no pad, 2-way LDSM conflict
#define XSTR 24           // xg smem row stride (bf16): conflict-free

typedef unsigned int u32;

// ---------------- scratch (device globals; no allocation) ----------------
__device__ float g_conv[(size_t)BB * TT * CC];    // conv output, T-MAJOR [b][t][c]
__device__ float g_xg[(size_t)2 * BB * TT * 128]; // lstm pre-gates [dir,B,T,128]
__device__ float g_mu[BB * 16];
__device__ float g_rsig[BB * 16];
__device__ int   g_gi[BB * TT];
__device__ float g_lam[BB * TT];
// split-bf16 x image, chunk-major: [b][chunk<17][row 0..195][ci16]; row r <-> t=r-2
__device__ __nv_bfloat16 g_xh[(size_t)BB * NCH0 * 196 * 16];
__device__ __nv_bfloat16 g_xl[(size_t)BB * NCH0 * 196 * 16];
// split conv weights, chunk-major: [chunk][k 5][o 256][ci16]
__device__ __nv_bfloat16 g_wh[NCH0 * 5 * 256 * 16];
__device__ __nv_bfloat16 g_wl[NCH0 * 5 * 256 * 16];
// split xg weights: [dir 2][chunk 16][g 128][ci16]
__device__ __nv_bfloat16 g_wxh[2 * 16 * 128 * 16];
__device__ __nv_bfloat16 g_wxl[2 * 16 * 128 * 16];

// ---------------- threefry2x32 (JAX), host + device ----------------
__host__ __device__ __forceinline__ void tf2x32(unsigned k0, unsigned k1,
                                                unsigned x0, unsigned x1,
                                                unsigned& y0, unsigned& y1) {
  unsigned ks2 = k0 ^ k1 ^ 0x1BD11BDAu;
  x0 += k0; x1 += k1;
#define TFR(r) x0 += x1; x1 = (x1 << (r)) | (x1 >> (32 - (r))); x1 ^= x0;
  TFR(13) TFR(15) TFR(26) TFR(6)
  x0 += k1;  x1 += ks2 + 1u;
  TFR(17) TFR(29) TFR(16) TFR(24)
  x0 += ks2; x1 += k0 + 2u;
  TFR(13) TFR(15) TFR(26) TFR(6)
  x0 += k0;  x1 += k1 + 3u;
  TFR(17) TFR(29) TFR(16) TFR(24)
  x0 += k1;  x1 += ks2 + 4u;
  TFR(13) TFR(15) TFR(26) TFR(6)
  x0 += ks2; x1 += k0 + 5u;
#undef TFR
  y0 = x0; y1 = x1;
}

__device__ __forceinline__ unsigned tf_bits32(unsigned k0, unsigned k1, unsigned n) {
  unsigned y0, y1;
  tf2x32(k0, k1, 0u, n, y0, y1);
  return y0 ^ y1;
}

// ---------------- mma.sync + ldmatrix + cp.async ----------------
__device__ __forceinline__ void mma16816(float* c, const u32* a, const u32* b) {
  asm volatile(
      "mma.sync.aligned.m16n8k16.row.col.f32.bf16.bf16.f32 "
      "{%0,%1,%2,%3}, {%4,%5,%6,%7}, {%8,%9}, {%0,%1,%2,%3};"
      : "+f"(c[0]), "+f"(c[1]), "+f"(c[2]), "+f"(c[3])
      : "r"(a[0]), "r"(a[1]), "r"(a[2]), "r"(a[3]), "r"(b[0]), "r"(b[1]));
}

__device__ __forceinline__ void ldsm4(u32* r, unsigned addr) {
  asm volatile("ldmatrix.sync.aligned.m8n8.x4.shared.b16 {%0,%1,%2,%3}, [%4];"
               : "=r"(r[0]), "=r"(r[1]), "=r"(r[2]), "=r"(r[3]) : "r"(addr));
}

__device__ __forceinline__ void cpasync16(unsigned d, const void* g) {
  asm volatile("cp.async.cg.shared.global [%0], [%1], 16;" :: "r"(d), "l"(g));
}
#define CP_COMMIT() asm volatile("cp.async.commit_group;" ::: "memory")

// ---------------- conv weight prep ----------------
__global__ __launch_bounds__(256) void wprep(const float* __restrict__ w,
                                             int Cin, int NCH) {
  int chunk = blockIdx.x / 5, k = blockIdx.x % 5;
  int o = threadIdx.x;
  size_t base = (size_t)((chunk * 5 + k) * 256 + o) * 16;
  for (int cl = 0; cl < 16; cl++) {
    int ci = chunk * 16 + cl;
    float v = (ci < Cin) ? w[((size_t)o * Cin + ci) * 5 + k] : 0.f;
    __nv_bfloat16 h = __float2bfloat16(v);
    g_wh[base + cl] = h;
    g_wl[base + cl] = __float2bfloat16(v - __bfloat162float(h));
  }
}

// ---------------- xg weight prep: [dir][chunk][g][ci] ----------------
__global__ __launch_bounds__(128) void wprep_xg(const float* __restrict__ wf,
                                                const float* __restrict__ wb) {
  int dir = blockIdx.x >> 4, chunk = blockIdx.x & 15;
  int g = threadIdx.x;
  const float* w = dir ? wb : wf;
  size_t base = (size_t)((dir * 16 + chunk) * 128 + g) * 16;
  for (int cl = 0; cl < 16; cl++) {
    float v = w[(size_t)g * CC + chunk * 16 + cl];
    __nv_bfloat16 h = __float2bfloat16(v);
    g_wxh[base + cl] = h;
    g_wxl[base + cl] = __float2bfloat16(v - __bfloat162float(h));
  }
}

// ---------------- x0 prep: transpose + split + pad ----------------
__global__ __launch_bounds__(256) void x0prep(const float* __restrict__ x) {
  int b = blockIdx.x;
  size_t ib = (size_t)b * NCH0 * 196 * 16;
  for (int idx = threadIdx.x; idx < NCH0 * 196 * 16; idx += 256) {
    int chunk = idx / (196 * 16);
    int rem = idx - chunk * 196 * 16;
    int row = rem >> 4, cl = rem & 15;
    int t = row - 2, ci = chunk * 16 + cl;
    float v = 0.f;
    if (t >= 0 && t < TT && ci < 257) v = x[((size_t)b * 257 + ci) * TT + t];
    __nv_bfloat16 h = __float2bfloat16(v);
    g_xh[ib + idx] = h;
    g_xl[ib + idx] = __float2bfloat16(v - __bfloat162float(h));
  }
}

// ---------------- HMMA conv: CTA = (oHalf, b); 128o x 192t; 2 CTA/SM ----------------
#define SA_ELEMS (10 * 128 * CSTR)
#define SB_ELEMS (2 * 196 * CSTR)
#define STAGE_ELEMS (SA_ELEMS + SB_ELEMS)
#define CONV_SMEM (STAGE_ELEMS * 2 * 2)

__device__ __forceinline__ void conv_fill(int chunk, unsigned sstage, int oHalf,
                                          const __nv_bfloat16* xbh,
                                          const __nv_bfloat16* xbl, int tid) {
  // A: 10 tiles (k*2+sp) x 128 o x 16 ci = 2560 16B-chunks
  for (int i = tid; i < 2560; i += 256) {
    int ksp = i >> 8;
    int rem = i & 255;
    int o = rem >> 1, half = rem & 1;
    int k = ksp >> 1, sp = ksp & 1;
    const __nv_bfloat16* wsrc = sp ? g_wl : g_wh;
    const void* g = wsrc + ((size_t)((chunk * 5 + k) * 256 + oHalf * 128 + o) * 16 + half * 8);
    unsigned d = sstage + (unsigned)(((ksp * 128 + o) * CSTR + half * 8) * 2);
    cpasync16(d, g);
  }
  // B: 2 splits x 196 rows x 16 = 784 16B-chunks
  for (int i = tid; i < 784; i += 256) {
    int sp = i >= 392;
    int rem = sp ? i - 392 : i;
    int row = rem >> 1, half = rem & 1;
    const __nv_bfloat16* xs = sp ? xbl : xbh;
    const void* g = xs + ((size_t)(chunk * 196 + row) * 16 + half * 8);
    unsigned d = sstage + (unsigned)((SA_ELEMS + (sp * 196 + row) * CSTR + half * 8) * 2);
    cpasync16(d, g);
  }
}

__global__ __launch_bounds__(256, 2) void mma_conv(
    const __nv_bfloat16* __restrict__ xh, const __nv_bfloat16* __restrict__ xl,
    const float* __restrict__ bias, float* __restrict__ outT, int NCH) {
  extern __shared__ __nv_bfloat16 sm[];
  int oHalf = blockIdx.x, b = blockIdx.y;
  int tid = threadIdx.x;
  int warp = tid >> 5, lane = tid & 31;
  int warpO = warp & 1, warpT = warp >> 1;
  int oBaseL = warpO * 64, tBase = warpT * 48;
  int lr = lane >> 2, lc = lane & 3;

  unsigned sb0 = (unsigned)__cvta_generic_to_shared(sm);
  unsigned rowA_off = ((oBaseL + (lane & 7) + ((lane >> 3) & 1) * 8) * CSTR +
                       ((lane >> 4) & 1) * 8) * 2;
  unsigned rowB_off = ((tBase + (lane & 7) + ((lane >> 4) & 1) * 8) * CSTR +
                       ((lane >> 3) & 1) * 8) * 2;

  float acc[4][6][4];
#pragma unroll
  for (int ot = 0; ot < 4; ot++)
#pragma unroll
    for (int tt = 0; tt < 6; tt++)
#pragma unroll
      for (int q = 0; q < 4; q++) acc[ot][tt][q] = 0.f;

  const __nv_bfloat16* xbh = xh + (size_t)b * NCH0 * 196 * 16;
  const __nv_bfloat16* xbl = xl + (size_t)b * NCH0 * 196 * 16;

  conv_fill(0, sb0, oHalf, xbh, xbl, tid);
  CP_COMMIT();

  for (int it = 0; it < NCH; it++) {
    int s = it & 1;
    if (it + 1 < NCH) {
      conv_fill(it + 1, sb0 + (unsigned)((s ^ 1) * STAGE_ELEMS * 2), oHalf, xbh, xbl, tid);
      CP_COMMIT();
      asm volatile("cp.async.wait_group 1;" ::: "memory");
    } else {
      asm volatile("cp.async.wait_group 0;" ::: "memory");
    }
    __syncthreads();
    unsigned sbA = sb0 + (unsigned)(s * STAGE_ELEMS * 2);
    unsigned sbB = sbA + (unsigned)(SA_ELEMS * 2);
#pragma unroll 1
    for (int sp = 0; sp < 3; sp++) {
      int aSel = (sp == 2) ? 1 : 0;   // hh, hl, lh
      int bSel = (sp == 1) ? 1 : 0;
      unsigned baseB = sbB + (unsigned)(bSel * 196 * CSTR * 2) + rowB_off;
#pragma unroll
      for (int k = 0; k < 5; k++) {
        u32 bfr[6][2];
#pragma unroll
        for (int q = 0; q < 3; q++)
          ldsm4(&bfr[2 * q][0], baseB + (unsigned)((q * 16 + k) * CSTR * 2));
        unsigned baseA = sbA + (unsigned)((k * 2 + aSel) * 128 * CSTR * 2) + rowA_off;
#pragma unroll
        for (int ot = 0; ot < 4; ot++) {
          u32 af[4];
          ldsm4(af, baseA + (unsigned)(ot * 16 * CSTR * 2));
#pragma unroll
          for (int tt = 0; tt < 6; tt++) mma16816(acc[ot][tt], af, bfr[tt]);
        }
      }
    }
    __syncthreads();
  }
  // epilogue: smem-staged transpose -> t-major coalesced stores
  float* stage = (float*)sm;   // [48][132], reuses pipeline smem (all consumed)
  for (int q = 0; q < 4; q++) {
    __syncthreads();
    if (warpT == q) {
#pragma unroll
      for (int ot = 0; ot < 4; ot++) {
        int o0 = oBaseL + ot * 16 + lr;
#pragma unroll
        for (int tt = 0; tt < 6; tt++) {
          int tl = tt * 8 + lc * 2;
          stage[tl * 132 + o0] = acc[ot][tt][0];
          stage[(tl + 1) * 132 + o0] = acc[ot][tt][1];
          stage[tl * 132 + o0 + 8] = acc[ot][tt][2];
          stage[(tl + 1) * 132 + o0 + 8] = acc[ot][tt][3];
        }
      }
    }
    __syncthreads();
    for (int i = tid; i < 6144; i += 256) {
      int tl = i >> 7, o = i & 127;
      outT[((size_t)b * TT + q * 48 + tl) * CC + oHalf * 128 + o] =
          stage[tl * 132 + o] + __ldg(bias + oHalf * 128 + o);
    }
  }
}

// ---------------- HMMA xg GEMM: CTA = (dir, b); 128g x 192t, K=256 ----------------
#define XA_ELEMS (2 * 128 * XSTR)
#define XB_ELEMS (2 * 192 * XSTR)
#define XG_SMEM_MAIN ((XA_ELEMS + XB_ELEMS) * 2)
#define XG_SMEM_STAGE (48 * 132 * 4)
#define XG_SMEM (XG_SMEM_MAIN > XG_SMEM_STAGE ? XG_SMEM_MAIN : XG_SMEM_STAGE)

__global__ __launch_bounds__(256) void xg_mma(
    const __nv_bfloat16* __restrict__ xh, const __nv_bfloat16* __restrict__ xl,
    const float* __restrict__ bif, const float* __restrict__ bhf,
    const float* __restrict__ bib, const float* __restrict__ bhb,
    float* __restrict__ xg) {
  extern __shared__ char xsm[];
  __nv_bfloat16* sA = (__nv_bfloat16*)xsm;            // [2][128][XSTR]
  __nv_bfloat16* sB = sA + XA_ELEMS;                  // [2][192][XSTR]
  float* stage = (float*)xsm;                         // [48][132], reused
  int dir = blockIdx.x, b = blockIdx.y;
  const float* bi = dir ? bib : bif;
  const float* bh = dir ? bhb : bhf;
  int tid = threadIdx.x;
  int warp = tid >> 5, lane = tid & 31;
  int warpO = warp & 1, warpT = warp >> 1;
  int oBaseL = warpO * 64, tBase = warpT * 48;
  int lr = lane >> 2, lc = lane & 3;

  unsigned sbA = (unsigned)__cvta_generic_to_shared(sA);
  unsigned sbB = (unsigned)__cvta_generic_to_shared(sB);
  unsigned rowA_off = ((oBaseL + (lane & 7) + ((lane >> 3) & 1) * 8) * XSTR +
                       ((lane >> 4) & 1) * 8) * 2;
  unsigned rowB_off = ((tBase + (lane & 7) + ((lane >> 4) & 1) * 8) * XSTR +
                       ((lane >> 3) & 1) * 8) * 2;

  float acc[4][6][4];
#pragma unroll
  for (int ot = 0; ot < 4; ot++)
#pragma unroll
    for (int tt = 0; tt < 6; tt++)
#pragma unroll
      for (int q = 0; q < 4; q++) acc[ot][tt][q] = 0.f;

  const __nv_bfloat16* xsrc[2] = {xh + (size_t)b * NCH0 * 196 * 16,
                                  xl + (size_t)b * NCH0 * 196 * 16};
  for (int chunk = 0; chunk < 16; chunk++) {
    for (int i = tid; i < 2048; i += 256) {
      int sp = i >> 10;
      int rem = i & 1023;
      int o = rem >> 3, cp = rem & 7;
      const __nv_bfloat16* wsrc = sp ? g_wxl : g_wxh;
      u32 v = *(const u32*)(wsrc + ((size_t)((dir * 16 + chunk) * 128 + o) * 16 + cp * 2));
      *(u32*)(sA + (sp * 128 + o) * XSTR + cp * 2) = v;
    }
    for (int i = tid; i < 3072; i += 256) {
      int sp = i >= 1536;
      int rem = sp ? i - 1536 : i;
      int row = rem >> 3, cp = rem & 7;
      u32 v = *(const u32*)(xsrc[sp] + ((size_t)(chunk * 196 + 2 + row) * 16 + cp * 2));
      *(u32*)(sB + (sp * 192 + row) * XSTR + cp * 2) = v;
    }
    __syncthreads();
#pragma unroll 1
    for (int sp = 0; sp < 3; sp++) {
      int aSel = (sp == 2) ? 1 : 0;
      int bSel = (sp == 1) ? 1 : 0;
      u32 bfr[6][2];
      unsigned baseB = sbB + (unsigned)(bSel * 192 * XSTR * 2) + rowB_off;
#pragma unroll
      for (int q = 0; q < 3; q++)
        ldsm4(&bfr[2 * q][0], baseB + (unsigned)(q * 16 * XSTR * 2));
      unsigned baseA = sbA + (unsigned)(aSel * 128 * XSTR * 2) + rowA_off;
#pragma unroll
      for (int ot = 0; ot < 4; ot++) {
        u32 af[4];
        ldsm4(af, baseA + (unsigned)(ot * 16 * XSTR * 2));
#pragma unroll
        for (int tt = 0; tt < 6; tt++) mma16816(acc[ot][tt], af, bfr[tt]);
      }
    }
    __syncthreads();
  }
  // epilogue: smem-transposed coalesced stores into [t][128] layout
  float* xgb = xg + (size_t)(dir * BB + b) * TT * 128;
  for (int q = 0; q < 4; q++) {
    __syncthreads();
    if (warpT == q) {
#pragma unroll
      for (int ot = 0; ot < 4; ot++) {
        int o0 = oBaseL + ot * 16 + lr;
#pragma unroll
        for (int tt = 0; tt < 6; tt++) {
          int tl = tt * 8 + lc * 2;
          stage[tl * 132 + o0] = acc[ot][tt][0];
          stage[(tl + 1) * 132 + o0] = acc[ot][tt][1];
          stage[tl * 132 + o0 + 8] = acc[ot][tt][2];
          stage[(tl + 1) * 132 + o0 + 8] = acc[ot][tt][3];
        }
      }
    }
    __syncthreads();
    for (int i = tid; i < 6144; i += 256) {
      int tl = i >> 7, g = i & 127;
      xgb[(size_t)(q * 48 + tl) * 128 + g] =
          stage[tl * 132 + g] + __ldg(bi + g) + __ldg(bh + g);
    }
  }
}

// ---------------- GroupNorm stats (t-major conv) ----------------
__global__ __launch_bounds__(128) void gn_stats(const float* __restrict__ convT,
                                                float* __restrict__ mu,
                                                float* __restrict__ rsig) {
  __shared__ float ss[128], ss2[128];
  int b = blockIdx.x >> 4, g = blockIdx.x & 15;
  const float* p = convT + (size_t)b * TT * CC + g * 16;
  float s = 0.f, s2 = 0.f;
  for (int i = threadIdx.x; i < 16 * TT; i += 128) {
    int t = i >> 4, cl = i & 15;
    float v = p[(size_t)t * CC + cl];
    s += v;
    s2 = fmaf(v, v, s2);
  }
  ss[threadIdx.x] = s; ss2[threadIdx.x] = s2;
  __syncthreads();
  for (int off = 64; off > 0; off >>= 1) {
    if (threadIdx.x < off) {
      ss[threadIdx.x] += ss[threadIdx.x + off];
      ss2[threadIdx.x] += ss2[threadIdx.x + off];
    }
    __syncthreads();
  }
  if (threadIdx.x == 0) {
    float m = ss[0] * (1.0f / 3072.0f);
    float var = ss2[0] * (1.0f / 3072.0f) - m * m;
    mu[blockIdx.x] = m;
    rsig[blockIdx.x] = rsqrtf(var + 1e-5f);
  }
}

// ---------------- interp_lnr metadata ----------------
__global__ void interp_meta(int* __restrict__ gi, float* __restrict__ lam,
                            unsigned u0, unsigned u1, unsigned a0, unsigned a1,
                            unsigned c0, unsigned c1) {
  int b = blockIdx.x * blockDim.x + threadIdx.x;
  if (b >= BB) return;
  int base = b * TT;
  for (int t = 0; t < TT; t++) gi[base + t] = -1;
  int off = 0, pos = 0;
  for (int s = 0; s < 7; s++) {
    unsigned n = (unsigned)(b * 7 + s);
    unsigned ub = tf_bits32(u0, u1, n);
    float f = __uint_as_float((ub >> 9) | 0x3f800000u) - 1.0f;
    float scale = f + 0.5f;
    unsigned hb = tf_bits32(a0, a1, n);
    unsigned lb = tf_bits32(c0, c1, n);
    unsigned offt = ((hb % 13u) * 9u + lb % 13u) % 13u;
    int len = 19 + (int)offt;
    float lenm1 = (float)(len - 1);
    for (int l = 0; l < 64; l++) {
      float idx = __fdiv_rn((float)l, scale);
      float fl = floorf(idx);
      float lm = idx - fl;
      if (fl < lenm1) {
        int io = (int)fl + off;
        if (io < TT - 1) {
          if (pos < TT) { gi[base + pos] = io; lam[base + pos] = lm; }
          pos++;
        }
      }
    }
    off += len;
  }
}

// ---------------- interp apply (t-major conv): coalesced gather ----------------
// grid (BB, 6), block 256 (tid = channel); each block handles 32 output t.
__global__ __launch_bounds__(256) void interp_apply(
    const float* __restrict__ convT, const int* __restrict__ gi,
    const float* __restrict__ lam, const float* __restrict__ mu,
    const float* __restrict__ rsig, const float* __restrict__ gnw,
    const float* __restrict__ gnb,
    __nv_bfloat16* __restrict__ xh, __nv_bfloat16* __restrict__ xl) {
  int b = blockIdx.x, c = threadIdx.x;
  int t0 = blockIdx.y * 32;
  __shared__ int sg[32];
  __shared__ float sl[32];
  if (c < 32) {
    sg[c] = gi[b * TT + t0 + c];
    sl[c] = lam[b * TT + t0 + c];
  }
  __syncthreads();
  float m = mu[b * 16 + (c >> 4)];
  float rs = rsig[b * 16 + (c >> 4)];
  float w = gnw[c], be = gnb[c];
  const float* cb = convT + (size_t)b * TT * CC;
  size_t ib = (size_t)b * NCH0 * 196 * 16;
  size_t xbase = ib + (size_t)(c >> 4) * 196 * 16 + (c & 15);
#pragma unroll 1
  for (int tt = 0; tt < 32; tt++) {
    int g = sg[tt];
    float val = 0.f;
    if (g >= 0) {
      float lm = sl[tt];
      float a = cb[(size_t)g * CC + c];
      float e = cb[(size_t)(g + 1) * CC + c];
      float fa = fmaxf((a - m) * rs * w + be, 0.f);
      float fb = fmaxf((e - m) * rs * w + be, 0.f);
      val = (1.0f - lm) * fa + lm * fb;
    }
    size_t xi = xbase + (size_t)(t0 + tt + 2) * 16;
    __nv_bfloat16 h = __float2bfloat16(val);
    xh[xi] = h;
    xl[xi] = __float2bfloat16(val - __bfloat162float(h));
  }
  if (blockIdx.y == 0) {  // zero pad rows 0,1,194,195 for all 16 chunks
    int chunk = c >> 4, cl = c & 15;
#pragma unroll
    for (int rr = 0; rr < 4; rr++) {
      int r = (rr < 2) ? rr : (192 + rr);
      size_t xi = ib + (size_t)(chunk * 196 + r) * 16 + cl;
      xh[xi] = __float2bfloat16(0.f);
      xl[xi] = __float2bfloat16(0.f);
    }
  }
}

// ---------------- LSTM recurrence: warp per batch element ----------------
__device__ __forceinline__ float sigf(float x) { return 1.0f / (1.0f + expf(-x)); }

__global__ __launch_bounds__(256) void lstm_kernel(
    const float* __restrict__ xg, const float* __restrict__ whf,
    const float* __restrict__ whb, float* __restrict__ out) {
  __shared__ float ws[32 * 128];
  int dir = blockIdx.y;
  const float* wh = dir ? whb : whf;
  int tid = threadIdx.x;
  for (int idx = tid; idx < 4096; idx += 256) {
    int j = idx >> 7, r = idx & 127;
    ws[idx] = wh[r * 32 + j];
  }
  __syncthreads();
  int warp = tid >> 5, lane = tid & 31;
  int b = blockIdx.x * 8 + warp;
  const float* xgb = xg + (size_t)(dir * BB + b) * TT * 128;
  float h = 0.f, c = 0.f;
  for (int step = 0; step < TT; step++) {
    int t = dir ? (TT - 1 - step) : step;
    const float* p = xgb + (size_t)t * 128;
    float gi = p[lane], gf = p[32 + lane], gg = p[64 + lane], go = p[96 + lane];
#pragma unroll
    for (int j = 0; j < 32; j++) {
      float hj = __shfl_sync(0xffffffffu, h, j);
      const float* wr = ws + j * 128;
      gi = fmaf(wr[lane], hj, gi);
      gf = fmaf(wr[32 + lane], hj, gf);
      gg = fmaf(wr[64 + lane], hj, gg);
      go = fmaf(wr[96 + lane], hj, go);
    }
    c = sigf(gf) * c + sigf(gi) * tanhf(gg);
    h = sigf(go) * tanhf(c);
    if (dir == 0) {
      if ((t & 7) == 7) out[((size_t)b * 24 + (t >> 3)) * 64 + lane] = h;
    } else {
      if ((t & 7) == 0) out[((size_t)b * 24 + (t >> 3)) * 64 + 32 + lane] = h;
    }
  }
}

// ---------------- launch ----------------
extern "C" void kernel_launch(void* const* d_in, const int* in_sizes, int n_in,
                              void* d_out, int out_size) {
  (void)in_sizes; (void)n_in; (void)out_size;
  float *p_conv, *p_xg, *p_mu, *p_rsig, *p_lam;
  int* p_gi;
  __nv_bfloat16 *p_xh, *p_xl;
  cudaGetSymbolAddress((void**)&p_conv, g_conv);
  cudaGetSymbolAddress((void**)&p_xg, g_xg);
  cudaGetSymbolAddress((void**)&p_mu, g_mu);
  cudaGetSymbolAddress((void**)&p_rsig, g_rsig);
  cudaGetSymbolAddress((void**)&p_gi, g_gi);
  cudaGetSymbolAddress((void**)&p_lam, g_lam);
  cudaGetSymbolAddress((void**)&p_xh, g_xh);
  cudaGetSymbolAddress((void**)&p_xl, g_xl);

  static int smem_set = 0;
  if (!smem_set) {
    cudaFuncSetAttribute(mma_conv, cudaFuncAttributeMaxDynamicSharedMemorySize, CONV_SMEM);
    cudaFuncSetAttribute(xg_mma, cudaFuncAttributeMaxDynamicSharedMemorySize, XG_SMEM);
    smem_set = 1;
  }

  const float* x0 = (const float*)d_in[0];

  // JAX threefry keys: rng = key(42); per layer i: fold_in -> split -> randint split
  unsigned keys[3][6];
  for (int i = 0; i < 3; i++) {
    unsigned f0, f1;
    tf2x32(0u, 42u, 0u, (unsigned)i, f0, f1);
    unsigned k1a, k1b, k2a, k2b;
    tf2x32(f0, f1, 0u, 0u, k1a, k1b);
    tf2x32(f0, f1, 0u, 1u, k2a, k2b);
    unsigned ha, hb2, la, lb2;
    tf2x32(k2a, k2b, 0u, 0u, ha, hb2);
    tf2x32(k2a, k2b, 0u, 1u, la, lb2);
    keys[i][0] = k1a; keys[i][1] = k1b;
    keys[i][2] = ha;  keys[i][3] = hb2;
    keys[i][4] = la;  keys[i][5] = lb2;
  }

  x0prep<<<BB, 256>>>(x0);
  wprep_xg<<<32, 128>>>((const float*)d_in[13], (const float*)d_in[17]);
  for (int i = 0; i < 3; i++) {
    const float* cw = (const float*)d_in[1 + 4 * i];
    const float* cb = (const float*)d_in[2 + 4 * i];
    const float* gw = (const float*)d_in[3 + 4 * i];
    const float* gb = (const float*)d_in[4 + 4 * i];
    int Cin = (i == 0) ? 257 : 256;
    int NCH = (i == 0) ? 17 : 16;
    wprep<<<NCH * 5, 256>>>(cw, Cin, NCH);
    mma_conv<<<dim3(2, BB), 256, CONV_SMEM>>>(p_xh, p_xl, cb, p_conv, NCH);
    gn_stats<<<BB * 16, 128>>>(p_conv, p_mu, p_rsig);
    interp_meta<<<2, 256>>>(p_gi, p_lam, keys[i][0], keys[i][1], keys[i][2],
                            keys[i][3], keys[i][4], keys[i][5]);
    interp_apply<<<dim3(BB, 6), 256>>>(p_conv, p_gi, p_lam, p_mu, p_rsig, gw, gb,
                                       p_xh, p_xl);
  }
  xg_mma<<<dim3(2, BB), 256, XG_SMEM>>>(p_xh, p_xl, (const float*)d_in[15],
                                        (const float*)d_in[16], (const float*)d_in[19],
                                        (const float*)d_in[20], p_xg);
  lstm_kernel<<<dim3(64, 2), 256>>>(p_xg, (const float*)d_in[14],
                                    (const float*)d_in[18], (float*)d_out);
}

// round 10
// speedup vs baseline: 5.1323x; 1.2273x over previous
#include <cuda_runtime.h>
#include <cuda_bf16.h>
#include <math.h>

#define BB 512
#define TT 192
#define CC 256
#define NCH0 17           // layer0 ci chunks of 16 (257 -> 272)
#define XSTR 24           // xg smem row stride (bf16): conflict-free

typedef unsigned int u32;

// ---------------- scratch (device globals; no allocation) ----------------
__device__ float g_conv[(size_t)BB * TT * CC];    // conv output, T-MAJOR [b][t][c]
__device__ float g_xg[(size_t)2 * BB * TT * 128]; // lstm pre-gates [dir,B,T,128]
__device__ float g_mu[BB * 16];
__device__ float g_rsig[BB * 16];
__device__ int   g_gi[3 * BB * TT];
__device__ float g_lam[3 * BB * TT];
// split-bf16 x image, chunk-major: [b][chunk<17][row 0..195][ci16]; row r <-> t=r-2
__device__ __nv_bfloat16 g_xh[(size_t)BB * NCH0 * 196 * 16];
__device__ __nv_bfloat16 g_xl[(size_t)BB * NCH0 * 196 * 16];
// split conv weights, chunk-major: [chunk][k 5][o 256][ci16]
__device__ __nv_bfloat16 g_wh[NCH0 * 5 * 256 * 16];
__device__ __nv_bfloat16 g_wl[NCH0 * 5 * 256 * 16];
// split xg weights: [dir 2][chunk 16][g 128][ci16]
__device__ __nv_bfloat16 g_wxh[2 * 16 * 128 * 16];
__device__ __nv_bfloat16 g_wxl[2 * 16 * 128 * 16];

// ---------------- threefry2x32 (JAX), host + device ----------------
__host__ __device__ __forceinline__ void tf2x32(unsigned k0, unsigned k1,
                                                unsigned x0, unsigned x1,
                                                unsigned& y0, unsigned& y1) {
  unsigned ks2 = k0 ^ k1 ^ 0x1BD11BDAu;
  x0 += k0; x1 += k1;
#define TFR(r) x0 += x1; x1 = (x1 << (r)) | (x1 >> (32 - (r))); x1 ^= x0;
  TFR(13) TFR(15) TFR(26) TFR(6)
  x0 += k1;  x1 += ks2 + 1u;
  TFR(17) TFR(29) TFR(16) TFR(24)
  x0 += ks2; x1 += k0 + 2u;
  TFR(13) TFR(15) TFR(26) TFR(6)
  x0 += k0;  x1 += k1 + 3u;
  TFR(17) TFR(29) TFR(16) TFR(24)
  x0 += k1;  x1 += ks2 + 4u;
  TFR(13) TFR(15) TFR(26) TFR(6)
  x0 += ks2; x1 += k0 + 5u;
#undef TFR
  y0 = x0; y1 = x1;
}

__device__ __forceinline__ unsigned tf_bits32(unsigned k0, unsigned k1, unsigned n) {
  unsigned y0, y1;
  tf2x32(k0, k1, 0u, n, y0, y1);
  return y0 ^ y1;
}

// ---------------- mma.sync + ldmatrix + cp.async ----------------
__device__ __forceinline__ void mma16816(float* c, const u32* a, const u32* b) {
  asm volatile(
      "mma.sync.aligned.m16n8k16.row.col.f32.bf16.bf16.f32 "
      "{%0,%1,%2,%3}, {%4,%5,%6,%7}, {%8,%9}, {%0,%1,%2,%3};"
      : "+f"(c[0]), "+f"(c[1]), "+f"(c[2]), "+f"(c[3])
      : "r"(a[0]), "r"(a[1]), "r"(a[2]), "r"(a[3]), "r"(b[0]), "r"(b[1]));
}

__device__ __forceinline__ void ldsm4(u32* r, unsigned addr) {
  asm volatile("ldmatrix.sync.aligned.m8n8.x4.shared.b16 {%0,%1,%2,%3}, [%4];"
               : "=r"(r[0]), "=r"(r[1]), "=r"(r[2]), "=r"(r[3]) : "r"(addr));
}

__device__ __forceinline__ void cpasync16(unsigned d, const void* g) {
  asm volatile("cp.async.cg.shared.global [%0], [%1], 16;" :: "r"(d), "l"(g));
}
#define CP_COMMIT() asm volatile("cp.async.commit_group;" ::: "memory")

// ---------------- conv weight prep ----------------
__global__ __launch_bounds__(256) void wprep(const float* __restrict__ w,
                                             int Cin, int NCH) {
  int chunk = blockIdx.x / 5, k = blockIdx.x % 5;
  int o = threadIdx.x;
  size_t base = (size_t)((chunk * 5 + k) * 256 + o) * 16;
  for (int cl = 0; cl < 16; cl++) {
    int ci = chunk * 16 + cl;
    float v = (ci < Cin) ? w[((size_t)o * Cin + ci) * 5 + k] : 0.f;
    __nv_bfloat16 h = __float2bfloat16(v);
    g_wh[base + cl] = h;
    g_wl[base + cl] = __float2bfloat16(v - __bfloat162float(h));
  }
}

// ---------------- xg weight prep: [dir][chunk][g][ci] ----------------
__global__ __launch_bounds__(128) void wprep_xg(const float* __restrict__ wf,
                                                const float* __restrict__ wb) {
  int dir = blockIdx.x >> 4, chunk = blockIdx.x & 15;
  int g = threadIdx.x;
  const float* w = dir ? wb : wf;
  size_t base = (size_t)((dir * 16 + chunk) * 128 + g) * 16;
  for (int cl = 0; cl < 16; cl++) {
    float v = w[(size_t)g * CC + chunk * 16 + cl];
    __nv_bfloat16 h = __float2bfloat16(v);
    g_wxh[base + cl] = h;
    g_wxl[base + cl] = __float2bfloat16(v - __bfloat162float(h));
  }
}

// ---------------- x0 prep: coalesced tile transpose + split + pad ----------------
__global__ __launch_bounds__(192) void x0prep(const float* __restrict__ x) {
  __shared__ float s[16][193];
  int b = blockIdx.x, ch = blockIdx.y;
  int tid = threadIdx.x;
#pragma unroll
  for (int i = 0; i < 16; i++) {
    int ci = ch * 16 + i;
    s[i][tid] = (ci < 257) ? x[((size_t)b * 257 + ci) * TT + tid] : 0.f;
  }
  __syncthreads();
  size_t ob = (size_t)b * NCH0 * 196 * 16 + (size_t)ch * 196 * 16;
  for (int idx = tid; idx < 196 * 16; idx += 192) {
    int row = idx >> 4, cl = idx & 15;
    int t = row - 2;
    float v = (t >= 0 && t < TT) ? s[cl][t] : 0.f;
    __nv_bfloat16 h = __float2bfloat16(v);
    g_xh[ob + idx] = h;
    g_xl[ob + idx] = __float2bfloat16(v - __bfloat162float(h));
  }
}

// ---------------- HMMA conv: swizzled smem, fused GroupNorm stats ----------------
#define SA_BYTES (10 * 128 * 32)
#define SB_BYTES (2 * 196 * 32)
#define STAGE_BYTES (SA_BYTES + SB_BYTES)
#define CONV_SMEM (STAGE_BYTES * 2)

__device__ __forceinline__ void conv_fill(int chunk, unsigned sstage, int oHalf,
                                          const __nv_bfloat16* xbh,
                                          const __nv_bfloat16* xbl, int tid) {
  // A: 10 tiles (k*2+sp) x 128 o x 16 ci = 2560 16B-chunks, XOR-swizzled
  for (int i = tid; i < 2560; i += 256) {
    int ksp = i >> 8;
    int rem = i & 255;
    int o = rem >> 1, half = rem & 1;
    int k = ksp >> 1, sp = ksp & 1;
    const __nv_bfloat16* wsrc = sp ? g_wl : g_wh;
    const void* g = wsrc + ((size_t)((chunk * 5 + k) * 256 + oHalf * 128 + o) * 16 + half * 8);
    unsigned d = sstage + (unsigned)((ksp * 128 + o) * 32 + ((half ^ ((o >> 2) & 1)) << 4));
    cpasync16(d, g);
  }
  // B: 2 splits x 196 rows x 16 = 784 16B-chunks, XOR-swizzled
  for (int i = tid; i < 784; i += 256) {
    int sp = i >= 392;
    int rem = sp ? i - 392 : i;
    int row = rem >> 1, half = rem & 1;
    const __nv_bfloat16* xs = sp ? xbl : xbh;
    const void* g = xs + ((size_t)(chunk * 196 + row) * 16 + half * 8);
    int rowg = sp * 196 + row;
    unsigned d = sstage + (unsigned)(SA_BYTES + rowg * 32 + ((half ^ ((rowg >> 2) & 1)) << 4));
    cpasync16(d, g);
  }
}

__global__ __launch_bounds__(256, 2) void mma_conv(
    const __nv_bfloat16* __restrict__ xh, const __nv_bfloat16* __restrict__ xl,
    const float* __restrict__ bias, float* __restrict__ outT, int NCH) {
  extern __shared__ __nv_bfloat16 sm[];
  int oHalf = blockIdx.x, b = blockIdx.y;
  int tid = threadIdx.x;
  int warp = tid >> 5, lane = tid & 31;
  int warpO = warp & 1, warpT = warp >> 1;
  int oBaseL = warpO * 64, tBase = warpT * 48;
  int lr = lane >> 2, lc = lane & 3;

  unsigned sb0 = (unsigned)__cvta_generic_to_shared(sm);
  // A: per-lane swizzled offset (tile offsets are multiples of 8 rows -> bit2 static)
  int lane_rA = (lane & 7) + ((lane >> 3) & 1) * 8;
  unsigned rowA_off = (unsigned)((oBaseL + lane_rA) * 32 +
                                 ((((lane >> 4) & 1) ^ ((lane_rA >> 2) & 1)) << 4));
  // B: per-lane row base; swizzle XOR computed per (sp,k)
  int tbl = tBase + (lane & 7) + ((lane >> 4) & 1) * 8;
  unsigned hB16 = (unsigned)(((lane >> 3) & 1) << 4);

  float acc[4][6][4];
#pragma unroll
  for (int ot = 0; ot < 4; ot++)
#pragma unroll
    for (int tt = 0; tt < 6; tt++)
#pragma unroll
      for (int q = 0; q < 4; q++) acc[ot][tt][q] = 0.f;

  const __nv_bfloat16* xbh = xh + (size_t)b * NCH0 * 196 * 16;
  const __nv_bfloat16* xbl = xl + (size_t)b * NCH0 * 196 * 16;

  conv_fill(0, sb0, oHalf, xbh, xbl, tid);
  CP_COMMIT();

  for (int it = 0; it < NCH; it++) {
    int s = it & 1;
    if (it + 1 < NCH) {
      conv_fill(it + 1, sb0 + (unsigned)((s ^ 1) * STAGE_BYTES), oHalf, xbh, xbl, tid);
      CP_COMMIT();
      asm volatile("cp.async.wait_group 1;" ::: "memory");
    } else {
      asm volatile("cp.async.wait_group 0;" ::: "memory");
    }
    __syncthreads();
    unsigned sbA = sb0 + (unsigned)(s * STAGE_BYTES);
    unsigned sbB = sbA + (unsigned)SA_BYTES;
#pragma unroll 1
    for (int sp = 0; sp < 3; sp++) {
      int aSel = (sp == 2) ? 1 : 0;   // hh, hl, lh
      int bSel = (sp == 1) ? 1 : 0;
#pragma unroll
      for (int k = 0; k < 5; k++) {
        int row0 = bSel * 196 + tbl + k;
        unsigned baseB = sbB + (unsigned)(row0 * 32) +
                         (hB16 ^ (unsigned)((((unsigned)row0 >> 2) & 1) << 4));
        u32 bfr[6][2];
#pragma unroll
        for (int q = 0; q < 3; q++)
          ldsm4(&bfr[2 * q][0], baseB + (unsigned)(q * 512));
        unsigned baseA = sbA + (unsigned)((k * 2 + aSel) * 128 * 32) + rowA_off;
#pragma unroll
        for (int ot = 0; ot < 4; ot++) {
          u32 af[4];
          ldsm4(af, baseA + (unsigned)(ot * 16 * 32));
#pragma unroll
          for (int tt = 0; tt < 6; tt++) mma16816(acc[ot][tt], af, bfr[tt]);
        }
      }
    }
    __syncthreads();
  }

  // ---- fused GroupNorm stats (each CTA owns 8 full channel-groups) ----
  float bvA[4], bvB[4];
#pragma unroll
  for (int ot = 0; ot < 4; ot++) {
    int o0 = oHalf * 128 + oBaseL + ot * 16 + lr;
    bvA[ot] = __ldg(bias + o0);
    bvB[ot] = __ldg(bias + o0 + 8);
  }
  {
    float* gsm = (float*)sm + 6336;
#pragma unroll
    for (int ot = 0; ot < 4; ot++) {
      float s = 0.f, s2 = 0.f;
#pragma unroll
      for (int tt = 0; tt < 6; tt++) {
#pragma unroll
        for (int q = 0; q < 4; q++) {
          float v = acc[ot][tt][q] + ((q < 2) ? bvA[ot] : bvB[ot]);
          s += v;
          s2 = fmaf(v, v, s2);
        }
      }
#pragma unroll
      for (int off = 16; off; off >>= 1) {
        s += __shfl_xor_sync(0xffffffffu, s, off);
        s2 += __shfl_xor_sync(0xffffffffu, s2, off);
      }
      if (lane == 0) {
        gsm[warp * 8 + ot * 2] = s;
        gsm[warp * 8 + ot * 2 + 1] = s2;
      }
    }
    __syncthreads();
    if (tid < 8) {
      int g = tid;
      float s = 0.f, s2 = 0.f;
#pragma unroll
      for (int wt = 0; wt < 4; wt++) {
        int w2 = (wt * 2 + (g >> 2)) * 8 + (g & 3) * 2;
        s += gsm[w2];
        s2 += gsm[w2 + 1];
      }
      float m = s * (1.0f / 3072.0f);
      float var = s2 * (1.0f / 3072.0f) - m * m;
      g_mu[b * 16 + oHalf * 8 + g] = m;
      g_rsig[b * 16 + oHalf * 8 + g] = rsqrtf(var + 1e-5f);
    }
  }

  // ---- epilogue: smem-staged transpose -> t-major coalesced stores ----
  float* stage = (float*)sm;
  for (int q = 0; q < 4; q++) {
    __syncthreads();
    if (warpT == q) {
#pragma unroll
      for (int ot = 0; ot < 4; ot++) {
        int o0 = oBaseL + ot * 16 + lr;
#pragma unroll
        for (int tt = 0; tt < 6; tt++) {
          int tl = tt * 8 + lc * 2;
          stage[tl * 132 + o0] = acc[ot][tt][0] + bvA[ot];
          stage[(tl + 1) * 132 + o0] = acc[ot][tt][1] + bvA[ot];
          stage[tl * 132 + o0 + 8] = acc[ot][tt][2] + bvB[ot];
          stage[(tl + 1) * 132 + o0 + 8] = acc[ot][tt][3] + bvB[ot];
        }
      }
    }
    __syncthreads();
    for (int i = tid; i < 6144; i += 256) {
      int tl = i >> 7, o = i & 127;
      outT[((size_t)b * TT + q * 48 + tl) * CC + oHalf * 128 + o] = stage[tl * 132 + o];
    }
  }
}

// ---------------- HMMA xg GEMM: CTA = (dir, b); 128g x 192t, K=256 ----------------
#define XA_ELEMS (2 * 128 * XSTR)
#define XB_ELEMS (2 * 192 * XSTR)
#define XG_SMEM_MAIN ((XA_ELEMS + XB_ELEMS) * 2)
#define XG_SMEM_STAGE (48 * 132 * 4)
#define XG_SMEM (XG_SMEM_MAIN > XG_SMEM_STAGE ? XG_SMEM_MAIN : XG_SMEM_STAGE)

__global__ __launch_bounds__(256) void xg_mma(
    const __nv_bfloat16* __restrict__ xh, const __nv_bfloat16* __restrict__ xl,
    const float* __restrict__ bif, const float* __restrict__ bhf,
    const float* __restrict__ bib, const float* __restrict__ bhb,
    float* __restrict__ xg) {
  extern __shared__ char xsm[];
  __nv_bfloat16* sA = (__nv_bfloat16*)xsm;            // [2][128][XSTR]
  __nv_bfloat16* sB = sA + XA_ELEMS;                  // [2][192][XSTR]
  float* stage = (float*)xsm;                         // [48][132], reused
  int dir = blockIdx.x, b = blockIdx.y;
  const float* bi = dir ? bib : bif;
  const float* bh = dir ? bhb : bhf;
  int tid = threadIdx.x;
  int warp = tid >> 5, lane = tid & 31;
  int warpO = warp & 1, warpT = warp >> 1;
  int oBaseL = warpO * 64, tBase = warpT * 48;
  int lr = lane >> 2, lc = lane & 3;

  unsigned sbA = (unsigned)__cvta_generic_to_shared(sA);
  unsigned sbB = (unsigned)__cvta_generic_to_shared(sB);
  unsigned rowA_off = ((oBaseL + (lane & 7) + ((lane >> 3) & 1) * 8) * XSTR +
                       ((lane >> 4) & 1) * 8) * 2;
  unsigned rowB_off = ((tBase + (lane & 7) + ((lane >> 4) & 1) * 8) * XSTR +
                       ((lane >> 3) & 1) * 8) * 2;

  float acc[4][6][4];
#pragma unroll
  for (int ot = 0; ot < 4; ot++)
#pragma unroll
    for (int tt = 0; tt < 6; tt++)
#pragma unroll
      for (int q = 0; q < 4; q++) acc[ot][tt][q] = 0.f;

  const __nv_bfloat16* xsrc[2] = {xh + (size_t)b * NCH0 * 196 * 16,
                                  xl + (size_t)b * NCH0 * 196 * 16};
  for (int chunk = 0; chunk < 16; chunk++) {
    for (int i = tid; i < 2048; i += 256) {
      int sp = i >> 10;
      int rem = i & 1023;
      int o = rem >> 3, cp = rem & 7;
      const __nv_bfloat16* wsrc = sp ? g_wxl : g_wxh;
      u32 v = *(const u32*)(wsrc + ((size_t)((dir * 16 + chunk) * 128 + o) * 16 + cp * 2));
      *(u32*)(sA + (sp * 128 + o) * XSTR + cp * 2) = v;
    }
    for (int i = tid; i < 3072; i += 256) {
      int sp = i >= 1536;
      int rem = sp ? i - 1536 : i;
      int row = rem >> 3, cp = rem & 7;
      u32 v = *(const u32*)(xsrc[sp] + ((size_t)(chunk * 196 + 2 + row) * 16 + cp * 2));
      *(u32*)(sB + (sp * 192 + row) * XSTR + cp * 2) = v;
    }
    __syncthreads();
#pragma unroll 1
    for (int sp = 0; sp < 3; sp++) {
      int aSel = (sp == 2) ? 1 : 0;
      int bSel = (sp == 1) ? 1 : 0;
      u32 bfr[6][2];
      unsigned baseB = sbB + (unsigned)(bSel * 192 * XSTR * 2) + rowB_off;
#pragma unroll
      for (int q = 0; q < 3; q++)
        ldsm4(&bfr[2 * q][0], baseB + (unsigned)(q * 16 * XSTR * 2));
      unsigned baseA = sbA + (unsigned)(aSel * 128 * XSTR * 2) + rowA_off;
#pragma unroll
      for (int ot = 0; ot < 4; ot++) {
        u32 af[4];
        ldsm4(af, baseA + (unsigned)(ot * 16 * XSTR * 2));
#pragma unroll
        for (int tt = 0; tt < 6; tt++) mma16816(acc[ot][tt], af, bfr[tt]);
      }
    }
    __syncthreads();
  }
  float* xgb = xg + (size_t)(dir * BB + b) * TT * 128;
  for (int q = 0; q < 4; q++) {
    __syncthreads();
    if (warpT == q) {
#pragma unroll
      for (int ot = 0; ot < 4; ot++) {
        int o0 = oBaseL + ot * 16 + lr;
#pragma unroll
        for (int tt = 0; tt < 6; tt++) {
          int tl = tt * 8 + lc * 2;
          stage[tl * 132 + o0] = acc[ot][tt][0];
          stage[(tl + 1) * 132 + o0] = acc[ot][tt][1];
          stage[tl * 132 + o0 + 8] = acc[ot][tt][2];
          stage[(tl + 1) * 132 + o0 + 8] = acc[ot][tt][3];
        }
      }
    }
    __syncthreads();
    for (int i = tid; i < 6144; i += 256) {
      int tl = i >> 7, g = i & 127;
      xgb[(size_t)(q * 48 + tl) * 128 + g] =
          stage[tl * 132 + g] + __ldg(bi + g) + __ldg(bh + g);
    }
  }
}

// ---------------- interp_lnr metadata: all 3 layers in one launch ----------------
struct KeyPack { unsigned v[18]; };

__global__ void interp_meta_all(int* __restrict__ gi, float* __restrict__ lam,
                                KeyPack kp) {
  int layer = blockIdx.y;
  int b = blockIdx.x * blockDim.x + threadIdx.x;
  if (b >= BB) return;
  const unsigned* K = kp.v + layer * 6;
  int base = layer * BB * TT + b * TT;
  for (int t = 0; t < TT; t++) gi[base + t] = -1;
  int off = 0, pos = 0;
  for (int s = 0; s < 7; s++) {
    unsigned n = (unsigned)(b * 7 + s);
    unsigned ub = tf_bits32(K[0], K[1], n);
    float f = __uint_as_float((ub >> 9) | 0x3f800000u) - 1.0f;
    float scale = f + 0.5f;
    unsigned hb = tf_bits32(K[2], K[3], n);
    unsigned lb = tf_bits32(K[4], K[5], n);
    unsigned offt = ((hb % 13u) * 9u + lb % 13u) % 13u;
    int len = 19 + (int)offt;
    float lenm1 = (float)(len - 1);
    for (int l = 0; l < 64; l++) {
      float idx = __fdiv_rn((float)l, scale);
      float fl = floorf(idx);
      float lm = idx - fl;
      if (fl < lenm1) {
        int io = (int)fl + off;
        if (io < TT - 1) {
          if (pos < TT) { gi[base + pos] = io; lam[base + pos] = lm; }
          pos++;
        }
      }
    }
    off += len;
  }
}

// ---------------- interp apply (t-major conv): coalesced gather ----------------
__global__ __launch_bounds__(256) void interp_apply(
    const float* __restrict__ convT, const int* __restrict__ gi,
    const float* __restrict__ lam, const float* __restrict__ mu,
    const float* __restrict__ rsig, const float* __restrict__ gnw,
    const float* __restrict__ gnb,
    __nv_bfloat16* __restrict__ xh, __nv_bfloat16* __restrict__ xl) {
  int b = blockIdx.x, c = threadIdx.x;
  int t0 = blockIdx.y * 32;
  __shared__ int sg[32];
  __shared__ float sl[32];
  if (c < 32) {
    sg[c] = gi[b * TT + t0 + c];
    sl[c] = lam[b * TT + t0 + c];
  }
  __syncthreads();
  float m = mu[b * 16 + (c >> 4)];
  float rs = rsig[b * 16 + (c >> 4)];
  float w = gnw[c], be = gnb[c];
  const float* cb = convT + (size_t)b * TT * CC;
  size_t ib = (size_t)b * NCH0 * 196 * 16;
  size_t xbase = ib + (size_t)(c >> 4) * 196 * 16 + (c & 15);
#pragma unroll 1
  for (int tt = 0; tt < 32; tt++) {
    int g = sg[tt];
    float val = 0.f;
    if (g >= 0) {
      float lm = sl[tt];
      float a = cb[(size_t)g * CC + c];
      float e = cb[(size_t)(g + 1) * CC + c];
      float fa = fmaxf((a - m) * rs * w + be, 0.f);
      float fb = fmaxf((e - m) * rs * w + be, 0.f);
      val = (1.0f - lm) * fa + lm * fb;
    }
    size_t xi = xbase + (size_t)(t0 + tt + 2) * 16;
    __nv_bfloat16 h = __float2bfloat16(val);
    xh[xi] = h;
    xl[xi] = __float2bfloat16(val - __bfloat162float(h));
  }
  if (blockIdx.y == 0) {  // zero pad rows 0,1,194,195 for all 16 chunks
    int chunk = c >> 4, cl = c & 15;
#pragma unroll
    for (int rr = 0; rr < 4; rr++) {
      int r = (rr < 2) ? rr : (192 + rr);
      size_t xi = ib + (size_t)(chunk * 196 + r) * 16 + cl;
      xh[xi] = __float2bfloat16(0.f);
      xl[xi] = __float2bfloat16(0.f);
    }
  }
}

// ---------------- LSTM recurrence: warp per batch element ----------------
__device__ __forceinline__ float sigf(float x) { return 1.0f / (1.0f + expf(-x)); }

__global__ __launch_bounds__(256) void lstm_kernel(
    const float* __restrict__ xg, const float* __restrict__ whf,
    const float* __restrict__ whb, float* __restrict__ out) {
  __shared__ float ws[32 * 128];
  int dir = blockIdx.y;
  const float* wh = dir ? whb : whf;
  int tid = threadIdx.x;
  for (int idx = tid; idx < 4096; idx += 256) {
    int j = idx >> 7, r = idx & 127;
    ws[idx] = wh[r * 32 + j];
  }
  __syncthreads();
  int warp = tid >> 5, lane = tid & 31;
  int b = blockIdx.x * 8 + warp;
  const float* xgb = xg + (size_t)(dir * BB + b) * TT * 128;
  float h = 0.f, c = 0.f;
  for (int step = 0; step < TT; step++) {
    int t = dir ? (TT - 1 - step) : step;
    const float* p = xgb + (size_t)t * 128;
    float gi = p[lane], gf = p[32 + lane], gg = p[64 + lane], go = p[96 + lane];
#pragma unroll
    for (int j = 0; j < 32; j++) {
      float hj = __shfl_sync(0xffffffffu, h, j);
      const float* wr = ws + j * 128;
      gi = fmaf(wr[lane], hj, gi);
      gf = fmaf(wr[32 + lane], hj, gf);
      gg = fmaf(wr[64 + lane], hj, gg);
      go = fmaf(wr[96 + lane], hj, go);
    }
    c = sigf(gf) * c + sigf(gi) * tanhf(gg);
    h = sigf(go) * tanhf(c);
    if (dir == 0) {
      if ((t & 7) == 7) out[((size_t)b * 24 + (t >> 3)) * 64 + lane] = h;
    } else {
      if ((t & 7) == 0) out[((size_t)b * 24 + (t >> 3)) * 64 + 32 + lane] = h;
    }
  }
}

// ---------------- launch ----------------
extern "C" void kernel_launch(void* const* d_in, const int* in_sizes, int n_in,
                              void* d_out, int out_size) {
  (void)in_sizes; (void)n_in; (void)out_size;
  float *p_conv, *p_xg, *p_mu, *p_rsig, *p_lam;
  int* p_gi;
  __nv_bfloat16 *p_xh, *p_xl;
  cudaGetSymbolAddress((void**)&p_conv, g_conv);
  cudaGetSymbolAddress((void**)&p_xg, g_xg);
  cudaGetSymbolAddress((void**)&p_mu, g_mu);
  cudaGetSymbolAddress((void**)&p_rsig, g_rsig);
  cudaGetSymbolAddress((void**)&p_gi, g_gi);
  cudaGetSymbolAddress((void**)&p_lam, g_lam);
  cudaGetSymbolAddress((void**)&p_xh, g_xh);
  cudaGetSymbolAddress((void**)&p_xl, g_xl);

  static int smem_set = 0;
  if (!smem_set) {
    cudaFuncSetAttribute(mma_conv, cudaFuncAttributeMaxDynamicSharedMemorySize, CONV_SMEM);
    cudaFuncSetAttribute(xg_mma, cudaFuncAttributeMaxDynamicSharedMemorySize, XG_SMEM);
    smem_set = 1;
  }

  const float* x0 = (const float*)d_in[0];

  // JAX threefry keys: rng = key(42); per layer i: fold_in -> split -> randint split
  KeyPack kp;
  for (int i = 0; i < 3; i++) {
    unsigned f0, f1;
    tf2x32(0u, 42u, 0u, (unsigned)i, f0, f1);
    unsigned k1a, k1b, k2a, k2b;
    tf2x32(f0, f1, 0u, 0u, k1a, k1b);
    tf2x32(f0, f1, 0u, 1u, k2a, k2b);
    unsigned ha, hb2, la, lb2;
    tf2x32(k2a, k2b, 0u, 0u, ha, hb2);
    tf2x32(k2a, k2b, 0u, 1u, la, lb2);
    kp.v[i * 6 + 0] = k1a; kp.v[i * 6 + 1] = k1b;
    kp.v[i * 6 + 2] = ha;  kp.v[i * 6 + 3] = hb2;
    kp.v[i * 6 + 4] = la;  kp.v[i * 6 + 5] = lb2;
  }

  x0prep<<<dim3(BB, NCH0), 192>>>(x0);
  wprep_xg<<<32, 128>>>((const float*)d_in[13], (const float*)d_in[17]);
  interp_meta_all<<<dim3(2, 3), 256>>>(p_gi, p_lam, kp);
  for (int i = 0; i < 3; i++) {
    const float* cw = (const float*)d_in[1 + 4 * i];
    const float* cb = (const float*)d_in[2 + 4 * i];
    const float* gw = (const float*)d_in[3 + 4 * i];
    const float* gb = (const float*)d_in[4 + 4 * i];
    int Cin = (i == 0) ? 257 : 256;
    int NCH = (i == 0) ? 17 : 16;
    wprep<<<NCH * 5, 256>>>(cw, Cin, NCH);
    mma_conv<<<dim3(2, BB), 256, CONV_SMEM>>>(p_xh, p_xl, cb, p_conv, NCH);
    interp_apply<<<dim3(BB, 6), 256>>>(p_conv, p_gi + i * BB * TT, p_lam + i * BB * TT,
                                       p_mu, p_rsig, gw, gb, p_xh, p_xl);
  }
  xg_mma<<<dim3(2, BB), 256, XG_SMEM>>>(p_xh, p_xl, (const float*)d_in[15],
                                        (const float*)d_in[16], (const float*)d_in[19],
                                        (const float*)d_in[20], p_xg);
  lstm_kernel<<<dim3(64, 2), 256>>>(p_xg, (const float*)d_in[14],
                                    (const float*)d_in[18], (float*)d_out);
}

// round 11
// speedup vs baseline: 5.3880x; 1.0498x over previous
#include <cuda_runtime.h>
#include <cuda_bf16.h>
#include <math.h>

#define BB 512
#define TT 192
#define CC 256
#define NCH0 17           // layer0 ci chunks of 16 (257 -> 272)
#define XSTR 24           // xg smem row stride (bf16): conflict-free

typedef unsigned int u32;

// ---------------- scratch (device globals; no allocation) ----------------
__device__ float g_xg[(size_t)2 * BB * TT * 128]; // lstm pre-gates [dir,B,T,128]
__device__ float g_mu[BB * 16];
__device__ float g_rsig[BB * 16];
__device__ int   g_gi[3 * BB * TT];
__device__ float g_lam[3 * BB * TT];
// split-bf16 x image, chunk-major: [b][chunk<17][row 0..195][ci16]; row r <-> t=r-2
__device__ __nv_bfloat16 g_xh[(size_t)BB * NCH0 * 196 * 16];
__device__ __nv_bfloat16 g_xl[(size_t)BB * NCH0 * 196 * 16];
// split conv weights, all 3 layers: [layer-chunk 49][k 5][o 256][ci16]
__device__ __nv_bfloat16 g_wh[49 * 5 * 256 * 16];
__device__ __nv_bfloat16 g_wl[49 * 5 * 256 * 16];
// split xg weights: [dir 2][chunk 16][g 128][ci16]
__device__ __nv_bfloat16 g_wxh[2 * 16 * 128 * 16];
__device__ __nv_bfloat16 g_wxl[2 * 16 * 128 * 16];

// ---------------- threefry2x32 (JAX), host + device ----------------
__host__ __device__ __forceinline__ void tf2x32(unsigned k0, unsigned k1,
                                                unsigned x0, unsigned x1,
                                                unsigned& y0, unsigned& y1) {
  unsigned ks2 = k0 ^ k1 ^ 0x1BD11BDAu;
  x0 += k0; x1 += k1;
#define TFR(r) x0 += x1; x1 = (x1 << (r)) | (x1 >> (32 - (r))); x1 ^= x0;
  TFR(13) TFR(15) TFR(26) TFR(6)
  x0 += k1;  x1 += ks2 + 1u;
  TFR(17) TFR(29) TFR(16) TFR(24)
  x0 += ks2; x1 += k0 + 2u;
  TFR(13) TFR(15) TFR(26) TFR(6)
  x0 += k0;  x1 += k1 + 3u;
  TFR(17) TFR(29) TFR(16) TFR(24)
  x0 += k1;  x1 += ks2 + 4u;
  TFR(13) TFR(15) TFR(26) TFR(6)
  x0 += ks2; x1 += k0 + 5u;
#undef TFR
  y0 = x0; y1 = x1;
}

__device__ __forceinline__ unsigned tf_bits32(unsigned k0, unsigned k1, unsigned n) {
  unsigned y0, y1;
  tf2x32(k0, k1, 0u, n, y0, y1);
  return y0 ^ y1;
}

// ---------------- mma.sync + ldmatrix + cp.async ----------------
__device__ __forceinline__ void mma16816(float* c, const u32* a, const u32* b) {
  asm volatile(
      "mma.sync.aligned.m16n8k16.row.col.f32.bf16.bf16.f32 "
      "{%0,%1,%2,%3}, {%4,%5,%6,%7}, {%8,%9}, {%0,%1,%2,%3};"
      : "+f"(c[0]), "+f"(c[1]), "+f"(c[2]), "+f"(c[3])
      : "r"(a[0]), "r"(a[1]), "r"(a[2]), "r"(a[3]), "r"(b[0]), "r"(b[1]));
}

__device__ __forceinline__ void ldsm4(u32* r, unsigned addr) {
  asm volatile("ldmatrix.sync.aligned.m8n8.x4.shared.b16 {%0,%1,%2,%3}, [%4];"
               : "=r"(r[0]), "=r"(r[1]), "=r"(r[2]), "=r"(r[3]) : "r"(addr));
}

__device__ __forceinline__ void cpasync16(unsigned d, const void* g) {
  asm volatile("cp.async.cg.shared.global [%0], [%1], 16;" :: "r"(d), "l"(g));
}
#define CP_COMMIT() asm volatile("cp.async.commit_group;" ::: "memory")

// ---------------- conv weight prep (per-layer disjoint regions) ----------------
__global__ __launch_bounds__(256) void wprep(const float* __restrict__ w,
                                             int Cin, int NCH,
                                             __nv_bfloat16* __restrict__ wh,
                                             __nv_bfloat16* __restrict__ wl) {
  int chunk = blockIdx.x / 5, k = blockIdx.x % 5;
  int o = threadIdx.x;
  size_t base = (size_t)((chunk * 5 + k) * 256 + o) * 16;
  for (int cl = 0; cl < 16; cl++) {
    int ci = chunk * 16 + cl;
    float v = (ci < Cin) ? w[((size_t)o * Cin + ci) * 5 + k] : 0.f;
    __nv_bfloat16 h = __float2bfloat16(v);
    wh[base + cl] = h;
    wl[base + cl] = __float2bfloat16(v - __bfloat162float(h));
  }
}

// ---------------- xg weight prep: [dir][chunk][g][ci] ----------------
__global__ __launch_bounds__(128) void wprep_xg(const float* __restrict__ wf,
                                                const float* __restrict__ wb) {
  int dir = blockIdx.x >> 4, chunk = blockIdx.x & 15;
  int g = threadIdx.x;
  const float* w = dir ? wb : wf;
  size_t base = (size_t)((dir * 16 + chunk) * 128 + g) * 16;
  for (int cl = 0; cl < 16; cl++) {
    float v = w[(size_t)g * CC + chunk * 16 + cl];
    __nv_bfloat16 h = __float2bfloat16(v);
    g_wxh[base + cl] = h;
    g_wxl[base + cl] = __float2bfloat16(v - __bfloat162float(h));
  }
}

// ---------------- x0 prep: coalesced tile transpose + split + pad ----------------
__global__ __launch_bounds__(192) void x0prep(const float* __restrict__ x) {
  __shared__ float s[16][193];
  int b = blockIdx.x, ch = blockIdx.y;
  int tid = threadIdx.x;
#pragma unroll
  for (int i = 0; i < 16; i++) {
    int ci = ch * 16 + i;
    s[i][tid] = (ci < 257) ? x[((size_t)b * 257 + ci) * TT + tid] : 0.f;
  }
  __syncthreads();
  size_t ob = (size_t)b * NCH0 * 196 * 16 + (size_t)ch * 196 * 16;
  for (int idx = tid; idx < 196 * 16; idx += 192) {
    int row = idx >> 4, cl = idx & 15;
    int t = row - 2;
    float v = (t >= 0 && t < TT) ? s[cl][t] : 0.f;
    __nv_bfloat16 h = __float2bfloat16(v);
    g_xh[ob + idx] = h;
    g_xl[ob + idx] = __float2bfloat16(v - __bfloat162float(h));
  }
}

// ---------------- interp_lnr metadata: all 3 layers in one launch ----------------
struct KeyPack { unsigned v[18]; };

__global__ void interp_meta_all(int* __restrict__ gi, float* __restrict__ lam,
                                KeyPack kp) {
  int layer = blockIdx.y;
  int b = blockIdx.x * blockDim.x + threadIdx.x;
  if (b >= BB) return;
  const unsigned* K = kp.v + layer * 6;
  int base = layer * BB * TT + b * TT;
  for (int t = 0; t < TT; t++) gi[base + t] = -1;
  int off = 0, pos = 0;
  for (int s = 0; s < 7; s++) {
    unsigned n = (unsigned)(b * 7 + s);
    unsigned ub = tf_bits32(K[0], K[1], n);
    float f = __uint_as_float((ub >> 9) | 0x3f800000u) - 1.0f;
    float scale = f + 0.5f;
    unsigned hb = tf_bits32(K[2], K[3], n);
    unsigned lb = tf_bits32(K[4], K[5], n);
    unsigned offt = ((hb % 13u) * 9u + lb % 13u) % 13u;
    int len = 19 + (int)offt;
    float lenm1 = (float)(len - 1);
    for (int l = 0; l < 64; l++) {
      float idx = __fdiv_rn((float)l, scale);
      float fl = floorf(idx);
      float lm = idx - fl;
      if (fl < lenm1) {
        int io = (int)fl + off;
        if (io < TT - 1) {
          if (pos < TT) { gi[base + pos] = io; lam[base + pos] = lm; }
          pos++;
        }
      }
    }
    off += len;
  }
}

// ---------------- HMMA conv: swizzled smem, fused GN + interp epilogue ----------------
#define SA_BYTES (10 * 128 * 32)
#define SB_BYTES (2 * 196 * 32)
#define STAGE_BYTES (SA_BYTES + SB_BYTES)
#define CONV_SMEM (STAGE_BYTES * 2)

__device__ __forceinline__ void conv_fill(int chunk, unsigned sstage, int oHalf,
                                          const __nv_bfloat16* wh,
                                          const __nv_bfloat16* wl,
                                          const __nv_bfloat16* xbh,
                                          const __nv_bfloat16* xbl, int tid) {
  for (int i = tid; i < 2560; i += 256) {
    int ksp = i >> 8;
    int rem = i & 255;
    int o = rem >> 1, half = rem & 1;
    int k = ksp >> 1, sp = ksp & 1;
    const __nv_bfloat16* wsrc = sp ? wl : wh;
    const void* g = wsrc + ((size_t)((chunk * 5 + k) * 256 + oHalf * 128 + o) * 16 + half * 8);
    unsigned d = sstage + (unsigned)((ksp * 128 + o) * 32 + ((half ^ ((o >> 2) & 1)) << 4));
    cpasync16(d, g);
  }
  for (int i = tid; i < 784; i += 256) {
    int sp = i >= 392;
    int rem = sp ? i - 392 : i;
    int row = rem >> 1, half = rem & 1;
    const __nv_bfloat16* xs = sp ? xbl : xbh;
    const void* g = xs + ((size_t)(chunk * 196 + row) * 16 + half * 8);
    int rowg = sp * 196 + row;
    unsigned d = sstage + (unsigned)(SA_BYTES + rowg * 32 + ((half ^ ((rowg >> 2) & 1)) << 4));
    cpasync16(d, g);
  }
}

__global__ __launch_bounds__(256, 2) void mma_conv(
    const __nv_bfloat16* __restrict__ wh, const __nv_bfloat16* __restrict__ wl,
    const float* __restrict__ bias,
    const int* __restrict__ gi, const float* __restrict__ lam,
    const float* __restrict__ gnw, const float* __restrict__ gnb,
    __nv_bfloat16* __restrict__ oxh, __nv_bfloat16* __restrict__ oxl,
    int NCH) {
  extern __shared__ __nv_bfloat16 sm[];
  int oHalf = blockIdx.x, b = blockIdx.y;
  int tid = threadIdx.x;
  int warp = tid >> 5, lane = tid & 31;
  int warpO = warp & 1, warpT = warp >> 1;
  int oBaseL = warpO * 64, tBase = warpT * 48;
  int lr = lane >> 2, lc = lane & 3;

  unsigned sb0 = (unsigned)__cvta_generic_to_shared(sm);
  int lane_rA = (lane & 7) + ((lane >> 3) & 1) * 8;
  unsigned rowA_off = (unsigned)((oBaseL + lane_rA) * 32 +
                                 ((((lane >> 4) & 1) ^ ((lane_rA >> 2) & 1)) << 4));
  int tbl = tBase + (lane & 7) + ((lane >> 4) & 1) * 8;
  unsigned hB16 = (unsigned)(((lane >> 3) & 1) << 4);

  float acc[4][6][4];
#pragma unroll
  for (int ot = 0; ot < 4; ot++)
#pragma unroll
    for (int tt = 0; tt < 6; tt++)
#pragma unroll
      for (int q = 0; q < 4; q++) acc[ot][tt][q] = 0.f;

  const __nv_bfloat16* xbh = g_xh + (size_t)b * NCH0 * 196 * 16;
  const __nv_bfloat16* xbl = g_xl + (size_t)b * NCH0 * 196 * 16;

  conv_fill(0, sb0, oHalf, wh, wl, xbh, xbl, tid);
  CP_COMMIT();

  for (int it = 0; it < NCH; it++) {
    int s = it & 1;
    if (it + 1 < NCH) {
      conv_fill(it + 1, sb0 + (unsigned)((s ^ 1) * STAGE_BYTES), oHalf, wh, wl, xbh, xbl, tid);
      CP_COMMIT();
      asm volatile("cp.async.wait_group 1;" ::: "memory");
    } else {
      asm volatile("cp.async.wait_group 0;" ::: "memory");
    }
    __syncthreads();
    unsigned sbA = sb0 + (unsigned)(s * STAGE_BYTES);
    unsigned sbB = sbA + (unsigned)SA_BYTES;
#pragma unroll 1
    for (int sp = 0; sp < 3; sp++) {
      int aSel = (sp == 2) ? 1 : 0;   // hh, hl, lh
      int bSel = (sp == 1) ? 1 : 0;
#pragma unroll
      for (int k = 0; k < 5; k++) {
        int row0 = bSel * 196 + tbl + k;
        unsigned baseB = sbB + (unsigned)(row0 * 32) +
                         (hB16 ^ (unsigned)((((unsigned)row0 >> 2) & 1) << 4));
        u32 bfr[6][2];
#pragma unroll
        for (int q = 0; q < 3; q++)
          ldsm4(&bfr[2 * q][0], baseB + (unsigned)(q * 512));
        unsigned baseA = sbA + (unsigned)((k * 2 + aSel) * 128 * 32) + rowA_off;
#pragma unroll
        for (int ot = 0; ot < 4; ot++) {
          u32 af[4];
          ldsm4(af, baseA + (unsigned)(ot * 16 * 32));
#pragma unroll
          for (int tt = 0; tt < 6; tt++) mma16816(acc[ot][tt], af, bfr[tt]);
        }
      }
    }
    __syncthreads();
  }

  // ---- epilogue: stats + full-tile smem stage + fused interp ----
  float* stage = (float*)sm;                 // [192][132] fp32
  float* gsm = stage + 25344;                // 64
  float* smu = stage + 25408;                // 8
  float* srs = stage + 25416;                // 8
  int*   sgi = (int*)(stage + 25424);        // 192
  float* sla = stage + 25616;                // 192

  float bvA[4], bvB[4];
#pragma unroll
  for (int ot = 0; ot < 4; ot++) {
    int o0 = oHalf * 128 + oBaseL + ot * 16 + lr;
    bvA[ot] = __ldg(bias + o0);
    bvB[ot] = __ldg(bias + o0 + 8);
  }
  // stage tile (bias-added) + per-warp stats
#pragma unroll
  for (int ot = 0; ot < 4; ot++) {
    int o0 = oBaseL + ot * 16 + lr;
    float s = 0.f, s2 = 0.f;
#pragma unroll
    for (int tt = 0; tt < 6; tt++) {
      int t = tBase + tt * 8 + lc * 2;
      float v0 = acc[ot][tt][0] + bvA[ot];
      float v1 = acc[ot][tt][1] + bvA[ot];
      float v2 = acc[ot][tt][2] + bvB[ot];
      float v3 = acc[ot][tt][3] + bvB[ot];
      stage[t * 132 + o0] = v0;
      stage[(t + 1) * 132 + o0] = v1;
      stage[t * 132 + o0 + 8] = v2;
      stage[(t + 1) * 132 + o0 + 8] = v3;
      s += v0 + v1 + v2 + v3;
      s2 = fmaf(v0, v0, s2); s2 = fmaf(v1, v1, s2);
      s2 = fmaf(v2, v2, s2); s2 = fmaf(v3, v3, s2);
    }
#pragma unroll
    for (int off = 16; off; off >>= 1) {
      s += __shfl_xor_sync(0xffffffffu, s, off);
      s2 += __shfl_xor_sync(0xffffffffu, s2, off);
    }
    if (lane == 0) {
      gsm[warp * 8 + ot * 2] = s;
      gsm[warp * 8 + ot * 2 + 1] = s2;
    }
  }
  __syncthreads();
  if (tid < 8) {
    int g = tid;
    float s = 0.f, s2 = 0.f;
#pragma unroll
    for (int wt = 0; wt < 4; wt++) {
      int w2 = (wt * 2 + (g >> 2)) * 8 + (g & 3) * 2;
      s += gsm[w2];
      s2 += gsm[w2 + 1];
    }
    float m = s * (1.0f / 3072.0f);
    float var = s2 * (1.0f / 3072.0f) - m * m;
    float rs = rsqrtf(var + 1e-5f);
    smu[g] = m;
    srs[g] = rs;
    g_mu[b * 16 + oHalf * 8 + g] = m;
    g_rsig[b * 16 + oHalf * 8 + g] = rs;
  }
  if (tid >= 64 && tid < 256) {
    int idx = tid - 64;
    sgi[idx] = gi[b * TT + idx];
    sla[idx] = lam[b * TT + idx];
  }
  __syncthreads();

  // fused interp: thread = (channel c = tid&127, t-half = tid>>7)
  {
    int c = tid & 127;
    int th = tid >> 7;
    float m = smu[c >> 4];
    float rs = srs[c >> 4];
    int gc = oHalf * 128 + c;
    float w = __ldg(gnw + gc), be = __ldg(gnb + gc);
    int chunk = gc >> 4, cl = gc & 15;
    __nv_bfloat16* xhp = oxh + (size_t)b * NCH0 * 196 * 16 + (size_t)chunk * 196 * 16 + cl;
    __nv_bfloat16* xlp = oxl + (size_t)b * NCH0 * 196 * 16 + (size_t)chunk * 196 * 16 + cl;
#pragma unroll 1
    for (int tp = th * 96; tp < th * 96 + 96; tp++) {
      int g = sgi[tp];
      float val = 0.f;
      if (g >= 0) {
        float lm = sla[tp];
        float a = stage[g * 132 + c];
        float e = stage[(g + 1) * 132 + c];
        float fa = fmaxf((a - m) * rs * w + be, 0.f);
        float fb = fmaxf((e - m) * rs * w + be, 0.f);
        val = (1.0f - lm) * fa + lm * fb;
      }
      __nv_bfloat16 h = __float2bfloat16(val);
      xhp[(size_t)(tp + 2) * 16] = h;
      xlp[(size_t)(tp + 2) * 16] = __float2bfloat16(val - __bfloat162float(h));
    }
  }
}

// ---------------- HMMA xg GEMM: CTA = (dir, b); 128g x 192t, K=256 ----------------
#define XA_ELEMS (2 * 128 * XSTR)
#define XB_ELEMS (2 * 192 * XSTR)
#define XG_SMEM_MAIN ((XA_ELEMS + XB_ELEMS) * 2)
#define XG_SMEM_STAGE (48 * 132 * 4)
#define XG_SMEM (XG_SMEM_MAIN > XG_SMEM_STAGE ? XG_SMEM_MAIN : XG_SMEM_STAGE)

__global__ __launch_bounds__(256) void xg_mma(
    const __nv_bfloat16* __restrict__ xh, const __nv_bfloat16* __restrict__ xl,
    const float* __restrict__ bif, const float* __restrict__ bhf,
    const float* __restrict__ bib, const float* __restrict__ bhb,
    float* __restrict__ xg) {
  extern __shared__ char xsm[];
  __nv_bfloat16* sA = (__nv_bfloat16*)xsm;            // [2][128][XSTR]
  __nv_bfloat16* sB = sA + XA_ELEMS;                  // [2][192][XSTR]
  float* stage = (float*)xsm;                         // [48][132], reused
  int dir = blockIdx.x, b = blockIdx.y;
  const float* bi = dir ? bib : bif;
  const float* bh = dir ? bhb : bhf;
  int tid = threadIdx.x;
  int warp = tid >> 5, lane = tid & 31;
  int warpO = warp & 1, warpT = warp >> 1;
  int oBaseL = warpO * 64, tBase = warpT * 48;
  int lr = lane >> 2, lc = lane & 3;

  unsigned sbA = (unsigned)__cvta_generic_to_shared(sA);
  unsigned sbB = (unsigned)__cvta_generic_to_shared(sB);
  unsigned rowA_off = ((oBaseL + (lane & 7) + ((lane >> 3) & 1) * 8) * XSTR +
                       ((lane >> 4) & 1) * 8) * 2;
  unsigned rowB_off = ((tBase + (lane & 7) + ((lane >> 4) & 1) * 8) * XSTR +
                       ((lane >> 3) & 1) * 8) * 2;

  float acc[4][6][4];
#pragma unroll
  for (int ot = 0; ot < 4; ot++)
#pragma unroll
    for (int tt = 0; tt < 6; tt++)
#pragma unroll
      for (int q = 0; q < 4; q++) acc[ot][tt][q] = 0.f;

  const __nv_bfloat16* xsrc[2] = {xh + (size_t)b * NCH0 * 196 * 16,
                                  xl + (size_t)b * NCH0 * 196 * 16};
  for (int chunk = 0; chunk < 16; chunk++) {
    for (int i = tid; i < 2048; i += 256) {
      int sp = i >> 10;
      int rem = i & 1023;
      int o = rem >> 3, cp = rem & 7;
      const __nv_bfloat16* wsrc = sp ? g_wxl : g_wxh;
      u32 v = *(const u32*)(wsrc + ((size_t)((dir * 16 + chunk) * 128 + o) * 16 + cp * 2));
      *(u32*)(sA + (sp * 128 + o) * XSTR + cp * 2) = v;
    }
    for (int i = tid; i < 3072; i += 256) {
      int sp = i >= 1536;
      int rem = sp ? i - 1536 : i;
      int row = rem >> 3, cp = rem & 7;
      u32 v = *(const u32*)(xsrc[sp] + ((size_t)(chunk * 196 + 2 + row) * 16 + cp * 2));
      *(u32*)(sB + (sp * 192 + row) * XSTR + cp * 2) = v;
    }
    __syncthreads();
#pragma unroll 1
    for (int sp = 0; sp < 3; sp++) {
      int aSel = (sp == 2) ? 1 : 0;
      int bSel = (sp == 1) ? 1 : 0;
      u32 bfr[6][2];
      unsigned baseB = sbB + (unsigned)(bSel * 192 * XSTR * 2) + rowB_off;
#pragma unroll
      for (int q = 0; q < 3; q++)
        ldsm4(&bfr[2 * q][0], baseB + (unsigned)(q * 16 * XSTR * 2));
      unsigned baseA = sbA + (unsigned)(aSel * 128 * XSTR * 2) + rowA_off;
#pragma unroll
      for (int ot = 0; ot < 4; ot++) {
        u32 af[4];
        ldsm4(af, baseA + (unsigned)(ot * 16 * XSTR * 2));
#pragma unroll
        for (int tt = 0; tt < 6; tt++) mma16816(acc[ot][tt], af, bfr[tt]);
      }
    }
    __syncthreads();
  }
  float* xgb = xg + (size_t)(dir * BB + b) * TT * 128;
  for (int q = 0; q < 4; q++) {
    __syncthreads();
    if (warpT == q) {
#pragma unroll
      for (int ot = 0; ot < 4; ot++) {
        int o0 = oBaseL + ot * 16 + lr;
#pragma unroll
        for (int tt = 0; tt < 6; tt++) {
          int tl = tt * 8 + lc * 2;
          stage[tl * 132 + o0] = acc[ot][tt][0];
          stage[(tl + 1) * 132 + o0] = acc[ot][tt][1];
          stage[tl * 132 + o0 + 8] = acc[ot][tt][2];
          stage[(tl + 1) * 132 + o0 + 8] = acc[ot][tt][3];
        }
      }
    }
    __syncthreads();
    for (int i = tid; i < 6144; i += 256) {
      int tl = i >> 7, g = i & 127;
      xgb[(size_t)(q * 48 + tl) * 128 + g] =
          stage[tl * 132 + g] + __ldg(bi + g) + __ldg(bh + g);
    }
  }
}

// ---------------- LSTM recurrence: warp per batch element ----------------
__device__ __forceinline__ float sigf(float x) { return 1.0f / (1.0f + expf(-x)); }

__global__ __launch_bounds__(256) void lstm_kernel(
    const float* __restrict__ xg, const float* __restrict__ whf,
    const float* __restrict__ whb, float* __restrict__ out) {
  __shared__ float ws[32 * 128];
  int dir = blockIdx.y;
  const float* wh = dir ? whb : whf;
  int tid = threadIdx.x;
  for (int idx = tid; idx < 4096; idx += 256) {
    int j = idx >> 7, r = idx & 127;
    ws[idx] = wh[r * 32 + j];
  }
  __syncthreads();
  int warp = tid >> 5, lane = tid & 31;
  int b = blockIdx.x * 8 + warp;
  const float* xgb = xg + (size_t)(dir * BB + b) * TT * 128;
  float h = 0.f, c = 0.f;
  for (int step = 0; step < TT; step++) {
    int t = dir ? (TT - 1 - step) : step;
    const float* p = xgb + (size_t)t * 128;
    float gi = p[lane], gf = p[32 + lane], gg = p[64 + lane], go = p[96 + lane];
#pragma unroll
    for (int j = 0; j < 32; j++) {
      float hj = __shfl_sync(0xffffffffu, h, j);
      const float* wr = ws + j * 128;
      gi = fmaf(wr[lane], hj, gi);
      gf = fmaf(wr[32 + lane], hj, gf);
      gg = fmaf(wr[64 + lane], hj, gg);
      go = fmaf(wr[96 + lane], hj, go);
    }
    c = sigf(gf) * c + sigf(gi) * tanhf(gg);
    h = sigf(go) * tanhf(c);
    if (dir == 0) {
      if ((t & 7) == 7) out[((size_t)b * 24 + (t >> 3)) * 64 + lane] = h;
    } else {
      if ((t & 7) == 0) out[((size_t)b * 24 + (t >> 3)) * 64 + 32 + lane] = h;
    }
  }
}

// ---------------- launch ----------------
extern "C" void kernel_launch(void* const* d_in, const int* in_sizes, int n_in,
                              void* d_out, int out_size) {
  (void)in_sizes; (void)n_in; (void)out_size;
  float *p_xg, *p_mu, *p_rsig, *p_lam;
  int* p_gi;
  __nv_bfloat16 *p_xh, *p_xl, *p_wh, *p_wl;
  cudaGetSymbolAddress((void**)&p_xg, g_xg);
  cudaGetSymbolAddress((void**)&p_mu, g_mu);
  cudaGetSymbolAddress((void**)&p_rsig, g_rsig);
  cudaGetSymbolAddress((void**)&p_gi, g_gi);
  cudaGetSymbolAddress((void**)&p_lam, g_lam);
  cudaGetSymbolAddress((void**)&p_xh, g_xh);
  cudaGetSymbolAddress((void**)&p_xl, g_xl);
  cudaGetSymbolAddress((void**)&p_wh, g_wh);
  cudaGetSymbolAddress((void**)&p_wl, g_wl);

  static int smem_set = 0;
  if (!smem_set) {
    cudaFuncSetAttribute(mma_conv, cudaFuncAttributeMaxDynamicSharedMemorySize, CONV_SMEM);
    cudaFuncSetAttribute(xg_mma, cudaFuncAttributeMaxDynamicSharedMemorySize, XG_SMEM);
    smem_set = 1;
  }

  const float* x0 = (const float*)d_in[0];

  // JAX threefry keys: rng = key(42); per layer i: fold_in -> split -> randint split
  KeyPack kp;
  for (int i = 0; i < 3; i++) {
    unsigned f0, f1;
    tf2x32(0u, 42u, 0u, (unsigned)i, f0, f1);
    unsigned k1a, k1b, k2a, k2b;
    tf2x32(f0, f1, 0u, 0u, k1a, k1b);
    tf2x32(f0, f1, 0u, 1u, k2a, k2b);
    unsigned ha, hb2, la, lb2;
    tf2x32(k2a, k2b, 0u, 0u, ha, hb2);
    tf2x32(k2a, k2b, 0u, 1u, la, lb2);
    kp.v[i * 6 + 0] = k1a; kp.v[i * 6 + 1] = k1b;
    kp.v[i * 6 + 2] = ha;  kp.v[i * 6 + 3] = hb2;
    kp.v[i * 6 + 4] = la;  kp.v[i * 6 + 5] = lb2;
  }

  // per-layer weight regions (chunks: 17, 16, 16)
  const int wofs[3] = {0, 17 * 5 * 256 * 16, 33 * 5 * 256 * 16};

  x0prep<<<dim3(BB, NCH0), 192>>>(x0);
  wprep_xg<<<32, 128>>>((const float*)d_in[13], (const float*)d_in[17]);
  interp_meta_all<<<dim3(2, 3), 256>>>(p_gi, p_lam, kp);
  for (int i = 0; i < 3; i++) {
    int Cin = (i == 0) ? 257 : 256;
    int NCH = (i == 0) ? 17 : 16;
    wprep<<<NCH * 5, 256>>>((const float*)d_in[1 + 4 * i], Cin, NCH,
                            p_wh + wofs[i], p_wl + wofs[i]);
  }
  for (int i = 0; i < 3; i++) {
    const float* cb = (const float*)d_in[2 + 4 * i];
    const float* gw = (const float*)d_in[3 + 4 * i];
    const float* gb = (const float*)d_in[4 + 4 * i];
    int NCH = (i == 0) ? 17 : 16;
    mma_conv<<<dim3(2, BB), 256, CONV_SMEM>>>(
        p_wh + wofs[i], p_wl + wofs[i], cb,
        p_gi + i * BB * TT, p_lam + i * BB * TT, gw, gb, p_xh, p_xl, NCH);
  }
  xg_mma<<<dim3(2, BB), 256, XG_SMEM>>>(p_xh, p_xl, (const float*)d_in[15],
                                        (const float*)d_in[16], (const float*)d_in[19],
                                        (const float*)d_in[20], p_xg);
  lstm_kernel<<<dim3(64, 2), 256>>>(p_xg, (const float*)d_in[14],
                                    (const float*)d_in[18], (float*)d_out);
}

// round 13
// speedup vs baseline: 5.4677x; 1.0148x over previous
#include <cuda_runtime.h>
#include <cuda_bf16.h>
#include <math.h>

#define BB 512
#define TT 192
#define CC 256
#define NCH0 17           // layer0 ci chunks of 16 (257 -> 272)
#define XSTR 24           // xg smem row stride (bf16): conflict-free
#define IMG ((size_t)BB * NCH0 * 196 * 16)

typedef unsigned int u32;

// ---------------- scratch (device globals; no allocation) ----------------
__device__ float g_xg[(size_t)2 * BB * TT * 128]; // lstm pre-gates [dir,B,T,128]
__device__ float g_mu[BB * 16];
__device__ float g_rsig[BB * 16];
__device__ int   g_gi[3 * BB * TT];
__device__ float g_lam[3 * BB * TT];
// DOUBLE-BUFFERED split-bf16 x images: [buf 2][b][chunk<17][row 0..195][ci16]
__device__ __nv_bfloat16 g_xh[2 * IMG];
__device__ __nv_bfloat16 g_xl[2 * IMG];
// split conv weights, all 3 layers: [layer-chunk 49][k 5][o 256][ci16]
__device__ __nv_bfloat16 g_wh[49 * 5 * 256 * 16];
__device__ __nv_bfloat16 g_wl[49 * 5 * 256 * 16];
// split xg weights: [dir 2][chunk 16][g 128][ci16]
__device__ __nv_bfloat16 g_wxh[2 * 16 * 128 * 16];
__device__ __nv_bfloat16 g_wxl[2 * 16 * 128 * 16];

// ---------------- threefry2x32 (JAX), host + device ----------------
__host__ __device__ __forceinline__ void tf2x32(unsigned k0, unsigned k1,
                                                unsigned x0, unsigned x1,
                                                unsigned& y0, unsigned& y1) {
  unsigned ks2 = k0 ^ k1 ^ 0x1BD11BDAu;
  x0 += k0; x1 += k1;
#define TFR(r) x0 += x1; x1 = (x1 << (r)) | (x1 >> (32 - (r))); x1 ^= x0;
  TFR(13) TFR(15) TFR(26) TFR(6)
  x0 += k1;  x1 += ks2 + 1u;
  TFR(17) TFR(29) TFR(16) TFR(24)
  x0 += ks2; x1 += k0 + 2u;
  TFR(13) TFR(15) TFR(26) TFR(6)
  x0 += k0;  x1 += k1 + 3u;
  TFR(17) TFR(29) TFR(16) TFR(24)
  x0 += k1;  x1 += ks2 + 4u;
  TFR(13) TFR(15) TFR(26) TFR(6)
  x0 += ks2; x1 += k0 + 5u;
#undef TFR
  y0 = x0; y1 = x1;
}

__device__ __forceinline__ unsigned tf_bits32(unsigned k0, unsigned k1, unsigned n) {
  unsigned y0, y1;
  tf2x32(k0, k1, 0u, n, y0, y1);
  return y0 ^ y1;
}

// ---------------- mma.sync + ldmatrix + cp.async ----------------
__device__ __forceinline__ void mma16816(float* c, const u32* a, const u32* b) {
  asm volatile(
      "mma.sync.aligned.m16n8k16.row.col.f32.bf16.bf16.f32 "
      "{%0,%1,%2,%3}, {%4,%5,%6,%7}, {%8,%9}, {%0,%1,%2,%3};"
      : "+f"(c[0]), "+f"(c[1]), "+f"(c[2]), "+f"(c[3])
      : "r"(a[0]), "r"(a[1]), "r"(a[2]), "r"(a[3]), "r"(b[0]), "r"(b[1]));
}

__device__ __forceinline__ void ldsm4(u32* r, unsigned addr) {
  asm volatile("ldmatrix.sync.aligned.m8n8.x4.shared.b16 {%0,%1,%2,%3}, [%4];"
               : "=r"(r[0]), "=r"(r[1]), "=r"(r[2]), "=r"(r[3]) : "r"(addr));
}

__device__ __forceinline__ void cpasync16(unsigned d, const void* g) {
  asm volatile("cp.async.cg.shared.global [%0], [%1], 16;" :: "r"(d), "l"(g));
}
#define CP_COMMIT() asm volatile("cp.async.commit_group;" ::: "memory")

// ---------------- conv weight prep: all 3 layers, one launch ----------------
__global__ __launch_bounds__(256) void wprep_all(const float* __restrict__ w0,
                                                 const float* __restrict__ w1,
                                                 const float* __restrict__ w2) {
  int blk = blockIdx.x;   // 0..244
  int layer, lblk;
  if (blk < 85) { layer = 0; lblk = blk; }
  else if (blk < 165) { layer = 1; lblk = blk - 85; }
  else { layer = 2; lblk = blk - 165; }
  const float* w = (layer == 0) ? w0 : ((layer == 1) ? w1 : w2);
  int Cin = (layer == 0) ? 257 : 256;
  int wof = (layer == 0) ? 0 : ((layer == 1) ? 17 * 5 * 256 * 16 : 33 * 5 * 256 * 16);
  int chunk = lblk / 5, k = lblk % 5;
  int o = threadIdx.x;
  size_t base = (size_t)wof + (size_t)((chunk * 5 + k) * 256 + o) * 16;
  for (int cl = 0; cl < 16; cl++) {
    int ci = chunk * 16 + cl;
    float v = (ci < Cin) ? w[((size_t)o * Cin + ci) * 5 + k] : 0.f;
    __nv_bfloat16 h = __float2bfloat16(v);
    g_wh[base + cl] = h;
    g_wl[base + cl] = __float2bfloat16(v - __bfloat162float(h));
  }
}

// ---------------- xg weight prep: [dir][chunk][g][ci] ----------------
__global__ __launch_bounds__(128) void wprep_xg(const float* __restrict__ wf,
                                                const float* __restrict__ wb) {
  int dir = blockIdx.x >> 4, chunk = blockIdx.x & 15;
  int g = threadIdx.x;
  const float* w = dir ? wb : wf;
  size_t base = (size_t)((dir * 16 + chunk) * 128 + g) * 16;
  for (int cl = 0; cl < 16; cl++) {
    float v = w[(size_t)g * CC + chunk * 16 + cl];
    __nv_bfloat16 h = __float2bfloat16(v);
    g_wxh[base + cl] = h;
    g_wxl[base + cl] = __float2bfloat16(v - __bfloat162float(h));
  }
}

// ---------------- x0 prep: transpose+split into buf0; zero pads in BOTH bufs ----------------
__global__ __launch_bounds__(192) void x0prep(const float* __restrict__ x) {
  __shared__ float s[16][193];
  int b = blockIdx.x, ch = blockIdx.y;
  int tid = threadIdx.x;
#pragma unroll
  for (int i = 0; i < 16; i++) {
    int ci = ch * 16 + i;
    s[i][tid] = (ci < 257) ? x[((size_t)b * 257 + ci) * TT + tid] : 0.f;
  }
  __syncthreads();
  size_t ob = (size_t)b * NCH0 * 196 * 16 + (size_t)ch * 196 * 16;
  for (int idx = tid; idx < 196 * 16; idx += 192) {
    int row = idx >> 4, cl = idx & 15;
    int t = row - 2;
    float v = (t >= 0 && t < TT) ? s[cl][t] : 0.f;
    __nv_bfloat16 h = __float2bfloat16(v);
    g_xh[ob + idx] = h;
    g_xl[ob + idx] = __float2bfloat16(v - __bfloat162float(h));
  }
  // zero pad rows (0,1,194,195) of buf1 for this (b, ch)
  if (tid < 64) {
    int rr = tid >> 4, cl = tid & 15;
    int r = (rr < 2) ? rr : (192 + rr);
    size_t xi = IMG + ob + (size_t)r * 16 + cl;
    g_xh[xi] = __float2bfloat16(0.f);
    g_xl[xi] = __float2bfloat16(0.f);
  }
}

// ---------------- interp_lnr metadata: all 3 layers in one launch ----------------
struct KeyPack { unsigned v[18]; };

__global__ void interp_meta_all(int* __restrict__ gi, float* __restrict__ lam,
                                KeyPack kp) {
  int layer = blockIdx.y;
  int b = blockIdx.x * blockDim.x + threadIdx.x;
  if (b >= BB) return;
  const unsigned* K = kp.v + layer * 6;
  int base = layer * BB * TT + b * TT;
  for (int t = 0; t < TT; t++) gi[base + t] = -1;
  int off = 0, pos = 0;
  for (int s = 0; s < 7; s++) {
    unsigned n = (unsigned)(b * 7 + s);
    unsigned ub = tf_bits32(K[0], K[1], n);
    float f = __uint_as_float((ub >> 9) | 0x3f800000u) - 1.0f;
    float scale = f + 0.5f;
    unsigned hb = tf_bits32(K[2], K[3], n);
    unsigned lb = tf_bits32(K[4], K[5], n);
    unsigned offt = ((hb % 13u) * 9u + lb % 13u) % 13u;
    int len = 19 + (int)offt;
    float lenm1 = (float)(len - 1);
    for (int l = 0; l < 64; l++) {
      float idx = __fdiv_rn((float)l, scale);
      float fl = floorf(idx);
      float lm = idx - fl;
      if (fl < lenm1) {
        int io = (int)fl + off;
        if (io < TT - 1) {
          if (pos < TT) { gi[base + pos] = io; lam[base + pos] = lm; }
          pos++;
        }
      }
    }
    off += len;
  }
}

// ---------------- HMMA conv: 64-o CTAs, 128 threads, 3 CTA/SM, ping-pong I/O ----------------
#define SA_BYTES (10 * 64 * 32)
#define SB_BYTES (2 * 196 * 32)
#define STAGE_BYTES (SA_BYTES + SB_BYTES)
#define CONV_SMEM (STAGE_BYTES * 2)

__device__ __forceinline__ void conv_fill(int chunk, unsigned sstage, int oQr,
                                          const __nv_bfloat16* wh,
                                          const __nv_bfloat16* wl,
                                          const __nv_bfloat16* xbh,
                                          const __nv_bfloat16* xbl, int tid) {
  // A: 10 tiles (k*2+sp) x 64 o x 16 ci = 1280 16B-chunks, XOR-swizzled
  for (int i = tid; i < 1280; i += 128) {
    int ksp = i >> 7;
    int rem = i & 127;
    int o = rem >> 1, half = rem & 1;
    int k = ksp >> 1, sp = ksp & 1;
    const __nv_bfloat16* wsrc = sp ? wl : wh;
    const void* g = wsrc + ((size_t)((chunk * 5 + k) * 256 + oQr * 64 + o) * 16 + half * 8);
    unsigned d = sstage + (unsigned)((ksp * 64 + o) * 32 + ((half ^ ((o >> 2) & 1)) << 4));
    cpasync16(d, g);
  }
  // B: 2 splits x 196 rows x 16 = 784 16B-chunks
  for (int i = tid; i < 784; i += 128) {
    int sp = i >= 392;
    int rem = sp ? i - 392 : i;
    int row = rem >> 1, half = rem & 1;
    const __nv_bfloat16* xs = sp ? xbl : xbh;
    const void* g = xs + ((size_t)(chunk * 196 + row) * 16 + half * 8);
    int rowg = sp * 196 + row;
    unsigned d = sstage + (unsigned)(SA_BYTES + rowg * 32 + ((half ^ ((rowg >> 2) & 1)) << 4));
    cpasync16(d, g);
  }
}

__global__ __launch_bounds__(128, 3) void mma_conv(
    const __nv_bfloat16* __restrict__ wh, const __nv_bfloat16* __restrict__ wl,
    const float* __restrict__ bias,
    const int* __restrict__ gi, const float* __restrict__ lam,
    const float* __restrict__ gnw, const float* __restrict__ gnb,
    const __nv_bfloat16* __restrict__ ixh, const __nv_bfloat16* __restrict__ ixl,
    __nv_bfloat16* __restrict__ oxh, __nv_bfloat16* __restrict__ oxl,
    int NCH) {
  extern __shared__ __nv_bfloat16 sm[];
  int oQr = blockIdx.x, b = blockIdx.y;
  int tid = threadIdx.x;
  int warp = tid >> 5, lane = tid & 31;
  int tBase = warp * 48;
  int lr = lane >> 2, lc = lane & 3;

  unsigned sb0 = (unsigned)__cvta_generic_to_shared(sm);
  int lane_rA = (lane & 7) + ((lane >> 3) & 1) * 8;
  unsigned rowA_off = (unsigned)(lane_rA * 32 +
                                 ((((lane >> 4) & 1) ^ ((lane_rA >> 2) & 1)) << 4));
  int tbl = tBase + (lane & 7) + ((lane >> 4) & 1) * 8;
  unsigned hB16 = (unsigned)(((lane >> 3) & 1) << 4);

  float acc[4][6][4];
#pragma unroll
  for (int ot = 0; ot < 4; ot++)
#pragma unroll
    for (int tt = 0; tt < 6; tt++)
#pragma unroll
      for (int q = 0; q < 4; q++) acc[ot][tt][q] = 0.f;

  const __nv_bfloat16* xbh = ixh + (size_t)b * NCH0 * 196 * 16;
  const __nv_bfloat16* xbl = ixl + (size_t)b * NCH0 * 196 * 16;

  conv_fill(0, sb0, oQr, wh, wl, xbh, xbl, tid);
  CP_COMMIT();

  for (int it = 0; it < NCH; it++) {
    int s = it & 1;
    if (it + 1 < NCH) {
      conv_fill(it + 1, sb0 + (unsigned)((s ^ 1) * STAGE_BYTES), oQr, wh, wl, xbh, xbl, tid);
      CP_COMMIT();
      asm volatile("cp.async.wait_group 1;" ::: "memory");
    } else {
      asm volatile("cp.async.wait_group 0;" ::: "memory");
    }
    __syncthreads();
    unsigned sbA = sb0 + (unsigned)(s * STAGE_BYTES);
    unsigned sbB = sbA + (unsigned)SA_BYTES;
#pragma unroll 1
    for (int sp = 0; sp < 3; sp++) {
      int aSel = (sp == 2) ? 1 : 0;   // hh, hl, lh
      int bSel = (sp == 1) ? 1 : 0;
#pragma unroll
      for (int k = 0; k < 5; k++) {
        int row0 = bSel * 196 + tbl + k;
        unsigned baseB = sbB + (unsigned)(row0 * 32) +
                         (hB16 ^ (unsigned)((((unsigned)row0 >> 2) & 1) << 4));
        u32 bfr[6][2];
#pragma unroll
        for (int q = 0; q < 3; q++)
          ldsm4(&bfr[2 * q][0], baseB + (unsigned)(q * 512));
        unsigned baseA = sbA + (unsigned)((k * 2 + aSel) * 64 * 32) + rowA_off;
#pragma unroll
        for (int ot = 0; ot < 4; ot++) {
          u32 af[4];
          ldsm4(af, baseA + (unsigned)(ot * 16 * 32));
#pragma unroll
          for (int tt = 0; tt < 6; tt++) mma16816(acc[ot][tt], af, bfr[tt]);
        }
      }
    }
    __syncthreads();
  }

  // ---- epilogue: full-tile smem stage [192][68] + GN stats + fused interp ----
  float* stage = (float*)sm;                 // [192][68]
  float* gsm = stage + 13056;                // 32
  float* smu = stage + 13088;                // 4
  float* srs = stage + 13092;                // 4
  int*   sgi = (int*)(stage + 13096);        // 192
  float* sla = stage + 13288;                // 192

  float bvA[4], bvB[4];
#pragma unroll
  for (int ot = 0; ot < 4; ot++) {
    int o0 = oQr * 64 + ot * 16 + lr;
    bvA[ot] = __ldg(bias + o0);
    bvB[ot] = __ldg(bias + o0 + 8);
  }
#pragma unroll
  for (int ot = 0; ot < 4; ot++) {
    int o0 = ot * 16 + lr;
    float s = 0.f, s2 = 0.f;
#pragma unroll
    for (int tt = 0; tt < 6; tt++) {
      int t = tBase + tt * 8 + lc * 2;
      float v0 = acc[ot][tt][0] + bvA[ot];
      float v1 = acc[ot][tt][1] + bvA[ot];
      float v2 = acc[ot][tt][2] + bvB[ot];
      float v3 = acc[ot][tt][3] + bvB[ot];
      stage[t * 68 + o0] = v0;
      stage[(t + 1) * 68 + o0] = v1;
      stage[t * 68 + o0 + 8] = v2;
      stage[(t + 1) * 68 + o0 + 8] = v3;
      s += v0 + v1 + v2 + v3;
      s2 = fmaf(v0, v0, s2); s2 = fmaf(v1, v1, s2);
      s2 = fmaf(v2, v2, s2); s2 = fmaf(v3, v3, s2);
    }
#pragma unroll
    for (int off = 16; off; off >>= 1) {
      s += __shfl_xor_sync(0xffffffffu, s, off);
      s2 += __shfl_xor_sync(0xffffffffu, s2, off);
    }
    if (lane == 0) {
      gsm[warp * 8 + ot * 2] = s;
      gsm[warp * 8 + ot * 2 + 1] = s2;
    }
  }
  __syncthreads();
  if (tid < 4) {
    int g = tid;
    float s = 0.f, s2 = 0.f;
#pragma unroll
    for (int wt = 0; wt < 4; wt++) {
      s += gsm[wt * 8 + g * 2];
      s2 += gsm[wt * 8 + g * 2 + 1];
    }
    float m = s * (1.0f / 3072.0f);
    float var = s2 * (1.0f / 3072.0f) - m * m;
    float rs = rsqrtf(var + 1e-5f);
    smu[g] = m;
    srs[g] = rs;
    g_mu[b * 16 + oQr * 4 + g] = m;
    g_rsig[b * 16 + oQr * 4 + g] = rs;
  }
  for (int i = tid; i < 192; i += 128) {
    sgi[i] = gi[b * TT + i];
    sla[i] = lam[b * TT + i];
  }
  __syncthreads();

  // fused interp: thread = (channel c = tid&63, t-half = tid>>6)
  {
    int c = tid & 63;
    int th = tid >> 6;
    float m = smu[c >> 4];
    float rs = srs[c >> 4];
    int gc = oQr * 64 + c;
    float w = __ldg(gnw + gc), be = __ldg(gnb + gc);
    int chunk = gc >> 4, cl = gc & 15;
    __nv_bfloat16* xhp = oxh + (size_t)b * NCH0 * 196 * 16 + (size_t)chunk * 196 * 16 + cl;
    __nv_bfloat16* xlp = oxl + (size_t)b * NCH0 * 196 * 16 + (size_t)chunk * 196 * 16 + cl;
#pragma unroll 1
    for (int tp = th * 96; tp < th * 96 + 96; tp++) {
      int g = sgi[tp];
      float val = 0.f;
      if (g >= 0) {
        float lm = sla[tp];
        float a = stage[g * 68 + c];
        float e = stage[(g + 1) * 68 + c];
        float fa = fmaxf((a - m) * rs * w + be, 0.f);
        float fb = fmaxf((e - m) * rs * w + be, 0.f);
        val = (1.0f - lm) * fa + lm * fb;
      }
      __nv_bfloat16 h = __float2bfloat16(val);
      xhp[(size_t)(tp + 2) * 16] = h;
      xlp[(size_t)(tp + 2) * 16] = __float2bfloat16(val - __bfloat162float(h));
    }
  }
}

// ---------------- HMMA xg GEMM: CTA = (dir, b); 128g x 192t, K=256 ----------------
#define XA_ELEMS (2 * 128 * XSTR)
#define XB_ELEMS (2 * 192 * XSTR)
#define XG_SMEM_MAIN ((XA_ELEMS + XB_ELEMS) * 2)
#define XG_SMEM_STAGE (48 * 132 * 4)
#define XG_SMEM (XG_SMEM_MAIN > XG_SMEM_STAGE ? XG_SMEM_MAIN : XG_SMEM_STAGE)

__global__ __launch_bounds__(256) void xg_mma(
    const __nv_bfloat16* __restrict__ xh, const __nv_bfloat16* __restrict__ xl,
    const float* __restrict__ bif, const float* __restrict__ bhf,
    const float* __restrict__ bib, const float* __restrict__ bhb,
    float* __restrict__ xg) {
  extern __shared__ char xsm[];
  __nv_bfloat16* sA = (__nv_bfloat16*)xsm;            // [2][128][XSTR]
  __nv_bfloat16* sB = sA + XA_ELEMS;                  // [2][192][XSTR]
  float* stage = (float*)xsm;                         // [48][132], reused
  int dir = blockIdx.x, b = blockIdx.y;
  const float* bi = dir ? bib : bif;
  const float* bh = dir ? bhb : bhf;
  int tid = threadIdx.x;
  int warp = tid >> 5, lane = tid & 31;
  int warpO = warp & 1, warpT = warp >> 1;
  int oBaseL = warpO * 64, tBase = warpT * 48;
  int lr = lane >> 2, lc = lane & 3;

  unsigned sbA = (unsigned)__cvta_generic_to_shared(sA);
  unsigned sbB = (unsigned)__cvta_generic_to_shared(sB);
  unsigned rowA_off = ((oBaseL + (lane & 7) + ((lane >> 3) & 1) * 8) * XSTR +
                       ((lane >> 4) & 1) * 8) * 2;
  unsigned rowB_off = ((tBase + (lane & 7) + ((lane >> 4) & 1) * 8) * XSTR +
                       ((lane >> 3) & 1) * 8) * 2;

  float acc[4][6][4];
#pragma unroll
  for (int ot = 0; ot < 4; ot++)
#pragma unroll
    for (int tt = 0; tt < 6; tt++)
#pragma unroll
      for (int q = 0; q < 4; q++) acc[ot][tt][q] = 0.f;

  const __nv_bfloat16* xsrc[2] = {xh + (size_t)b * NCH0 * 196 * 16,
                                  xl + (size_t)b * NCH0 * 196 * 16};
  for (int chunk = 0; chunk < 16; chunk++) {
    for (int i = tid; i < 2048; i += 256) {
      int sp = i >> 10;
      int rem = i & 1023;
      int o = rem >> 3, cp = rem & 7;
      const __nv_bfloat16* wsrc = sp ? g_wxl : g_wxh;
      u32 v = *(const u32*)(wsrc + ((size_t)((dir * 16 + chunk) * 128 + o) * 16 + cp * 2));
      *(u32*)(sA + (sp * 128 + o) * XSTR + cp * 2) = v;
    }
    for (int i = tid; i < 3072; i += 256) {
      int sp = i >= 1536;
      int rem = sp ? i - 1536 : i;
      int row = rem >> 3, cp = rem & 7;
      u32 v = *(const u32*)(xsrc[sp] + ((size_t)(chunk * 196 + 2 + row) * 16 + cp * 2));
      *(u32*)(sB + (sp * 192 + row) * XSTR + cp * 2) = v;
    }
    __syncthreads();
#pragma unroll 1
    for (int sp = 0; sp < 3; sp++) {
      int aSel = (sp == 2) ? 1 : 0;
      int bSel = (sp == 1) ? 1 : 0;
      u32 bfr[6][2];
      unsigned baseB = sbB + (unsigned)(bSel * 192 * XSTR * 2) + rowB_off;
#pragma unroll
      for (int q = 0; q < 3; q++)
        ldsm4(&bfr[2 * q][0], baseB + (unsigned)(q * 16 * XSTR * 2));
      unsigned baseA = sbA + (unsigned)(aSel * 128 * XSTR * 2) + rowA_off;
#pragma unroll
      for (int ot = 0; ot < 4; ot++) {
        u32 af[4];
        ldsm4(af, baseA + (unsigned)(ot * 16 * XSTR * 2));
#pragma unroll
        for (int tt = 0; tt < 6; tt++) mma16816(acc[ot][tt], af, bfr[tt]);
      }
    }
    __syncthreads();
  }
  float* xgb = xg + (size_t)(dir * BB + b) * TT * 128;
  for (int q = 0; q < 4; q++) {
    __syncthreads();
    if (warpT == q) {
#pragma unroll
      for (int ot = 0; ot < 4; ot++) {
        int o0 = oBaseL + ot * 16 + lr;
#pragma unroll
        for (int tt = 0; tt < 6; tt++) {
          int tl = tt * 8 + lc * 2;
          stage[tl * 132 + o0] = acc[ot][tt][0];
          stage[(tl + 1) * 132 + o0] = acc[ot][tt][1];
          stage[tl * 132 + o0 + 8] = acc[ot][tt][2];
          stage[(tl + 1) * 132 + o0 + 8] = acc[ot][tt][3];
        }
      }
    }
    __syncthreads();
    for (int i = tid; i < 6144; i += 256) {
      int tl = i >> 7, g = i & 127;
      xgb[(size_t)(q * 48 + tl) * 128 + g] =
          stage[tl * 132 + g] + __ldg(bi + g) + __ldg(bh + g);
    }
  }
}

// ---------------- LSTM recurrence: warp per batch element ----------------
__device__ __forceinline__ float sigf(float x) { return 1.0f / (1.0f + expf(-x)); }

__global__ __launch_bounds__(256) void lstm_kernel(
    const float* __restrict__ xg, const float* __restrict__ whf,
    const float* __restrict__ whb, float* __restrict__ out) {
  __shared__ float ws[32 * 128];
  int dir = blockIdx.y;
  const float* wh = dir ? whb : whf;
  int tid = threadIdx.x;
  for (int idx = tid; idx < 4096; idx += 256) {
    int j = idx >> 7, r = idx & 127;
    ws[idx] = wh[r * 32 + j];
  }
  __syncthreads();
  int warp = tid >> 5, lane = tid & 31;
  int b = blockIdx.x * 8 + warp;
  const float* xgb = xg + (size_t)(dir * BB + b) * TT * 128;
  float h = 0.f, c = 0.f;
  for (int step = 0; step < TT; step++) {
    int t = dir ? (TT - 1 - step) : step;
    const float* p = xgb + (size_t)t * 128;
    float gi = p[lane], gf = p[32 + lane], gg = p[64 + lane], go = p[96 + lane];
#pragma unroll
    for (int j = 0; j < 32; j++) {
      float hj = __shfl_sync(0xffffffffu, h, j);
      const float* wr = ws + j * 128;
      gi = fmaf(wr[lane], hj, gi);
      gf = fmaf(wr[32 + lane], hj, gf);
      gg = fmaf(wr[64 + lane], hj, gg);
      go = fmaf(wr[96 + lane], hj, go);
    }
    c = sigf(gf) * c + sigf(gi) * tanhf(gg);
    h = sigf(go) * tanhf(c);
    if (dir == 0) {
      if ((t & 7) == 7) out[((size_t)b * 24 + (t >> 3)) * 64 + lane] = h;
    } else {
      if ((t & 7) == 0) out[((size_t)b * 24 + (t >> 3)) * 64 + 32 + lane] = h;
    }
  }
}

// ---------------- launch ----------------
extern "C" void kernel_launch(void* const* d_in, const int* in_sizes, int n_in,
                              void* d_out, int out_size) {
  (void)in_sizes; (void)n_in; (void)out_size;
  float *p_xg, *p_lam;
  int* p_gi;
  __nv_bfloat16 *p_xh, *p_xl, *p_wh, *p_wl;
  cudaGetSymbolAddress((void**)&p_xg, g_xg);
  cudaGetSymbolAddress((void**)&p_gi, g_gi);
  cudaGetSymbolAddress((void**)&p_lam, g_lam);
  cudaGetSymbolAddress((void**)&p_xh, g_xh);
  cudaGetSymbolAddress((void**)&p_xl, g_xl);
  cudaGetSymbolAddress((void**)&p_wh, g_wh);
  cudaGetSymbolAddress((void**)&p_wl, g_wl);

  static int smem_set = 0;
  if (!smem_set) {
    cudaFuncSetAttribute(mma_conv, cudaFuncAttributeMaxDynamicSharedMemorySize, CONV_SMEM);
    cudaFuncSetAttribute(xg_mma, cudaFuncAttributeMaxDynamicSharedMemorySize, XG_SMEM);
    smem_set = 1;
  }

  const float* x0 = (const float*)d_in[0];

  // JAX threefry keys: rng = key(42); per layer i: fold_in -> split -> randint split
  KeyPack kp;
  for (int i = 0; i < 3; i++) {
    unsigned f0, f1;
    tf2x32(0u, 42u, 0u, (unsigned)i, f0, f1);
    unsigned k1a, k1b, k2a, k2b;
    tf2x32(f0, f1, 0u, 0u, k1a, k1b);
    tf2x32(f0, f1, 0u, 1u, k2a, k2b);
    unsigned ha, hb2, la, lb2;
    tf2x32(k2a, k2b, 0u, 0u, ha, hb2);
    tf2x32(k2a, k2b, 0u, 1u, la, lb2);
    kp.v[i * 6 + 0] = k1a; kp.v[i * 6 + 1] = k1b;
    kp.v[i * 6 + 2] = ha;  kp.v[i * 6 + 3] = hb2;
    kp.v[i * 6 + 4] = la;  kp.v[i * 6 + 5] = lb2;
  }

  const int wofs[3] = {0, 17 * 5 * 256 * 16, 33 * 5 * 256 * 16};
  // ping-pong: layer0 buf0->buf1, layer1 buf1->buf0, layer2 buf0->buf1
  const size_t inof[3] = {0, IMG, 0};
  const size_t outof[3] = {IMG, 0, IMG};

  x0prep<<<dim3(BB, NCH0), 192>>>(x0);
  wprep_all<<<245, 256>>>((const float*)d_in[1], (const float*)d_in[5],
                          (const float*)d_in[9]);
  wprep_xg<<<32, 128>>>((const float*)d_in[13], (const float*)d_in[17]);
  interp_meta_all<<<dim3(2, 3), 256>>>(p_gi, p_lam, kp);
  for (int i = 0; i < 3; i++) {
    const float* cb = (const float*)d_in[2 + 4 * i];
    const float* gw = (const float*)d_in[3 + 4 * i];
    const float* gb = (const float*)d_in[4 + 4 * i];
    int NCH = (i == 0) ? 17 : 16;
    mma_conv<<<dim3(4, BB), 128, CONV_SMEM>>>(
        p_wh + wofs[i], p_wl + wofs[i], cb,
        p_gi + i * BB * TT, p_lam + i * BB * TT, gw, gb,
        p_xh + inof[i], p_xl + inof[i], p_xh + outof[i], p_xl + outof[i], NCH);
  }
  xg_mma<<<dim3(2, BB), 256, XG_SMEM>>>(p_xh + IMG, p_xl + IMG,
                                        (const float*)d_in[15], (const float*)d_in[16],
                                        (const float*)d_in[19], (const float*)d_in[20],
                                        p_xg);
  lstm_kernel<<<dim3(64, 2), 256>>>(p_xg, (const float*)d_in[14],
                                    (const float*)d_in[18], (float*)d_out);
}

// round 14
// speedup vs baseline: 5.6426x; 1.0320x over previous
#include <cuda_runtime.h>
#include <cuda_bf16.h>
#include <math.h>

#define BB 512
#define TT 192
#define CC 256
#define NCH0 17           // layer0 ci chunks of 16 (257 -> 272)
#define XSTR 24           // xg smem row stride (bf16): conflict-free
#define IMG ((size_t)BB * NCH0 * 196 * 16)

typedef unsigned int u32;

// ---------------- scratch (device globals; no allocation) ----------------
__device__ float g_xg[(size_t)2 * BB * TT * 128]; // lstm pre-gates [dir,B,T,128]
__device__ float g_mu[BB * 16];
__device__ float g_rsig[BB * 16];
__device__ int   g_gi[3 * BB * TT];
__device__ float g_lam[3 * BB * TT];
// DOUBLE-BUFFERED split-bf16 x images: [buf 2][b][chunk<17][row 0..195][ci16]
__device__ __nv_bfloat16 g_xh[2 * IMG];
__device__ __nv_bfloat16 g_xl[2 * IMG];
// split conv weights, all 3 layers: [layer-chunk 49][k 5][o 256][ci16]
__device__ __nv_bfloat16 g_wh[49 * 5 * 256 * 16];
__device__ __nv_bfloat16 g_wl[49 * 5 * 256 * 16];
// split xg weights: [dir 2][chunk 16][g 128][ci16]
__device__ __nv_bfloat16 g_wxh[2 * 16 * 128 * 16];
__device__ __nv_bfloat16 g_wxl[2 * 16 * 128 * 16];

// ---------------- threefry2x32 (JAX), host + device ----------------
__host__ __device__ __forceinline__ void tf2x32(unsigned k0, unsigned k1,
                                                unsigned x0, unsigned x1,
                                                unsigned& y0, unsigned& y1) {
  unsigned ks2 = k0 ^ k1 ^ 0x1BD11BDAu;
  x0 += k0; x1 += k1;
#define TFR(r) x0 += x1; x1 = (x1 << (r)) | (x1 >> (32 - (r))); x1 ^= x0;
  TFR(13) TFR(15) TFR(26) TFR(6)
  x0 += k1;  x1 += ks2 + 1u;
  TFR(17) TFR(29) TFR(16) TFR(24)
  x0 += ks2; x1 += k0 + 2u;
  TFR(13) TFR(15) TFR(26) TFR(6)
  x0 += k0;  x1 += k1 + 3u;
  TFR(17) TFR(29) TFR(16) TFR(24)
  x0 += k1;  x1 += ks2 + 4u;
  TFR(13) TFR(15) TFR(26) TFR(6)
  x0 += ks2; x1 += k0 + 5u;
#undef TFR
  y0 = x0; y1 = x1;
}

__device__ __forceinline__ unsigned tf_bits32(unsigned k0, unsigned k1, unsigned n) {
  unsigned y0, y1;
  tf2x32(k0, k1, 0u, n, y0, y1);
  return y0 ^ y1;
}

// ---------------- mma.sync + ldmatrix + cp.async ----------------
__device__ __forceinline__ void mma16816(float* c, const u32* a, const u32* b) {
  asm volatile(
      "mma.sync.aligned.m16n8k16.row.col.f32.bf16.bf16.f32 "
      "{%0,%1,%2,%3}, {%4,%5,%6,%7}, {%8,%9}, {%0,%1,%2,%3};"
      : "+f"(c[0]), "+f"(c[1]), "+f"(c[2]), "+f"(c[3])
      : "r"(a[0]), "r"(a[1]), "r"(a[2]), "r"(a[3]), "r"(b[0]), "r"(b[1]));
}

__device__ __forceinline__ void ldsm4(u32* r, unsigned addr) {
  asm volatile("ldmatrix.sync.aligned.m8n8.x4.shared.b16 {%0,%1,%2,%3}, [%4];"
               : "=r"(r[0]), "=r"(r[1]), "=r"(r[2]), "=r"(r[3]) : "r"(addr));
}

__device__ __forceinline__ void cpasync16(unsigned d, const void* g) {
  asm volatile("cp.async.cg.shared.global [%0], [%1], 16;" :: "r"(d), "l"(g));
}
#define CP_COMMIT() asm volatile("cp.async.commit_group;" ::: "memory")

// ---------------- conv weight prep: all 3 layers, one launch ----------------
__global__ __launch_bounds__(256) void wprep_all(const float* __restrict__ w0,
                                                 const float* __restrict__ w1,
                                                 const float* __restrict__ w2) {
  int blk = blockIdx.x;   // 0..244
  int layer, lblk;
  if (blk < 85) { layer = 0; lblk = blk; }
  else if (blk < 165) { layer = 1; lblk = blk - 85; }
  else { layer = 2; lblk = blk - 165; }
  const float* w = (layer == 0) ? w0 : ((layer == 1) ? w1 : w2);
  int Cin = (layer == 0) ? 257 : 256;
  int wof = (layer == 0) ? 0 : ((layer == 1) ? 17 * 5 * 256 * 16 : 33 * 5 * 256 * 16);
  int chunk = lblk / 5, k = lblk % 5;
  int o = threadIdx.x;
  size_t base = (size_t)wof + (size_t)((chunk * 5 + k) * 256 + o) * 16;
  for (int cl = 0; cl < 16; cl++) {
    int ci = chunk * 16 + cl;
    float v = (ci < Cin) ? w[((size_t)o * Cin + ci) * 5 + k] : 0.f;
    __nv_bfloat16 h = __float2bfloat16(v);
    g_wh[base + cl] = h;
    g_wl[base + cl] = __float2bfloat16(v - __bfloat162float(h));
  }
}

// ---------------- xg weight prep: [dir][chunk][g][ci] ----------------
__global__ __launch_bounds__(128) void wprep_xg(const float* __restrict__ wf,
                                                const float* __restrict__ wb) {
  int dir = blockIdx.x >> 4, chunk = blockIdx.x & 15;
  int g = threadIdx.x;
  const float* w = dir ? wb : wf;
  size_t base = (size_t)((dir * 16 + chunk) * 128 + g) * 16;
  for (int cl = 0; cl < 16; cl++) {
    float v = w[(size_t)g * CC + chunk * 16 + cl];
    __nv_bfloat16 h = __float2bfloat16(v);
    g_wxh[base + cl] = h;
    g_wxl[base + cl] = __float2bfloat16(v - __bfloat162float(h));
  }
}

// ---------------- x0 prep: transpose+split into buf0; zero pads in BOTH bufs ----------------
__global__ __launch_bounds__(192) void x0prep(const float* __restrict__ x) {
  __shared__ float s[16][193];
  int b = blockIdx.x, ch = blockIdx.y;
  int tid = threadIdx.x;
#pragma unroll
  for (int i = 0; i < 16; i++) {
    int ci = ch * 16 + i;
    s[i][tid] = (ci < 257) ? x[((size_t)b * 257 + ci) * TT + tid] : 0.f;
  }
  __syncthreads();
  size_t ob = (size_t)b * NCH0 * 196 * 16 + (size_t)ch * 196 * 16;
  for (int idx = tid; idx < 196 * 16; idx += 192) {
    int row = idx >> 4, cl = idx & 15;
    int t = row - 2;
    float v = (t >= 0 && t < TT) ? s[cl][t] : 0.f;
    __nv_bfloat16 h = __float2bfloat16(v);
    g_xh[ob + idx] = h;
    g_xl[ob + idx] = __float2bfloat16(v - __bfloat162float(h));
  }
  // zero pad rows (0,1,194,195) of buf1 for this (b, ch)
  if (tid < 64) {
    int rr = tid >> 4, cl = tid & 15;
    int r = (rr < 2) ? rr : (192 + rr);
    size_t xi = IMG + ob + (size_t)r * 16 + cl;
    g_xh[xi] = __float2bfloat16(0.f);
    g_xl[xi] = __float2bfloat16(0.f);
  }
}

// ---------------- interp_lnr metadata: all 3 layers; 32-thread blocks over 48 SMs ----------------
struct KeyPack { unsigned v[18]; };

__global__ __launch_bounds__(32) void interp_meta_all(int* __restrict__ gi,
                                                      float* __restrict__ lam,
                                                      KeyPack kp) {
  int layer = blockIdx.y;
  int b = blockIdx.x * 32 + threadIdx.x;
  if (b >= BB) return;
  const unsigned* K = kp.v + layer * 6;
  int base = layer * BB * TT + b * TT;
  for (int t = 0; t < TT; t++) gi[base + t] = -1;
  int off = 0, pos = 0;
  for (int s = 0; s < 7; s++) {
    unsigned n = (unsigned)(b * 7 + s);
    unsigned ub = tf_bits32(K[0], K[1], n);
    float f = __uint_as_float((ub >> 9) | 0x3f800000u) - 1.0f;
    float scale = f + 0.5f;
    unsigned hb = tf_bits32(K[2], K[3], n);
    unsigned lb = tf_bits32(K[4], K[5], n);
    unsigned offt = ((hb % 13u) * 9u + lb % 13u) % 13u;
    int len = 19 + (int)offt;
    float lenm1 = (float)(len - 1);
    for (int l = 0; l < 64; l++) {
      float idx = __fdiv_rn((float)l, scale);
      float fl = floorf(idx);
      float lm = idx - fl;
      if (fl < lenm1) {
        int io = (int)fl + off;
        if (io < TT - 1) {
          if (pos < TT) { gi[base + pos] = io; lam[base + pos] = lm; }
          pos++;
        }
      }
    }
    off += len;
  }
}

// ---------------- HMMA conv: 64-o CTAs, 128 threads, 3 CTA/SM, ping-pong I/O ----------------
#define SA_BYTES (10 * 64 * 32)
#define SB_BYTES (2 * 196 * 32)
#define STAGE_BYTES (SA_BYTES + SB_BYTES)
#define CONV_SMEM (STAGE_BYTES * 2)

__device__ __forceinline__ void conv_fill(int chunk, unsigned sstage, int oQr,
                                          const __nv_bfloat16* wh,
                                          const __nv_bfloat16* wl,
                                          const __nv_bfloat16* xbh,
                                          const __nv_bfloat16* xbl, int tid) {
  // A: 10 tiles (k*2+sp) x 64 o x 16 ci = 1280 16B-chunks, XOR-swizzled
  for (int i = tid; i < 1280; i += 128) {
    int ksp = i >> 7;
    int rem = i & 127;
    int o = rem >> 1, half = rem & 1;
    int k = ksp >> 1, sp = ksp & 1;
    const __nv_bfloat16* wsrc = sp ? wl : wh;
    const void* g = wsrc + ((size_t)((chunk * 5 + k) * 256 + oQr * 64 + o) * 16 + half * 8);
    unsigned d = sstage + (unsigned)((ksp * 64 + o) * 32 + ((half ^ ((o >> 2) & 1)) << 4));
    cpasync16(d, g);
  }
  // B: 2 splits x 196 rows x 16 = 784 16B-chunks
  for (int i = tid; i < 784; i += 128) {
    int sp = i >= 392;
    int rem = sp ? i - 392 : i;
    int row = rem >> 1, half = rem & 1;
    const __nv_bfloat16* xs = sp ? xbl : xbh;
    const void* g = xs + ((size_t)(chunk * 196 + row) * 16 + half * 8);
    int rowg = sp * 196 + row;
    unsigned d = sstage + (unsigned)(SA_BYTES + rowg * 32 + ((half ^ ((rowg >> 2) & 1)) << 4));
    cpasync16(d, g);
  }
}

__global__ __launch_bounds__(128, 3) void mma_conv(
    const __nv_bfloat16* __restrict__ wh, const __nv_bfloat16* __restrict__ wl,
    const float* __restrict__ bias,
    const int* __restrict__ gi, const float* __restrict__ lam,
    const float* __restrict__ gnw, const float* __restrict__ gnb,
    const __nv_bfloat16* __restrict__ ixh, const __nv_bfloat16* __restrict__ ixl,
    __nv_bfloat16* __restrict__ oxh, __nv_bfloat16* __restrict__ oxl,
    int NCH) {
  extern __shared__ __nv_bfloat16 sm[];
  int oQr = blockIdx.x, b = blockIdx.y;
  int tid = threadIdx.x;
  int warp = tid >> 5, lane = tid & 31;
  int tBase = warp * 48;
  int lr = lane >> 2, lc = lane & 3;

  unsigned sb0 = (unsigned)__cvta_generic_to_shared(sm);
  int lane_rA = (lane & 7) + ((lane >> 3) & 1) * 8;
  unsigned rowA_off = (unsigned)(lane_rA * 32 +
                                 ((((lane >> 4) & 1) ^ ((lane_rA >> 2) & 1)) << 4));
  int tbl = tBase + (lane & 7) + ((lane >> 4) & 1) * 8;
  unsigned hB16 = (unsigned)(((lane >> 3) & 1) << 4);

  float acc[4][6][4];
#pragma unroll
  for (int ot = 0; ot < 4; ot++)
#pragma unroll
    for (int tt = 0; tt < 6; tt++)
#pragma unroll
      for (int q = 0; q < 4; q++) acc[ot][tt][q] = 0.f;

  const __nv_bfloat16* xbh = ixh + (size_t)b * NCH0 * 196 * 16;
  const __nv_bfloat16* xbl = ixl + (size_t)b * NCH0 * 196 * 16;

  conv_fill(0, sb0, oQr, wh, wl, xbh, xbl, tid);
  CP_COMMIT();

  for (int it = 0; it < NCH; it++) {
    int s = it & 1;
    if (it + 1 < NCH) {
      conv_fill(it + 1, sb0 + (unsigned)((s ^ 1) * STAGE_BYTES), oQr, wh, wl, xbh, xbl, tid);
      CP_COMMIT();
      asm volatile("cp.async.wait_group 1;" ::: "memory");
    } else {
      asm volatile("cp.async.wait_group 0;" ::: "memory");
    }
    __syncthreads();
    unsigned sbA = sb0 + (unsigned)(s * STAGE_BYTES);
    unsigned sbB = sbA + (unsigned)SA_BYTES;
#pragma unroll 1
    for (int sp = 0; sp < 3; sp++) {
      int aSel = (sp == 2) ? 1 : 0;   // hh, hl, lh
      int bSel = (sp == 1) ? 1 : 0;
#pragma unroll
      for (int k = 0; k < 5; k++) {
        int row0 = bSel * 196 + tbl + k;
        unsigned baseB = sbB + (unsigned)(row0 * 32) +
                         (hB16 ^ (unsigned)((((unsigned)row0 >> 2) & 1) << 4));
        u32 bfr[6][2];
#pragma unroll
        for (int q = 0; q < 3; q++)
          ldsm4(&bfr[2 * q][0], baseB + (unsigned)(q * 512));
        unsigned baseA = sbA + (unsigned)((k * 2 + aSel) * 64 * 32) + rowA_off;
#pragma unroll
        for (int ot = 0; ot < 4; ot++) {
          u32 af[4];
          ldsm4(af, baseA + (unsigned)(ot * 16 * 32));
#pragma unroll
          for (int tt = 0; tt < 6; tt++) mma16816(acc[ot][tt], af, bfr[tt]);
        }
      }
    }
    __syncthreads();
  }

  // ---- epilogue: full-tile smem stage [192][68] + GN stats + fused interp ----
  float* stage = (float*)sm;                 // [192][68]
  float* gsm = stage + 13056;                // 32
  float* smu = stage + 13088;                // 4
  float* srs = stage + 13092;                // 4
  int*   sgi = (int*)(stage + 13096);        // 192
  float* sla = stage + 13288;                // 192

  float bvA[4], bvB[4];
#pragma unroll
  for (int ot = 0; ot < 4; ot++) {
    int o0 = oQr * 64 + ot * 16 + lr;
    bvA[ot] = __ldg(bias + o0);
    bvB[ot] = __ldg(bias + o0 + 8);
  }
#pragma unroll
  for (int ot = 0; ot < 4; ot++) {
    int o0 = ot * 16 + lr;
    float s = 0.f, s2 = 0.f;
#pragma unroll
    for (int tt = 0; tt < 6; tt++) {
      int t = tBase + tt * 8 + lc * 2;
      float v0 = acc[ot][tt][0] + bvA[ot];
      float v1 = acc[ot][tt][1] + bvA[ot];
      float v2 = acc[ot][tt][2] + bvB[ot];
      float v3 = acc[ot][tt][3] + bvB[ot];
      stage[t * 68 + o0] = v0;
      stage[(t + 1) * 68 + o0] = v1;
      stage[t * 68 + o0 + 8] = v2;
      stage[(t + 1) * 68 + o0 + 8] = v3;
      s += v0 + v1 + v2 + v3;
      s2 = fmaf(v0, v0, s2); s2 = fmaf(v1, v1, s2);
      s2 = fmaf(v2, v2, s2); s2 = fmaf(v3, v3, s2);
    }
#pragma unroll
    for (int off = 16; off; off >>= 1) {
      s += __shfl_xor_sync(0xffffffffu, s, off);
      s2 += __shfl_xor_sync(0xffffffffu, s2, off);
    }
    if (lane == 0) {
      gsm[warp * 8 + ot * 2] = s;
      gsm[warp * 8 + ot * 2 + 1] = s2;
    }
  }
  __syncthreads();
  if (tid < 4) {
    int g = tid;
    float s = 0.f, s2 = 0.f;
#pragma unroll
    for (int wt = 0; wt < 4; wt++) {
      s += gsm[wt * 8 + g * 2];
      s2 += gsm[wt * 8 + g * 2 + 1];
    }
    float m = s * (1.0f / 3072.0f);
    float var = s2 * (1.0f / 3072.0f) - m * m;
    float rs = rsqrtf(var + 1e-5f);
    smu[g] = m;
    srs[g] = rs;
    g_mu[b * 16 + oQr * 4 + g] = m;
    g_rsig[b * 16 + oQr * 4 + g] = rs;
  }
  for (int i = tid; i < 192; i += 128) {
    sgi[i] = gi[b * TT + i];
    sla[i] = lam[b * TT + i];
  }
  __syncthreads();

  // fused interp: thread = (channel c = tid&63, t-half = tid>>6)
  {
    int c = tid & 63;
    int th = tid >> 6;
    float m = smu[c >> 4];
    float rs = srs[c >> 4];
    int gc = oQr * 64 + c;
    float w = __ldg(gnw + gc), be = __ldg(gnb + gc);
    int chunk = gc >> 4, cl = gc & 15;
    __nv_bfloat16* xhp = oxh + (size_t)b * NCH0 * 196 * 16 + (size_t)chunk * 196 * 16 + cl;
    __nv_bfloat16* xlp = oxl + (size_t)b * NCH0 * 196 * 16 + (size_t)chunk * 196 * 16 + cl;
#pragma unroll 1
    for (int tp = th * 96; tp < th * 96 + 96; tp++) {
      int g = sgi[tp];
      float val = 0.f;
      if (g >= 0) {
        float lm = sla[tp];
        float a = stage[g * 68 + c];
        float e = stage[(g + 1) * 68 + c];
        float fa = fmaxf((a - m) * rs * w + be, 0.f);
        float fb = fmaxf((e - m) * rs * w + be, 0.f);
        val = (1.0f - lm) * fa + lm * fb;
      }
      __nv_bfloat16 h = __float2bfloat16(val);
      xhp[(size_t)(tp + 2) * 16] = h;
      xlp[(size_t)(tp + 2) * 16] = __float2bfloat16(val - __bfloat162float(h));
    }
  }
}

// ---------------- HMMA xg GEMM: CTA = (dir, b); 128g x 192t, K=256 ----------------
#define XA_ELEMS (2 * 128 * XSTR)
#define XB_ELEMS (2 * 192 * XSTR)
#define XG_SMEM_MAIN ((XA_ELEMS + XB_ELEMS) * 2)
#define XG_SMEM_STAGE (48 * 132 * 4)
#define XG_SMEM (XG_SMEM_MAIN > XG_SMEM_STAGE ? XG_SMEM_MAIN : XG_SMEM_STAGE)

__global__ __launch_bounds__(256) void xg_mma(
    const __nv_bfloat16* __restrict__ xh, const __nv_bfloat16* __restrict__ xl,
    const float* __restrict__ bif, const float* __restrict__ bhf,
    const float* __restrict__ bib, const float* __restrict__ bhb,
    float* __restrict__ xg) {
  extern __shared__ char xsm[];
  __nv_bfloat16* sA = (__nv_bfloat16*)xsm;            // [2][128][XSTR]
  __nv_bfloat16* sB = sA + XA_ELEMS;                  // [2][192][XSTR]
  float* stage = (float*)xsm;                         // [48][132], reused
  int dir = blockIdx.x, b = blockIdx.y;
  const float* bi = dir ? bib : bif;
  const float* bh = dir ? bhb : bhf;
  int tid = threadIdx.x;
  int warp = tid >> 5, lane = tid & 31;
  int warpO = warp & 1, warpT = warp >> 1;
  int oBaseL = warpO * 64, tBase = warpT * 48;
  int lr = lane >> 2, lc = lane & 3;

  unsigned sbA = (unsigned)__cvta_generic_to_shared(sA);
  unsigned sbB = (unsigned)__cvta_generic_to_shared(sB);
  unsigned rowA_off = ((oBaseL + (lane & 7) + ((lane >> 3) & 1) * 8) * XSTR +
                       ((lane >> 4) & 1) * 8) * 2;
  unsigned rowB_off = ((tBase + (lane & 7) + ((lane >> 4) & 1) * 8) * XSTR +
                       ((lane >> 3) & 1) * 8) * 2;

  float acc[4][6][4];
#pragma unroll
  for (int ot = 0; ot < 4; ot++)
#pragma unroll
    for (int tt = 0; tt < 6; tt++)
#pragma unroll
      for (int q = 0; q < 4; q++) acc[ot][tt][q] = 0.f;

  const __nv_bfloat16* xsrc[2] = {xh + (size_t)b * NCH0 * 196 * 16,
                                  xl + (size_t)b * NCH0 * 196 * 16};
  for (int chunk = 0; chunk < 16; chunk++) {
    for (int i = tid; i < 2048; i += 256) {
      int sp = i >> 10;
      int rem = i & 1023;
      int o = rem >> 3, cp = rem & 7;
      const __nv_bfloat16* wsrc = sp ? g_wxl : g_wxh;
      u32 v = *(const u32*)(wsrc + ((size_t)((dir * 16 + chunk) * 128 + o) * 16 + cp * 2));
      *(u32*)(sA + (sp * 128 + o) * XSTR + cp * 2) = v;
    }
    for (int i = tid; i < 3072; i += 256) {
      int sp = i >= 1536;
      int rem = sp ? i - 1536 : i;
      int row = rem >> 3, cp = rem & 7;
      u32 v = *(const u32*)(xsrc[sp] + ((size_t)(chunk * 196 + 2 + row) * 16 + cp * 2));
      *(u32*)(sB + (sp * 192 + row) * XSTR + cp * 2) = v;
    }
    __syncthreads();
#pragma unroll 1
    for (int sp = 0; sp < 3; sp++) {
      int aSel = (sp == 2) ? 1 : 0;
      int bSel = (sp == 1) ? 1 : 0;
      u32 bfr[6][2];
      unsigned baseB = sbB + (unsigned)(bSel * 192 * XSTR * 2) + rowB_off;
#pragma unroll
      for (int q = 0; q < 3; q++)
        ldsm4(&bfr[2 * q][0], baseB + (unsigned)(q * 16 * XSTR * 2));
      unsigned baseA = sbA + (unsigned)(aSel * 128 * XSTR * 2) + rowA_off;
#pragma unroll
      for (int ot = 0; ot < 4; ot++) {
        u32 af[4];
        ldsm4(af, baseA + (unsigned)(ot * 16 * XSTR * 2));
#pragma unroll
        for (int tt = 0; tt < 6; tt++) mma16816(acc[ot][tt], af, bfr[tt]);
      }
    }
    __syncthreads();
  }
  float* xgb = xg + (size_t)(dir * BB + b) * TT * 128;
  for (int q = 0; q < 4; q++) {
    __syncthreads();
    if (warpT == q) {
#pragma unroll
      for (int ot = 0; ot < 4; ot++) {
        int o0 = oBaseL + ot * 16 + lr;
#pragma unroll
        for (int tt = 0; tt < 6; tt++) {
          int tl = tt * 8 + lc * 2;
          stage[tl * 132 + o0] = acc[ot][tt][0];
          stage[(tl + 1) * 132 + o0] = acc[ot][tt][1];
          stage[tl * 132 + o0 + 8] = acc[ot][tt][2];
          stage[(tl + 1) * 132 + o0 + 8] = acc[ot][tt][3];
        }
      }
    }
    __syncthreads();
    for (int i = tid; i < 6144; i += 256) {
      int tl = i >> 7, g = i & 127;
      xgb[(size_t)(q * 48 + tl) * 128 + g] =
          stage[tl * 132 + g] + __ldg(bi + g) + __ldg(bh + g);
    }
  }
}

// ---------------- LSTM recurrence: warp per batch element ----------------
__device__ __forceinline__ float sigf(float x) { return 1.0f / (1.0f + expf(-x)); }

__global__ __launch_bounds__(256) void lstm_kernel(
    const float* __restrict__ xg, const float* __restrict__ whf,
    const float* __restrict__ whb, float* __restrict__ out) {
  __shared__ float ws[32 * 128];
  int dir = blockIdx.y;
  const float* wh = dir ? whb : whf;
  int tid = threadIdx.x;
  for (int idx = tid; idx < 4096; idx += 256) {
    int j = idx >> 7, r = idx & 127;
    ws[idx] = wh[r * 32 + j];
  }
  __syncthreads();
  int warp = tid >> 5, lane = tid & 31;
  int b = blockIdx.x * 8 + warp;
  const float* xgb = xg + (size_t)(dir * BB + b) * TT * 128;
  float h = 0.f, c = 0.f;
  for (int step = 0; step < TT; step++) {
    int t = dir ? (TT - 1 - step) : step;
    const float* p = xgb + (size_t)t * 128;
    float gi = p[lane], gf = p[32 + lane], gg = p[64 + lane], go = p[96 + lane];
#pragma unroll
    for (int j = 0; j < 32; j++) {
      float hj = __shfl_sync(0xffffffffu, h, j);
      const float* wr = ws + j * 128;
      gi = fmaf(wr[lane], hj, gi);
      gf = fmaf(wr[32 + lane], hj, gf);
      gg = fmaf(wr[64 + lane], hj, gg);
      go = fmaf(wr[96 + lane], hj, go);
    }
    c = sigf(gf) * c + sigf(gi) * tanhf(gg);
    h = sigf(go) * tanhf(c);
    if (dir == 0) {
      if ((t & 7) == 7) out[((size_t)b * 24 + (t >> 3)) * 64 + lane] = h;
    } else {
      if ((t & 7) == 0) out[((size_t)b * 24 + (t >> 3)) * 64 + 32 + lane] = h;
    }
  }
}

// ---------------- launch ----------------
extern "C" void kernel_launch(void* const* d_in, const int* in_sizes, int n_in,
                              void* d_out, int out_size) {
  (void)in_sizes; (void)n_in; (void)out_size;
  float *p_xg, *p_lam;
  int* p_gi;
  __nv_bfloat16 *p_xh, *p_xl, *p_wh, *p_wl;
  cudaGetSymbolAddress((void**)&p_xg, g_xg);
  cudaGetSymbolAddress((void**)&p_gi, g_gi);
  cudaGetSymbolAddress((void**)&p_lam, g_lam);
  cudaGetSymbolAddress((void**)&p_xh, g_xh);
  cudaGetSymbolAddress((void**)&p_xl, g_xl);
  cudaGetSymbolAddress((void**)&p_wh, g_wh);
  cudaGetSymbolAddress((void**)&p_wl, g_wl);

  static int smem_set = 0;
  if (!smem_set) {
    cudaFuncSetAttribute(mma_conv, cudaFuncAttributeMaxDynamicSharedMemorySize, CONV_SMEM);
    cudaFuncSetAttribute(xg_mma, cudaFuncAttributeMaxDynamicSharedMemorySize, XG_SMEM);
    smem_set = 1;
  }

  const float* x0 = (const float*)d_in[0];

  // JAX threefry keys: rng = key(42); per layer i: fold_in -> split -> randint split
  KeyPack kp;
  for (int i = 0; i < 3; i++) {
    unsigned f0, f1;
    tf2x32(0u, 42u, 0u, (unsigned)i, f0, f1);
    unsigned k1a, k1b, k2a, k2b;
    tf2x32(f0, f1, 0u, 0u, k1a, k1b);
    tf2x32(f0, f1, 0u, 1u, k2a, k2b);
    unsigned ha, hb2, la, lb2;
    tf2x32(k2a, k2b, 0u, 0u, ha, hb2);
    tf2x32(k2a, k2b, 0u, 1u, la, lb2);
    kp.v[i * 6 + 0] = k1a; kp.v[i * 6 + 1] = k1b;
    kp.v[i * 6 + 2] = ha;  kp.v[i * 6 + 3] = hb2;
    kp.v[i * 6 + 4] = la;  kp.v[i * 6 + 5] = lb2;
  }

  const int wofs[3] = {0, 17 * 5 * 256 * 16, 33 * 5 * 256 * 16};
  // ping-pong: layer0 buf0->buf1, layer1 buf1->buf0, layer2 buf0->buf1
  const size_t inof[3] = {0, IMG, 0};
  const size_t outof[3] = {IMG, 0, IMG};

  interp_meta_all<<<dim3(16, 3), 32>>>(p_gi, p_lam, kp);
  x0prep<<<dim3(BB, NCH0), 192>>>(x0);
  wprep_all<<<245, 256>>>((const float*)d_in[1], (const float*)d_in[5],
                          (const float*)d_in[9]);
  wprep_xg<<<32, 128>>>((const float*)d_in[13], (const float*)d_in[17]);
  for (int i = 0; i < 3; i++) {
    const float* cb = (const float*)d_in[2 + 4 * i];
    const float* gw = (const float*)d_in[3 + 4 * i];
    const float* gb = (const float*)d_in[4 + 4 * i];
    int NCH = (i == 0) ? 17 : 16;
    mma_conv<<<dim3(4, BB), 128, CONV_SMEM>>>(
        p_wh + wofs[i], p_wl + wofs[i], cb,
        p_gi + i * BB * TT, p_lam + i * BB * TT, gw, gb,
        p_xh + inof[i], p_xl + inof[i], p_xh + outof[i], p_xl + outof[i], NCH);
  }
  xg_mma<<<dim3(2, BB), 256, XG_SMEM>>>(p_xh + IMG, p_xl + IMG,
                                        (const float*)d_in[15], (const float*)d_in[16],
                                        (const float*)d_in[19], (const float*)d_in[20],
                                        p_xg);
  lstm_kernel<<<dim3(64, 2), 256>>>(p_xg, (const float*)d_in[14],
                                    (const float*)d_in[18], (float*)d_out);
}

// round 15
// speedup vs baseline: 6.1953x; 1.0979x over previous
#include <cuda_runtime.h>
#include <cuda_bf16.h>
#include <math.h>

#define BB 512
#define TT 192
#define CC 256
#define NCH0 17           // layer0 ci chunks of 16 (257 -> 272)
#define XSTR 24           // xg smem row stride (bf16): conflict-free
#define IMG ((size_t)BB * NCH0 * 196 * 16)

typedef unsigned int u32;

// ---------------- scratch (device globals; no allocation) ----------------
__device__ float g_xg[(size_t)2 * BB * TT * 128]; // lstm pre-gates [dir,B,T,128]
__device__ float g_mu[BB * 16];
__device__ float g_rsig[BB * 16];
__device__ int   g_gi[3 * BB * TT];
__device__ float g_lam[3 * BB * TT];
// DOUBLE-BUFFERED split-bf16 x images: [buf 2][b][chunk<17][row 0..195][ci16]
__device__ __nv_bfloat16 g_xh[2 * IMG];
__device__ __nv_bfloat16 g_xl[2 * IMG];
// split conv weights, all 3 layers: [layer-chunk 49][k 5][o 256][ci16]
__device__ __nv_bfloat16 g_wh[49 * 5 * 256 * 16];
__device__ __nv_bfloat16 g_wl[49 * 5 * 256 * 16];
// split xg weights: [dir 2][chunk 16][g 128][ci16]
__device__ __nv_bfloat16 g_wxh[2 * 16 * 128 * 16];
__device__ __nv_bfloat16 g_wxl[2 * 16 * 128 * 16];

// ---------------- threefry2x32 (JAX), host + device ----------------
__host__ __device__ __forceinline__ void tf2x32(unsigned k0, unsigned k1,
                                                unsigned x0, unsigned x1,
                                                unsigned& y0, unsigned& y1) {
  unsigned ks2 = k0 ^ k1 ^ 0x1BD11BDAu;
  x0 += k0; x1 += k1;
#define TFR(r) x0 += x1; x1 = (x1 << (r)) | (x1 >> (32 - (r))); x1 ^= x0;
  TFR(13) TFR(15) TFR(26) TFR(6)
  x0 += k1;  x1 += ks2 + 1u;
  TFR(17) TFR(29) TFR(16) TFR(24)
  x0 += ks2; x1 += k0 + 2u;
  TFR(13) TFR(15) TFR(26) TFR(6)
  x0 += k0;  x1 += k1 + 3u;
  TFR(17) TFR(29) TFR(16) TFR(24)
  x0 += k1;  x1 += ks2 + 4u;
  TFR(13) TFR(15) TFR(26) TFR(6)
  x0 += ks2; x1 += k0 + 5u;
#undef TFR
  y0 = x0; y1 = x1;
}

__device__ __forceinline__ unsigned tf_bits32(unsigned k0, unsigned k1, unsigned n) {
  unsigned y0, y1;
  tf2x32(k0, k1, 0u, n, y0, y1);
  return y0 ^ y1;
}

// ---------------- mma.sync + ldmatrix + cp.async ----------------
__device__ __forceinline__ void mma16816(float* c, const u32* a, const u32* b) {
  asm volatile(
      "mma.sync.aligned.m16n8k16.row.col.f32.bf16.bf16.f32 "
      "{%0,%1,%2,%3}, {%4,%5,%6,%7}, {%8,%9}, {%0,%1,%2,%3};"
      : "+f"(c[0]), "+f"(c[1]), "+f"(c[2]), "+f"(c[3])
      : "r"(a[0]), "r"(a[1]), "r"(a[2]), "r"(a[3]), "r"(b[0]), "r"(b[1]));
}

__device__ __forceinline__ void ldsm4(u32* r, unsigned addr) {
  asm volatile("ldmatrix.sync.aligned.m8n8.x4.shared.b16 {%0,%1,%2,%3}, [%4];"
               : "=r"(r[0]), "=r"(r[1]), "=r"(r[2]), "=r"(r[3]) : "r"(addr));
}

__device__ __forceinline__ void cpasync16(unsigned d, const void* g) {
  asm volatile("cp.async.cg.shared.global [%0], [%1], 16;" :: "r"(d), "l"(g));
}
#define CP_COMMIT() asm volatile("cp.async.commit_group;" ::: "memory")

// ---------------- conv weight prep: all 3 layers, one launch ----------------
__global__ __launch_bounds__(256) void wprep_all(const float* __restrict__ w0,
                                                 const float* __restrict__ w1,
                                                 const float* __restrict__ w2) {
  int blk = blockIdx.x;   // 0..244
  int layer, lblk;
  if (blk < 85) { layer = 0; lblk = blk; }
  else if (blk < 165) { layer = 1; lblk = blk - 85; }
  else { layer = 2; lblk = blk - 165; }
  const float* w = (layer == 0) ? w0 : ((layer == 1) ? w1 : w2);
  int Cin = (layer == 0) ? 257 : 256;
  int wof = (layer == 0) ? 0 : ((layer == 1) ? 17 * 5 * 256 * 16 : 33 * 5 * 256 * 16);
  int chunk = lblk / 5, k = lblk % 5;
  int o = threadIdx.x;
  size_t base = (size_t)wof + (size_t)((chunk * 5 + k) * 256 + o) * 16;
  for (int cl = 0; cl < 16; cl++) {
    int ci = chunk * 16 + cl;
    float v = (ci < Cin) ? w[((size_t)o * Cin + ci) * 5 + k] : 0.f;
    __nv_bfloat16 h = __float2bfloat16(v);
    g_wh[base + cl] = h;
    g_wl[base + cl] = __float2bfloat16(v - __bfloat162float(h));
  }
}

// ---------------- xg weight prep: [dir][chunk][g][ci] ----------------
__global__ __launch_bounds__(128) void wprep_xg(const float* __restrict__ wf,
                                                const float* __restrict__ wb) {
  int dir = blockIdx.x >> 4, chunk = blockIdx.x & 15;
  int g = threadIdx.x;
  const float* w = dir ? wb : wf;
  size_t base = (size_t)((dir * 16 + chunk) * 128 + g) * 16;
  for (int cl = 0; cl < 16; cl++) {
    float v = w[(size_t)g * CC + chunk * 16 + cl];
    __nv_bfloat16 h = __float2bfloat16(v);
    g_wxh[base + cl] = h;
    g_wxl[base + cl] = __float2bfloat16(v - __bfloat162float(h));
  }
}

// ---------------- x0 prep: transpose+split into buf0; zero pads in BOTH bufs ----------------
__global__ __launch_bounds__(192) void x0prep(const float* __restrict__ x) {
  __shared__ float s[16][193];
  int b = blockIdx.x, ch = blockIdx.y;
  int tid = threadIdx.x;
#pragma unroll
  for (int i = 0; i < 16; i++) {
    int ci = ch * 16 + i;
    s[i][tid] = (ci < 257) ? x[((size_t)b * 257 + ci) * TT + tid] : 0.f;
  }
  __syncthreads();
  size_t ob = (size_t)b * NCH0 * 196 * 16 + (size_t)ch * 196 * 16;
  for (int idx = tid; idx < 196 * 16; idx += 192) {
    int row = idx >> 4, cl = idx & 15;
    int t = row - 2;
    float v = (t >= 0 && t < TT) ? s[cl][t] : 0.f;
    __nv_bfloat16 h = __float2bfloat16(v);
    g_xh[ob + idx] = h;
    g_xl[ob + idx] = __float2bfloat16(v - __bfloat162float(h));
  }
  // zero pad rows (0,1,194,195) of buf1 for this (b, ch)
  if (tid < 64) {
    int rr = tid >> 4, cl = tid & 15;
    int r = (rr < 2) ? rr : (192 + rr);
    size_t xi = IMG + ob + (size_t)r * 16 + cl;
    g_xh[xi] = __float2bfloat16(0.f);
    g_xl[xi] = __float2bfloat16(0.f);
  }
}

// ---------------- interp_lnr metadata: all 3 layers; spread over SMs ----------------
struct KeyPack { unsigned v[18]; };

__global__ __launch_bounds__(32) void interp_meta_all(int* __restrict__ gi,
                                                      float* __restrict__ lam,
                                                      KeyPack kp) {
  int layer = blockIdx.y;
  int b = blockIdx.x * 32 + threadIdx.x;
  if (b >= BB) return;
  const unsigned* K = kp.v + layer * 6;
  int base = layer * BB * TT + b * TT;
  for (int t = 0; t < TT; t++) gi[base + t] = -1;
  int off = 0, pos = 0;
  for (int s = 0; s < 7; s++) {
    unsigned n = (unsigned)(b * 7 + s);
    unsigned ub = tf_bits32(K[0], K[1], n);
    float f = __uint_as_float((ub >> 9) | 0x3f800000u) - 1.0f;
    float scale = f + 0.5f;
    unsigned hb = tf_bits32(K[2], K[3], n);
    unsigned lb = tf_bits32(K[4], K[5], n);
    unsigned offt = ((hb % 13u) * 9u + lb % 13u) % 13u;
    int len = 19 + (int)offt;
    float lenm1 = (float)(len - 1);
    for (int l = 0; l < 64; l++) {
      float idx = __fdiv_rn((float)l, scale);
      float fl = floorf(idx);
      float lm = idx - fl;
      if (fl < lenm1) {
        int io = (int)fl + off;
        if (io < TT - 1) {
          if (pos < TT) { gi[base + pos] = io; lam[base + pos] = lm; }
          pos++;
        }
      }
    }
    off += len;
  }
}

// ---------------- HMMA conv: 64-o CTAs, 128 threads, 3 CTA/SM, ping-pong I/O ----------------
#define SA_BYTES (10 * 64 * 32)
#define SB_BYTES (2 * 196 * 32)
#define STAGE_BYTES (SA_BYTES + SB_BYTES)
#define META_BYTES 1536                 // sgi[192] + sla[192]
#define CONV_SMEM (STAGE_BYTES * 2 + META_BYTES)

__device__ __forceinline__ void conv_fill(int chunk, unsigned sstage, int oQr,
                                          const __nv_bfloat16* wh,
                                          const __nv_bfloat16* wl,
                                          const __nv_bfloat16* xbh,
                                          const __nv_bfloat16* xbl, int tid) {
  // A: 10 tiles (k*2+sp) x 64 o x 16 ci = 1280 16B-chunks, XOR-swizzled
  for (int i = tid; i < 1280; i += 128) {
    int ksp = i >> 7;
    int rem = i & 127;
    int o = rem >> 1, half = rem & 1;
    int k = ksp >> 1, sp = ksp & 1;
    const __nv_bfloat16* wsrc = sp ? wl : wh;
    const void* g = wsrc + ((size_t)((chunk * 5 + k) * 256 + oQr * 64 + o) * 16 + half * 8);
    unsigned d = sstage + (unsigned)((ksp * 64 + o) * 32 + ((half ^ ((o >> 2) & 1)) << 4));
    cpasync16(d, g);
  }
  // B: 2 splits x 196 rows x 16 = 784 16B-chunks
  for (int i = tid; i < 784; i += 128) {
    int sp = i >= 392;
    int rem = sp ? i - 392 : i;
    int row = rem >> 1, half = rem & 1;
    const __nv_bfloat16* xs = sp ? xbl : xbh;
    const void* g = xs + ((size_t)(chunk * 196 + row) * 16 + half * 8);
    int rowg = sp * 196 + row;
    unsigned d = sstage + (unsigned)(SA_BYTES + rowg * 32 + ((half ^ ((rowg >> 2) & 1)) << 4));
    cpasync16(d, g);
  }
}

__global__ __launch_bounds__(128, 3) void mma_conv(
    const __nv_bfloat16* __restrict__ wh, const __nv_bfloat16* __restrict__ wl,
    const float* __restrict__ bias,
    const int* __restrict__ gi, const float* __restrict__ lam,
    const float* __restrict__ gnw, const float* __restrict__ gnb,
    const __nv_bfloat16* __restrict__ ixh, const __nv_bfloat16* __restrict__ ixl,
    __nv_bfloat16* __restrict__ oxh, __nv_bfloat16* __restrict__ oxl,
    int NCH) {
  extern __shared__ __nv_bfloat16 sm[];
  int oQr = blockIdx.x, b = blockIdx.y;
  int tid = threadIdx.x;
  int warp = tid >> 5, lane = tid & 31;
  int tBase = warp * 48;
  int lr = lane >> 2, lc = lane & 3;

  unsigned sb0 = (unsigned)__cvta_generic_to_shared(sm);
  int lane_rA = (lane & 7) + ((lane >> 3) & 1) * 8;
  unsigned rowA_off = (unsigned)(lane_rA * 32 +
                                 ((((lane >> 4) & 1) ^ ((lane_rA >> 2) & 1)) << 4));
  int tbl = tBase + (lane & 7) + ((lane >> 4) & 1) * 8;
  unsigned hB16 = (unsigned)(((lane >> 3) & 1) << 4);

  // dedicated meta region (never touched by pipeline stages)
  int*   sgi = (int*)((char*)sm + 2 * STAGE_BYTES);     // 192
  float* sla = (float*)((char*)sm + 2 * STAGE_BYTES + 768);  // 192

  float acc[4][6][4];
#pragma unroll
  for (int ot = 0; ot < 4; ot++)
#pragma unroll
    for (int tt = 0; tt < 6; tt++)
#pragma unroll
      for (int q = 0; q < 4; q++) acc[ot][tt][q] = 0.f;

  const __nv_bfloat16* xbh = ixh + (size_t)b * NCH0 * 196 * 16;
  const __nv_bfloat16* xbl = ixl + (size_t)b * NCH0 * 196 * 16;

  conv_fill(0, sb0, oQr, wh, wl, xbh, xbl, tid);
  CP_COMMIT();
  // preload interp metadata (overlaps with first cp.async wait)
  for (int i = tid; i < 192; i += 128) {
    sgi[i] = gi[b * TT + i];
    sla[i] = lam[b * TT + i];
  }

  for (int it = 0; it < NCH; it++) {
    int s = it & 1;
    if (it + 1 < NCH) {
      conv_fill(it + 1, sb0 + (unsigned)((s ^ 1) * STAGE_BYTES), oQr, wh, wl, xbh, xbl, tid);
      CP_COMMIT();
      asm volatile("cp.async.wait_group 1;" ::: "memory");
    } else {
      asm volatile("cp.async.wait_group 0;" ::: "memory");
    }
    __syncthreads();
    unsigned sbA = sb0 + (unsigned)(s * STAGE_BYTES);
    unsigned sbB = sbA + (unsigned)SA_BYTES;
#pragma unroll 1
    for (int sp = 0; sp < 3; sp++) {
      int aSel = (sp == 2) ? 1 : 0;   // hh, hl, lh
      int bSel = (sp == 1) ? 1 : 0;
#pragma unroll
      for (int k = 0; k < 5; k++) {
        int row0 = bSel * 196 + tbl + k;
        unsigned baseB = sbB + (unsigned)(row0 * 32) +
                         (hB16 ^ (unsigned)((((unsigned)row0 >> 2) & 1) << 4));
        u32 bfr[6][2];
#pragma unroll
        for (int q = 0; q < 3; q++)
          ldsm4(&bfr[2 * q][0], baseB + (unsigned)(q * 512));
        unsigned baseA = sbA + (unsigned)((k * 2 + aSel) * 64 * 32) + rowA_off;
#pragma unroll
        for (int ot = 0; ot < 4; ot++) {
          u32 af[4];
          ldsm4(af, baseA + (unsigned)(ot * 16 * 32));
#pragma unroll
          for (int tt = 0; tt < 6; tt++) mma16816(acc[ot][tt], af, bfr[tt]);
        }
      }
    }
    __syncthreads();
  }

  // ---- epilogue: full-tile smem stage [192][68] + GN stats + fused interp ----
  float* stage = (float*)sm;                 // [192][68]
  float* gsm = stage + 13056;                // 32
  float* smu = stage + 13088;                // 4
  float* srs = stage + 13092;                // 4

  float bvA[4], bvB[4];
#pragma unroll
  for (int ot = 0; ot < 4; ot++) {
    int o0 = oQr * 64 + ot * 16 + lr;
    bvA[ot] = __ldg(bias + o0);
    bvB[ot] = __ldg(bias + o0 + 8);
  }
#pragma unroll
  for (int ot = 0; ot < 4; ot++) {
    int o0 = ot * 16 + lr;
    float s = 0.f, s2 = 0.f;
#pragma unroll
    for (int tt = 0; tt < 6; tt++) {
      int t = tBase + tt * 8 + lc * 2;
      float v0 = acc[ot][tt][0] + bvA[ot];
      float v1 = acc[ot][tt][1] + bvA[ot];
      float v2 = acc[ot][tt][2] + bvB[ot];
      float v3 = acc[ot][tt][3] + bvB[ot];
      stage[t * 68 + o0] = v0;
      stage[(t + 1) * 68 + o0] = v1;
      stage[t * 68 + o0 + 8] = v2;
      stage[(t + 1) * 68 + o0 + 8] = v3;
      s += v0 + v1 + v2 + v3;
      s2 = fmaf(v0, v0, s2); s2 = fmaf(v1, v1, s2);
      s2 = fmaf(v2, v2, s2); s2 = fmaf(v3, v3, s2);
    }
#pragma unroll
    for (int off = 16; off; off >>= 1) {
      s += __shfl_xor_sync(0xffffffffu, s, off);
      s2 += __shfl_xor_sync(0xffffffffu, s2, off);
    }
    if (lane == 0) {
      gsm[warp * 8 + ot * 2] = s;
      gsm[warp * 8 + ot * 2 + 1] = s2;
    }
  }
  __syncthreads();
  if (tid < 4) {
    int g = tid;
    float s = 0.f, s2 = 0.f;
#pragma unroll
    for (int wt = 0; wt < 4; wt++) {
      s += gsm[wt * 8 + g * 2];
      s2 += gsm[wt * 8 + g * 2 + 1];
    }
    float m = s * (1.0f / 3072.0f);
    float var = s2 * (1.0f / 3072.0f) - m * m;
    float rs = rsqrtf(var + 1e-5f);
    smu[g] = m;
    srs[g] = rs;
    g_mu[b * 16 + oQr * 4 + g] = m;
    g_rsig[b * 16 + oQr * 4 + g] = rs;
  }
  __syncthreads();

  // fused interp: thread = (channel c = tid&63, t-half = tid>>6)
  {
    int c = tid & 63;
    int th = tid >> 6;
    float m = smu[c >> 4];
    float rs = srs[c >> 4];
    int gc = oQr * 64 + c;
    float w = __ldg(gnw + gc), be = __ldg(gnb + gc);
    int chunk = gc >> 4, cl = gc & 15;
    __nv_bfloat16* xhp = oxh + (size_t)b * NCH0 * 196 * 16 + (size_t)chunk * 196 * 16 + cl;
    __nv_bfloat16* xlp = oxl + (size_t)b * NCH0 * 196 * 16 + (size_t)chunk * 196 * 16 + cl;
#pragma unroll 1
    for (int tp = th * 96; tp < th * 96 + 96; tp++) {
      int g = sgi[tp];
      float val = 0.f;
      if (g >= 0) {
        float lm = sla[tp];
        float a = stage[g * 68 + c];
        float e = stage[(g + 1) * 68 + c];
        float fa = fmaxf((a - m) * rs * w + be, 0.f);
        float fb = fmaxf((e - m) * rs * w + be, 0.f);
        val = (1.0f - lm) * fa + lm * fb;
      }
      __nv_bfloat16 h = __float2bfloat16(val);
      xhp[(size_t)(tp + 2) * 16] = h;
      xlp[(size_t)(tp + 2) * 16] = __float2bfloat16(val - __bfloat162float(h));
    }
  }
}

// ---------------- HMMA xg GEMM: 2-stage cp.async pipeline ----------------
#define XA_BYTES (2 * 128 * XSTR * 2)
#define XB_BYTES (2 * 192 * XSTR * 2)
#define XSTAGE_BYTES (XA_BYTES + XB_BYTES)
#define XG_SMEM (XSTAGE_BYTES * 2)

__device__ __forceinline__ void xg_fill(int chunk, unsigned sstage, int dir,
                                        const __nv_bfloat16* xbh,
                                        const __nv_bfloat16* xbl, int tid) {
  // A: 2 sp x 128 o x 2 halves = 512 16B-chunks
  for (int i = tid; i < 512; i += 256) {
    int sp = i >> 8;
    int rem = i & 255;
    int o = rem >> 1, half = rem & 1;
    const __nv_bfloat16* wsrc = sp ? g_wxl : g_wxh;
    const void* g = wsrc + ((size_t)((dir * 16 + chunk) * 128 + o) * 16 + half * 8);
    unsigned d = sstage + (unsigned)((sp * 128 + o) * XSTR * 2 + half * 16);
    cpasync16(d, g);
  }
  // B: 2 sp x 192 rows x 2 halves = 768 16B-chunks (image rows 2..193)
  for (int i = tid; i < 768; i += 256) {
    int sp = i >= 384;
    int rem = sp ? i - 384 : i;
    int row = rem >> 1, half = rem & 1;
    const __nv_bfloat16* xs = sp ? xbl : xbh;
    const void* g = xs + ((size_t)(chunk * 196 + 2 + row) * 16 + half * 8);
    unsigned d = sstage + (unsigned)(XA_BYTES + (sp * 192 + row) * XSTR * 2 + half * 16);
    cpasync16(d, g);
  }
}

__global__ __launch_bounds__(256) void xg_mma(
    const __nv_bfloat16* __restrict__ xh, const __nv_bfloat16* __restrict__ xl,
    const float* __restrict__ bif, const float* __restrict__ bhf,
    const float* __restrict__ bib, const float* __restrict__ bhb,
    float* __restrict__ xg) {
  extern __shared__ char xsm[];
  float* stage = (float*)xsm;                         // [48][132], epilogue reuse
  int dir = blockIdx.x, b = blockIdx.y;
  const float* bi = dir ? bib : bif;
  const float* bh = dir ? bhb : bhf;
  int tid = threadIdx.x;
  int warp = tid >> 5, lane = tid & 31;
  int warpO = warp & 1, warpT = warp >> 1;
  int oBaseL = warpO * 64, tBase = warpT * 48;
  int lr = lane >> 2, lc = lane & 3;

  unsigned sb0 = (unsigned)__cvta_generic_to_shared(xsm);
  unsigned rowA_off = ((oBaseL + (lane & 7) + ((lane >> 3) & 1) * 8) * XSTR +
                       ((lane >> 4) & 1) * 8) * 2;
  unsigned rowB_off = ((tBase + (lane & 7) + ((lane >> 4) & 1) * 8) * XSTR +
                       ((lane >> 3) & 1) * 8) * 2;

  float acc[4][6][4];
#pragma unroll
  for (int ot = 0; ot < 4; ot++)
#pragma unroll
    for (int tt = 0; tt < 6; tt++)
#pragma unroll
      for (int q = 0; q < 4; q++) acc[ot][tt][q] = 0.f;

  const __nv_bfloat16* xbh = xh + (size_t)b * NCH0 * 196 * 16;
  const __nv_bfloat16* xbl = xl + (size_t)b * NCH0 * 196 * 16;

  xg_fill(0, sb0, dir, xbh, xbl, tid);
  CP_COMMIT();

  for (int chunk = 0; chunk < 16; chunk++) {
    int s = chunk & 1;
    if (chunk + 1 < 16) {
      xg_fill(chunk + 1, sb0 + (unsigned)((s ^ 1) * XSTAGE_BYTES), dir, xbh, xbl, tid);
      CP_COMMIT();
      asm volatile("cp.async.wait_group 1;" ::: "memory");
    } else {
      asm volatile("cp.async.wait_group 0;" ::: "memory");
    }
    __syncthreads();
    unsigned sbA = sb0 + (unsigned)(s * XSTAGE_BYTES);
    unsigned sbB = sbA + (unsigned)XA_BYTES;
#pragma unroll 1
    for (int sp = 0; sp < 3; sp++) {
      int aSel = (sp == 2) ? 1 : 0;
      int bSel = (sp == 1) ? 1 : 0;
      u32 bfr[6][2];
      unsigned baseB = sbB + (unsigned)(bSel * 192 * XSTR * 2) + rowB_off;
#pragma unroll
      for (int q = 0; q < 3; q++)
        ldsm4(&bfr[2 * q][0], baseB + (unsigned)(q * 16 * XSTR * 2));
      unsigned baseA = sbA + (unsigned)(aSel * 128 * XSTR * 2) + rowA_off;
#pragma unroll
      for (int ot = 0; ot < 4; ot++) {
        u32 af[4];
        ldsm4(af, baseA + (unsigned)(ot * 16 * XSTR * 2));
#pragma unroll
        for (int tt = 0; tt < 6; tt++) mma16816(acc[ot][tt], af, bfr[tt]);
      }
    }
    __syncthreads();
  }
  float* xgb = xg + (size_t)(dir * BB + b) * TT * 128;
  for (int q = 0; q < 4; q++) {
    __syncthreads();
    if (warpT == q) {
#pragma unroll
      for (int ot = 0; ot < 4; ot++) {
        int o0 = oBaseL + ot * 16 + lr;
#pragma unroll
        for (int tt = 0; tt < 6; tt++) {
          int tl = tt * 8 + lc * 2;
          stage[tl * 132 + o0] = acc[ot][tt][0];
          stage[(tl + 1) * 132 + o0] = acc[ot][tt][1];
          stage[tl * 132 + o0 + 8] = acc[ot][tt][2];
          stage[(tl + 1) * 132 + o0 + 8] = acc[ot][tt][3];
        }
      }
    }
    __syncthreads();
    for (int i = tid; i < 6144; i += 256) {
      int tl = i >> 7, g = i & 127;
      xgb[(size_t)(q * 48 + tl) * 128 + g] =
          stage[tl * 132 + g] + __ldg(bi + g) + __ldg(bh + g);
    }
  }
}

// ---------------- LSTM recurrence: warp per batch, prefetched gates ----------------
__device__ __forceinline__ float sigf(float x) { return 1.0f / (1.0f + expf(-x)); }

__global__ __launch_bounds__(256) void lstm_kernel(
    const float* __restrict__ xg, const float* __restrict__ whf,
    const float* __restrict__ whb, float* __restrict__ out) {
  __shared__ float ws[32 * 128];
  int dir = blockIdx.y;
  const float* wh = dir ? whb : whf;
  int tid = threadIdx.x;
  for (int idx = tid; idx < 4096; idx += 256) {
    int j = idx >> 7, r = idx & 127;
    ws[idx] = wh[r * 32 + j];
  }
  __syncthreads();
  int warp = tid >> 5, lane = tid & 31;
  int b = blockIdx.x * 8 + warp;
  const float* xgb = xg + (size_t)(dir * BB + b) * TT * 128;
  float h = 0.f, c = 0.f;
  int t0 = dir ? (TT - 1) : 0;
  const float* p0 = xgb + (size_t)t0 * 128;
  float gi = p0[lane], gf = p0[32 + lane], gg = p0[64 + lane], go = p0[96 + lane];
  for (int step = 0; step < TT; step++) {
    int t = dir ? (TT - 1 - step) : step;
    float ni = 0.f, nf = 0.f, ng = 0.f, no = 0.f;
    if (step + 1 < TT) {
      int tn = dir ? (t - 1) : (t + 1);
      const float* pn = xgb + (size_t)tn * 128;
      ni = pn[lane]; nf = pn[32 + lane]; ng = pn[64 + lane]; no = pn[96 + lane];
    }
#pragma unroll
    for (int j = 0; j < 32; j++) {
      float hj = __shfl_sync(0xffffffffu, h, j);
      const float* wr = ws + j * 128;
      gi = fmaf(wr[lane], hj, gi);
      gf = fmaf(wr[32 + lane], hj, gf);
      gg = fmaf(wr[64 + lane], hj, gg);
      go = fmaf(wr[96 + lane], hj, go);
    }
    c = sigf(gf) * c + sigf(gi) * tanhf(gg);
    h = sigf(go) * tanhf(c);
    if (dir == 0) {
      if ((t & 7) == 7) out[((size_t)b * 24 + (t >> 3)) * 64 + lane] = h;
    } else {
      if ((t & 7) == 0) out[((size_t)b * 24 + (t >> 3)) * 64 + 32 + lane] = h;
    }
    gi = ni; gf = nf; gg = ng; go = no;
  }
}

// ---------------- launch ----------------
extern "C" void kernel_launch(void* const* d_in, const int* in_sizes, int n_in,
                              void* d_out, int out_size) {
  (void)in_sizes; (void)n_in; (void)out_size;
  float *p_xg, *p_lam;
  int* p_gi;
  __nv_bfloat16 *p_xh, *p_xl, *p_wh, *p_wl;
  cudaGetSymbolAddress((void**)&p_xg, g_xg);
  cudaGetSymbolAddress((void**)&p_gi, g_gi);
  cudaGetSymbolAddress((void**)&p_lam, g_lam);
  cudaGetSymbolAddress((void**)&p_xh, g_xh);
  cudaGetSymbolAddress((void**)&p_xl, g_xl);
  cudaGetSymbolAddress((void**)&p_wh, g_wh);
  cudaGetSymbolAddress((void**)&p_wl, g_wl);

  static int smem_set = 0;
  if (!smem_set) {
    cudaFuncSetAttribute(mma_conv, cudaFuncAttributeMaxDynamicSharedMemorySize, CONV_SMEM);
    cudaFuncSetAttribute(xg_mma, cudaFuncAttributeMaxDynamicSharedMemorySize, XG_SMEM);
    smem_set = 1;
  }

  const float* x0 = (const float*)d_in[0];

  // JAX threefry keys: rng = key(42); per layer i: fold_in -> split -> randint split
  KeyPack kp;
  for (int i = 0; i < 3; i++) {
    unsigned f0, f1;
    tf2x32(0u, 42u, 0u, (unsigned)i, f0, f1);
    unsigned k1a, k1b, k2a, k2b;
    tf2x32(f0, f1, 0u, 0u, k1a, k1b);
    tf2x32(f0, f1, 0u, 1u, k2a, k2b);
    unsigned ha, hb2, la, lb2;
    tf2x32(k2a, k2b, 0u, 0u, ha, hb2);
    tf2x32(k2a, k2b, 0u, 1u, la, lb2);
    kp.v[i * 6 + 0] = k1a; kp.v[i * 6 + 1] = k1b;
    kp.v[i * 6 + 2] = ha;  kp.v[i * 6 + 3] = hb2;
    kp.v[i * 6 + 4] = la;  kp.v[i * 6 + 5] = lb2;
  }

  const int wofs[3] = {0, 17 * 5 * 256 * 16, 33 * 5 * 256 * 16};
  // ping-pong: layer0 buf0->buf1, layer1 buf1->buf0, layer2 buf0->buf1
  const size_t inof[3] = {0, IMG, 0};
  const size_t outof[3] = {IMG, 0, IMG};

  interp_meta_all<<<dim3(16, 3), 32>>>(p_gi, p_lam, kp);
  x0prep<<<dim3(BB, NCH0), 192>>>(x0);
  wprep_all<<<245, 256>>>((const float*)d_in[1], (const float*)d_in[5],
                          (const float*)d_in[9]);
  wprep_xg<<<32, 128>>>((const float*)d_in[13], (const float*)d_in[17]);
  for (int i = 0; i < 3; i++) {
    const float* cb = (const float*)d_in[2 + 4 * i];
    const float* gw = (const float*)d_in[3 + 4 * i];
    const float* gb = (const float*)d_in[4 + 4 * i];
    int NCH = (i == 0) ? 17 : 16;
    mma_conv<<<dim3(4, BB), 128, CONV_SMEM>>>(
        p_wh + wofs[i], p_wl + wofs[i], cb,
        p_gi + i * BB * TT, p_lam + i * BB * TT, gw, gb,
        p_xh + inof[i], p_xl + inof[i], p_xh + outof[i], p_xl + outof[i], NCH);
  }
  xg_mma<<<dim3(2, BB), 256, XG_SMEM>>>(p_xh + IMG, p_xl + IMG,
                                        (const float*)d_in[15], (const float*)d_in[16],
                                        (const float*)d_in[19], (const float*)d_in[20],
                                        p_xg);
  lstm_kernel<<<dim3(64, 2), 256>>>(p_xg, (const float*)d_in[14],
                                    (const float*)d_in[18], (float*)d_out);
}

// round 16
// speedup vs baseline: 8.0283x; 1.2959x over previous
#include <cuda_runtime.h>
#include <cuda_fp16.h>
#include <math.h>

#define BB 512
#define TT 192
#define CC 256
#define NCH0 17           // layer0 ci chunks of 16 (257 -> 272)
#define XSTR 24           // xg smem row stride (fp16): conflict-free
#define IMG ((size_t)BB * NCH0 * 196 * 16)

typedef unsigned int u32;

// ---------------- scratch (device globals; no allocation) ----------------
__device__ float g_xg[(size_t)2 * BB * TT * 128]; // lstm pre-gates [dir,B,T,128]
__device__ float g_mu[BB * 16];
__device__ float g_rsig[BB * 16];
__device__ int   g_gi[3 * BB * TT];
__device__ float g_lam[3 * BB * TT];
// DOUBLE-BUFFERED fp16-split x images: [buf 2][b][chunk<17][row 0..195][ci16]
__device__ __half g_xh[2 * IMG];
__device__ __half g_xl[2 * IMG];
// fp16 conv weights, all 3 layers: [layer-chunk 49][k 5][o 256][ci16]
__device__ __half g_wh[49 * 5 * 256 * 16];
// fp16 xg weights: [dir 2][chunk 16][g 128][ci16]
__device__ __half g_wxh[2 * 16 * 128 * 16];

// ---------------- threefry2x32 (JAX), host + device ----------------
__host__ __device__ __forceinline__ void tf2x32(unsigned k0, unsigned k1,
                                                unsigned x0, unsigned x1,
                                                unsigned& y0, unsigned& y1) {
  unsigned ks2 = k0 ^ k1 ^ 0x1BD11BDAu;
  x0 += k0; x1 += k1;
#define TFR(r) x0 += x1; x1 = (x1 << (r)) | (x1 >> (32 - (r))); x1 ^= x0;
  TFR(13) TFR(15) TFR(26) TFR(6)
  x0 += k1;  x1 += ks2 + 1u;
  TFR(17) TFR(29) TFR(16) TFR(24)
  x0 += ks2; x1 += k0 + 2u;
  TFR(13) TFR(15) TFR(26) TFR(6)
  x0 += k0;  x1 += k1 + 3u;
  TFR(17) TFR(29) TFR(16) TFR(24)
  x0 += k1;  x1 += ks2 + 4u;
  TFR(13) TFR(15) TFR(26) TFR(6)
  x0 += ks2; x1 += k0 + 5u;
#undef TFR
  y0 = x0; y1 = x1;
}

__device__ __forceinline__ unsigned tf_bits32(unsigned k0, unsigned k1, unsigned n) {
  unsigned y0, y1;
  tf2x32(k0, k1, 0u, n, y0, y1);
  return y0 ^ y1;
}

// ---------------- mma.sync (fp16) + ldmatrix + cp.async ----------------
__device__ __forceinline__ void mma16816(float* c, const u32* a, const u32* b) {
  asm volatile(
      "mma.sync.aligned.m16n8k16.row.col.f32.f16.f16.f32 "
      "{%0,%1,%2,%3}, {%4,%5,%6,%7}, {%8,%9}, {%0,%1,%2,%3};"
      : "+f"(c[0]), "+f"(c[1]), "+f"(c[2]), "+f"(c[3])
      : "r"(a[0]), "r"(a[1]), "r"(a[2]), "r"(a[3]), "r"(b[0]), "r"(b[1]));
}

__device__ __forceinline__ void ldsm4(u32* r, unsigned addr) {
  asm volatile("ldmatrix.sync.aligned.m8n8.x4.shared.b16 {%0,%1,%2,%3}, [%4];"
               : "=r"(r[0]), "=r"(r[1]), "=r"(r[2]), "=r"(r[3]) : "r"(addr));
}

__device__ __forceinline__ void cpasync16(unsigned d, const void* g) {
  asm volatile("cp.async.cg.shared.global [%0], [%1], 16;" :: "r"(d), "l"(g));
}
#define CP_COMMIT() asm volatile("cp.async.commit_group;" ::: "memory")

// ---------------- conv weight prep: all 3 layers, single fp16 ----------------
__global__ __launch_bounds__(256) void wprep_all(const float* __restrict__ w0,
                                                 const float* __restrict__ w1,
                                                 const float* __restrict__ w2) {
  int blk = blockIdx.x;   // 0..244
  int layer, lblk;
  if (blk < 85) { layer = 0; lblk = blk; }
  else if (blk < 165) { layer = 1; lblk = blk - 85; }
  else { layer = 2; lblk = blk - 165; }
  const float* w = (layer == 0) ? w0 : ((layer == 1) ? w1 : w2);
  int Cin = (layer == 0) ? 257 : 256;
  int wof = (layer == 0) ? 0 : ((layer == 1) ? 17 * 5 * 256 * 16 : 33 * 5 * 256 * 16);
  int chunk = lblk / 5, k = lblk % 5;
  int o = threadIdx.x;
  size_t base = (size_t)wof + (size_t)((chunk * 5 + k) * 256 + o) * 16;
  for (int cl = 0; cl < 16; cl++) {
    int ci = chunk * 16 + cl;
    float v = (ci < Cin) ? w[((size_t)o * Cin + ci) * 5 + k] : 0.f;
    g_wh[base + cl] = __float2half_rn(v);
  }
}

// ---------------- xg weight prep: single fp16 ----------------
__global__ __launch_bounds__(128) void wprep_xg(const float* __restrict__ wf,
                                                const float* __restrict__ wb) {
  int dir = blockIdx.x >> 4, chunk = blockIdx.x & 15;
  int g = threadIdx.x;
  const float* w = dir ? wb : wf;
  size_t base = (size_t)((dir * 16 + chunk) * 128 + g) * 16;
  for (int cl = 0; cl < 16; cl++)
    g_wxh[base + cl] = __float2half_rn(w[(size_t)g * CC + chunk * 16 + cl]);
}

// ---------------- x0 prep: transpose + fp16 split into buf0; pads both bufs ----------------
__global__ __launch_bounds__(192) void x0prep(const float* __restrict__ x) {
  __shared__ float s[16][193];
  int b = blockIdx.x, ch = blockIdx.y;
  int tid = threadIdx.x;
#pragma unroll
  for (int i = 0; i < 16; i++) {
    int ci = ch * 16 + i;
    s[i][tid] = (ci < 257) ? x[((size_t)b * 257 + ci) * TT + tid] : 0.f;
  }
  __syncthreads();
  size_t ob = (size_t)b * NCH0 * 196 * 16 + (size_t)ch * 196 * 16;
  for (int idx = tid; idx < 196 * 16; idx += 192) {
    int row = idx >> 4, cl = idx & 15;
    int t = row - 2;
    float v = (t >= 0 && t < TT) ? s[cl][t] : 0.f;
    __half h = __float2half_rn(v);
    g_xh[ob + idx] = h;
    g_xl[ob + idx] = __float2half_rn(v - __half2float(h));
  }
  if (tid < 64) {
    int rr = tid >> 4, cl = tid & 15;
    int r = (rr < 2) ? rr : (192 + rr);
    size_t xi = IMG + ob + (size_t)r * 16 + cl;
    g_xh[xi] = __float2half_rn(0.f);
    g_xl[xi] = __float2half_rn(0.f);
  }
}

// ---------------- interp_lnr metadata ----------------
struct KeyPack { unsigned v[18]; };

__global__ __launch_bounds__(32) void interp_meta_all(int* __restrict__ gi,
                                                      float* __restrict__ lam,
                                                      KeyPack kp) {
  int layer = blockIdx.y;
  int b = blockIdx.x * 32 + threadIdx.x;
  if (b >= BB) return;
  const unsigned* K = kp.v + layer * 6;
  int base = layer * BB * TT + b * TT;
  for (int t = 0; t < TT; t++) gi[base + t] = -1;
  int off = 0, pos = 0;
  for (int s = 0; s < 7; s++) {
    unsigned n = (unsigned)(b * 7 + s);
    unsigned ub = tf_bits32(K[0], K[1], n);
    float f = __uint_as_float((ub >> 9) | 0x3f800000u) - 1.0f;
    float scale = f + 0.5f;
    unsigned hb = tf_bits32(K[2], K[3], n);
    unsigned lb = tf_bits32(K[4], K[5], n);
    unsigned offt = ((hb % 13u) * 9u + lb % 13u) % 13u;
    int len = 19 + (int)offt;
    float lenm1 = (float)(len - 1);
    for (int l = 0; l < 64; l++) {
      float idx = __fdiv_rn((float)l, scale);
      float fl = floorf(idx);
      float lm = idx - fl;
      if (fl < lenm1) {
        int io = (int)fl + off;
        if (io < TT - 1) {
          if (pos < TT) { gi[base + pos] = io; lam[base + pos] = lm; }
          pos++;
        }
      }
    }
    off += len;
  }
}

// ---------------- HMMA conv: fp16 2-pass; 64-o CTAs, 128 thr, 3 CTA/SM ----------------
#define SA_BYTES (5 * 64 * 32)
#define SB_BYTES (2 * 196 * 32)
#define STAGE_BYTES (SA_BYTES + SB_BYTES)
// smem map: [0 .. 2*STAGE_BYTES) pipeline; epilogue stage [192][68] fp32 = 52224
// meta (sgi/sla/gsm/smu/srs) above max(pipeline, stage)
#define META_OFF 52224
#define CONV_SMEM (META_OFF + 1792)

__device__ __forceinline__ void conv_fill(int chunk, unsigned sstage, int oQr,
                                          const __half* wh,
                                          const __half* xbh,
                                          const __half* xbl, int tid) {
  // A: 5 tap-tiles x 64 o x 16 ci = 640 16B-chunks, XOR-swizzled
  for (int i = tid; i < 640; i += 128) {
    int k = i >> 7;
    int rem = i & 127;
    int o = rem >> 1, half = rem & 1;
    const void* g = wh + ((size_t)((chunk * 5 + k) * 256 + oQr * 64 + o) * 16 + half * 8);
    unsigned d = sstage + (unsigned)((k * 64 + o) * 32 + ((half ^ ((o >> 2) & 1)) << 4));
    cpasync16(d, g);
  }
  // B: 2 splits x 196 rows x 16 = 784 16B-chunks
  for (int i = tid; i < 784; i += 128) {
    int sp = i >= 392;
    int rem = sp ? i - 392 : i;
    int row = rem >> 1, half = rem & 1;
    const __half* xs = sp ? xbl : xbh;
    const void* g = xs + ((size_t)(chunk * 196 + row) * 16 + half * 8);
    int rowg = sp * 196 + row;
    unsigned d = sstage + (unsigned)(SA_BYTES + rowg * 32 + ((half ^ ((rowg >> 2) & 1)) << 4));
    cpasync16(d, g);
  }
}

__global__ __launch_bounds__(128, 3) void mma_conv(
    const __half* __restrict__ wh,
    const float* __restrict__ bias,
    const int* __restrict__ gi, const float* __restrict__ lam,
    const float* __restrict__ gnw, const float* __restrict__ gnb,
    const __half* __restrict__ ixh, const __half* __restrict__ ixl,
    __half* __restrict__ oxh, __half* __restrict__ oxl,
    int NCH) {
  extern __shared__ __half sm[];
  int oQr = blockIdx.x, b = blockIdx.y;
  int tid = threadIdx.x;
  int warp = tid >> 5, lane = tid & 31;
  int tBase = warp * 48;
  int lr = lane >> 2, lc = lane & 3;

  unsigned sb0 = (unsigned)__cvta_generic_to_shared(sm);
  int lane_rA = (lane & 7) + ((lane >> 3) & 1) * 8;
  unsigned rowA_off = (unsigned)(lane_rA * 32 +
                                 ((((lane >> 4) & 1) ^ ((lane_rA >> 2) & 1)) << 4));
  int tbl = tBase + (lane & 7) + ((lane >> 4) & 1) * 8;
  unsigned hB16 = (unsigned)(((lane >> 3) & 1) << 4);

  int*   sgi = (int*)((char*)sm + META_OFF);           // 192
  float* sla = (float*)((char*)sm + META_OFF + 768);   // 192
  float* gsm = (float*)((char*)sm + META_OFF + 1536);  // 32
  float* smu = gsm + 32;                               // 4
  float* srs = gsm + 36;                               // 4

  float acc[4][6][4];
#pragma unroll
  for (int ot = 0; ot < 4; ot++)
#pragma unroll
    for (int tt = 0; tt < 6; tt++)
#pragma unroll
      for (int q = 0; q < 4; q++) acc[ot][tt][q] = 0.f;

  const __half* xbh = ixh + (size_t)b * NCH0 * 196 * 16;
  const __half* xbl = ixl + (size_t)b * NCH0 * 196 * 16;

  conv_fill(0, sb0, oQr, wh, xbh, xbl, tid);
  CP_COMMIT();
  for (int i = tid; i < 192; i += 128) {
    sgi[i] = gi[b * TT + i];
    sla[i] = lam[b * TT + i];
  }

  for (int it = 0; it < NCH; it++) {
    int s = it & 1;
    if (it + 1 < NCH) {
      conv_fill(it + 1, sb0 + (unsigned)((s ^ 1) * STAGE_BYTES), oQr, wh, xbh, xbl, tid);
      CP_COMMIT();
      asm volatile("cp.async.wait_group 1;" ::: "memory");
    } else {
      asm volatile("cp.async.wait_group 0;" ::: "memory");
    }
    __syncthreads();
    unsigned sbA = sb0 + (unsigned)(s * STAGE_BYTES);
    unsigned sbB = sbA + (unsigned)SA_BYTES;
#pragma unroll 1
    for (int sp = 0; sp < 2; sp++) {    // passes: wh*xh, wh*xl
#pragma unroll
      for (int k = 0; k < 5; k++) {
        int row0 = sp * 196 + tbl + k;
        unsigned baseB = sbB + (unsigned)(row0 * 32) +
                         (hB16 ^ (unsigned)((((unsigned)row0 >> 2) & 1) << 4));
        u32 bfr[6][2];
#pragma unroll
        for (int q = 0; q < 3; q++)
          ldsm4(&bfr[2 * q][0], baseB + (unsigned)(q * 512));
        unsigned baseA = sbA + (unsigned)(k * 64 * 32) + rowA_off;
#pragma unroll
        for (int ot = 0; ot < 4; ot++) {
          u32 af[4];
          ldsm4(af, baseA + (unsigned)(ot * 16 * 32));
#pragma unroll
          for (int tt = 0; tt < 6; tt++) mma16816(acc[ot][tt], af, bfr[tt]);
        }
      }
    }
    __syncthreads();
  }

  // ---- epilogue: full-tile smem stage [192][68] + GN stats + fused interp ----
  float* stage = (float*)sm;                 // [192][68]

  float bvA[4], bvB[4];
#pragma unroll
  for (int ot = 0; ot < 4; ot++) {
    int o0 = oQr * 64 + ot * 16 + lr;
    bvA[ot] = __ldg(bias + o0);
    bvB[ot] = __ldg(bias + o0 + 8);
  }
#pragma unroll
  for (int ot = 0; ot < 4; ot++) {
    int o0 = ot * 16 + lr;
    float s = 0.f, s2 = 0.f;
#pragma unroll
    for (int tt = 0; tt < 6; tt++) {
      int t = tBase + tt * 8 + lc * 2;
      float v0 = acc[ot][tt][0] + bvA[ot];
      float v1 = acc[ot][tt][1] + bvA[ot];
      float v2 = acc[ot][tt][2] + bvB[ot];
      float v3 = acc[ot][tt][3] + bvB[ot];
      stage[t * 68 + o0] = v0;
      stage[(t + 1) * 68 + o0] = v1;
      stage[t * 68 + o0 + 8] = v2;
      stage[(t + 1) * 68 + o0 + 8] = v3;
      s += v0 + v1 + v2 + v3;
      s2 = fmaf(v0, v0, s2); s2 = fmaf(v1, v1, s2);
      s2 = fmaf(v2, v2, s2); s2 = fmaf(v3, v3, s2);
    }
#pragma unroll
    for (int off = 16; off; off >>= 1) {
      s += __shfl_xor_sync(0xffffffffu, s, off);
      s2 += __shfl_xor_sync(0xffffffffu, s2, off);
    }
    if (lane == 0) {
      gsm[warp * 8 + ot * 2] = s;
      gsm[warp * 8 + ot * 2 + 1] = s2;
    }
  }
  __syncthreads();
  if (tid < 4) {
    int g = tid;
    float s = 0.f, s2 = 0.f;
#pragma unroll
    for (int wt = 0; wt < 4; wt++) {
      s += gsm[wt * 8 + g * 2];
      s2 += gsm[wt * 8 + g * 2 + 1];
    }
    float m = s * (1.0f / 3072.0f);
    float var = s2 * (1.0f / 3072.0f) - m * m;
    float rs = rsqrtf(var + 1e-5f);
    smu[g] = m;
    srs[g] = rs;
    g_mu[b * 16 + oQr * 4 + g] = m;
    g_rsig[b * 16 + oQr * 4 + g] = rs;
  }
  __syncthreads();

  // fused interp: thread = (channel c = tid&63, t-half = tid>>6)
  {
    int c = tid & 63;
    int th = tid >> 6;
    float m = smu[c >> 4];
    float rs = srs[c >> 4];
    int gc = oQr * 64 + c;
    float w = __ldg(gnw + gc), be = __ldg(gnb + gc);
    int chunk = gc >> 4, cl = gc & 15;
    __half* xhp = oxh + (size_t)b * NCH0 * 196 * 16 + (size_t)chunk * 196 * 16 + cl;
    __half* xlp = oxl + (size_t)b * NCH0 * 196 * 16 + (size_t)chunk * 196 * 16 + cl;
#pragma unroll 1
    for (int tp = th * 96; tp < th * 96 + 96; tp++) {
      int g = sgi[tp];
      float val = 0.f;
      if (g >= 0) {
        float lm = sla[tp];
        float a = stage[g * 68 + c];
        float e = stage[(g + 1) * 68 + c];
        float fa = fmaxf((a - m) * rs * w + be, 0.f);
        float fb = fmaxf((e - m) * rs * w + be, 0.f);
        val = (1.0f - lm) * fa + lm * fb;
      }
      __half h = __float2half_rn(val);
      xhp[(size_t)(tp + 2) * 16] = h;
      xlp[(size_t)(tp + 2) * 16] = __float2half_rn(val - __half2float(h));
    }
  }
}

// ---------------- HMMA xg GEMM: fp16 2-pass, 2-stage cp.async ----------------
#define XA_BYTES (128 * XSTR * 2)
#define XB_BYTES (2 * 192 * XSTR * 2)
#define XSTAGE_BYTES (XA_BYTES + XB_BYTES)
#define XG_SMEM_MAIN (XSTAGE_BYTES * 2)
#define XG_SMEM_STAGE (48 * 132 * 4)
#define XG_SMEM (XG_SMEM_MAIN > XG_SMEM_STAGE ? XG_SMEM_MAIN : XG_SMEM_STAGE)

__device__ __forceinline__ void xg_fill(int chunk, unsigned sstage, int dir,
                                        const __half* xbh,
                                        const __half* xbl, int tid) {
  // A: 128 g x 2 halves = 256 16B-chunks
  for (int i = tid; i < 256; i += 256) {
    int o = i >> 1, half = i & 1;
    const void* g = g_wxh + ((size_t)((dir * 16 + chunk) * 128 + o) * 16 + half * 8);
    unsigned d = sstage + (unsigned)(o * XSTR * 2 + half * 16);
    cpasync16(d, g);
  }
  // B: 2 sp x 192 rows x 2 halves = 768 16B-chunks (image rows 2..193)
  for (int i = tid; i < 768; i += 256) {
    int sp = i >= 384;
    int rem = sp ? i - 384 : i;
    int row = rem >> 1, half = rem & 1;
    const __half* xs = sp ? xbl : xbh;
    const void* g = xs + ((size_t)(chunk * 196 + 2 + row) * 16 + half * 8);
    unsigned d = sstage + (unsigned)(XA_BYTES + (sp * 192 + row) * XSTR * 2 + half * 16);
    cpasync16(d, g);
  }
}

__global__ __launch_bounds__(256) void xg_mma(
    const __half* __restrict__ xh, const __half* __restrict__ xl,
    const float* __restrict__ bif, const float* __restrict__ bhf,
    const float* __restrict__ bib, const float* __restrict__ bhb,
    float* __restrict__ xg) {
  extern __shared__ char xsm[];
  float* stage = (float*)xsm;                         // [48][132], epilogue reuse
  int dir = blockIdx.x, b = blockIdx.y;
  const float* bi = dir ? bib : bif;
  const float* bh = dir ? bhb : bhf;
  int tid = threadIdx.x;
  int warp = tid >> 5, lane = tid & 31;
  int warpO = warp & 1, warpT = warp >> 1;
  int oBaseL = warpO * 64, tBase = warpT * 48;
  int lr = lane >> 2, lc = lane & 3;

  unsigned sb0 = (unsigned)__cvta_generic_to_shared(xsm);
  unsigned rowA_off = ((oBaseL + (lane & 7) + ((lane >> 3) & 1) * 8) * XSTR +
                       ((lane >> 4) & 1) * 8) * 2;
  unsigned rowB_off = ((tBase + (lane & 7) + ((lane >> 4) & 1) * 8) * XSTR +
                       ((lane >> 3) & 1) * 8) * 2;

  float acc[4][6][4];
#pragma unroll
  for (int ot = 0; ot < 4; ot++)
#pragma unroll
    for (int tt = 0; tt < 6; tt++)
#pragma unroll
      for (int q = 0; q < 4; q++) acc[ot][tt][q] = 0.f;

  const __half* xbh = xh + (size_t)b * NCH0 * 196 * 16;
  const __half* xbl = xl + (size_t)b * NCH0 * 196 * 16;

  xg_fill(0, sb0, dir, xbh, xbl, tid);
  CP_COMMIT();

  for (int chunk = 0; chunk < 16; chunk++) {
    int s = chunk & 1;
    if (chunk + 1 < 16) {
      xg_fill(chunk + 1, sb0 + (unsigned)((s ^ 1) * XSTAGE_BYTES), dir, xbh, xbl, tid);
      CP_COMMIT();
      asm volatile("cp.async.wait_group 1;" ::: "memory");
    } else {
      asm volatile("cp.async.wait_group 0;" ::: "memory");
    }
    __syncthreads();
    unsigned sbA = sb0 + (unsigned)(s * XSTAGE_BYTES);
    unsigned sbB = sbA + (unsigned)XA_BYTES;
#pragma unroll 1
    for (int sp = 0; sp < 2; sp++) {
      u32 bfr[6][2];
      unsigned baseB = sbB + (unsigned)(sp * 192 * XSTR * 2) + rowB_off;
#pragma unroll
      for (int q = 0; q < 3; q++)
        ldsm4(&bfr[2 * q][0], baseB + (unsigned)(q * 16 * XSTR * 2));
      unsigned baseA = sbA + rowA_off;
#pragma unroll
      for (int ot = 0; ot < 4; ot++) {
        u32 af[4];
        ldsm4(af, baseA + (unsigned)(ot * 16 * XSTR * 2));
#pragma unroll
        for (int tt = 0; tt < 6; tt++) mma16816(acc[ot][tt], af, bfr[tt]);
      }
    }
    __syncthreads();
  }
  float* xgb = xg + (size_t)(dir * BB + b) * TT * 128;
  for (int q = 0; q < 4; q++) {
    __syncthreads();
    if (warpT == q) {
#pragma unroll
      for (int ot = 0; ot < 4; ot++) {
        int o0 = oBaseL + ot * 16 + lr;
#pragma unroll
        for (int tt = 0; tt < 6; tt++) {
          int tl = tt * 8 + lc * 2;
          stage[tl * 132 + o0] = acc[ot][tt][0];
          stage[(tl + 1) * 132 + o0] = acc[ot][tt][1];
          stage[tl * 132 + o0 + 8] = acc[ot][tt][2];
          stage[(tl + 1) * 132 + o0 + 8] = acc[ot][tt][3];
        }
      }
    }
    __syncthreads();
    for (int i = tid; i < 6144; i += 256) {
      int tl = i >> 7, g = i & 127;
      xgb[(size_t)(q * 48 + tl) * 128 + g] =
          stage[tl * 132 + g] + __ldg(bi + g) + __ldg(bh + g);
    }
  }
}

// ---------------- LSTM recurrence: warp per batch, prefetched gates ----------------
__device__ __forceinline__ float sigf(float x) { return 1.0f / (1.0f + expf(-x)); }

__global__ __launch_bounds__(256) void lstm_kernel(
    const float* __restrict__ xg, const float* __restrict__ whf,
    const float* __restrict__ whb, float* __restrict__ out) {
  __shared__ float ws[32 * 128];
  int dir = blockIdx.y;
  const float* wh = dir ? whb : whf;
  int tid = threadIdx.x;
  for (int idx = tid; idx < 4096; idx += 256) {
    int j = idx >> 7, r = idx & 127;
    ws[idx] = wh[r * 32 + j];
  }
  __syncthreads();
  int warp = tid >> 5, lane = tid & 31;
  int b = blockIdx.x * 8 + warp;
  const float* xgb = xg + (size_t)(dir * BB + b) * TT * 128;
  float h = 0.f, c = 0.f;
  int t0 = dir ? (TT - 1) : 0;
  const float* p0 = xgb + (size_t)t0 * 128;
  float gi = p0[lane], gf = p0[32 + lane], gg = p0[64 + lane], go = p0[96 + lane];
  for (int step = 0; step < TT; step++) {
    int t = dir ? (TT - 1 - step) : step;
    float ni = 0.f, nf = 0.f, ng = 0.f, no = 0.f;
    if (step + 1 < TT) {
      int tn = dir ? (t - 1) : (t + 1);
      const float* pn = xgb + (size_t)tn * 128;
      ni = pn[lane]; nf = pn[32 + lane]; ng = pn[64 + lane]; no = pn[96 + lane];
    }
#pragma unroll
    for (int j = 0; j < 32; j++) {
      float hj = __shfl_sync(0xffffffffu, h, j);
      const float* wr = ws + j * 128;
      gi = fmaf(wr[lane], hj, gi);
      gf = fmaf(wr[32 + lane], hj, gf);
      gg = fmaf(wr[64 + lane], hj, gg);
      go = fmaf(wr[96 + lane], hj, go);
    }
    c = sigf(gf) * c + sigf(gi) * tanhf(gg);
    h = sigf(go) * tanhf(c);
    if (dir == 0) {
      if ((t & 7) == 7) out[((size_t)b * 24 + (t >> 3)) * 64 + lane] = h;
    } else {
      if ((t & 7) == 0) out[((size_t)b * 24 + (t >> 3)) * 64 + 32 + lane] = h;
    }
    gi = ni; gf = nf; gg = ng; go = no;
  }
}

// ---------------- launch ----------------
extern "C" void kernel_launch(void* const* d_in, const int* in_sizes, int n_in,
                              void* d_out, int out_size) {
  (void)in_sizes; (void)n_in; (void)out_size;
  float *p_xg, *p_lam;
  int* p_gi;
  __half *p_xh, *p_xl, *p_wh;
  cudaGetSymbolAddress((void**)&p_xg, g_xg);
  cudaGetSymbolAddress((void**)&p_gi, g_gi);
  cudaGetSymbolAddress((void**)&p_lam, g_lam);
  cudaGetSymbolAddress((void**)&p_xh, g_xh);
  cudaGetSymbolAddress((void**)&p_xl, g_xl);
  cudaGetSymbolAddress((void**)&p_wh, g_wh);

  static int smem_set = 0;
  if (!smem_set) {
    cudaFuncSetAttribute(mma_conv, cudaFuncAttributeMaxDynamicSharedMemorySize, CONV_SMEM);
    cudaFuncSetAttribute(xg_mma, cudaFuncAttributeMaxDynamicSharedMemorySize, XG_SMEM);
    smem_set = 1;
  }

  const float* x0 = (const float*)d_in[0];

  // JAX threefry keys: rng = key(42); per layer i: fold_in -> split -> randint split
  KeyPack kp;
  for (int i = 0; i < 3; i++) {
    unsigned f0, f1;
    tf2x32(0u, 42u, 0u, (unsigned)i, f0, f1);
    unsigned k1a, k1b, k2a, k2b;
    tf2x32(f0, f1, 0u, 0u, k1a, k1b);
    tf2x32(f0, f1, 0u, 1u, k2a, k2b);
    unsigned ha, hb2, la, lb2;
    tf2x32(k2a, k2b, 0u, 0u, ha, hb2);
    tf2x32(k2a, k2b, 0u, 1u, la, lb2);
    kp.v[i * 6 + 0] = k1a; kp.v[i * 6 + 1] = k1b;
    kp.v[i * 6 + 2] = ha;  kp.v[i * 6 + 3] = hb2;
    kp.v[i * 6 + 4] = la;  kp.v[i * 6 + 5] = lb2;
  }

  const int wofs[3] = {0, 17 * 5 * 256 * 16, 33 * 5 * 256 * 16};
  // ping-pong: layer0 buf0->buf1, layer1 buf1->buf0, layer2 buf0->buf1
  const size_t inof[3] = {0, IMG, 0};
  const size_t outof[3] = {IMG, 0, IMG};

  interp_meta_all<<<dim3(16, 3), 32>>>(p_gi, p_lam, kp);
  x0prep<<<dim3(BB, NCH0), 192>>>(x0);
  wprep_all<<<245, 256>>>((const float*)d_in[1], (const float*)d_in[5],
                          (const float*)d_in[9]);
  wprep_xg<<<32, 128>>>((const float*)d_in[13], (const float*)d_in[17]);
  for (int i = 0; i < 3; i++) {
    const float* cb = (const float*)d_in[2 + 4 * i];
    const float* gw = (const float*)d_in[3 + 4 * i];
    const float* gb = (const float*)d_in[4 + 4 * i];
    int NCH = (i == 0) ? 17 : 16;
    mma_conv<<<dim3(4, BB), 128, CONV_SMEM>>>(
        p_wh + wofs[i], cb,
        p_gi + i * BB * TT, p_lam + i * BB * TT, gw, gb,
        p_xh + inof[i], p_xl + inof[i], p_xh + outof[i], p_xl + outof[i], NCH);
  }
  xg_mma<<<dim3(2, BB), 256, XG_SMEM>>>(p_xh + IMG, p_xl + IMG,
                                        (const float*)d_in[15], (const float*)d_in[16],
                                        (const float*)d_in[19], (const float*)d_in[20],
                                        p_xg);
  lstm_kernel<<<dim3(64, 2), 256>>>(p_xg, (const float*)d_in[14],
                                    (const float*)d_in[18], (float*)d_out);
}

// round 17
// speedup vs baseline: 8.0594x; 1.0039x over previous
#include <cuda_runtime.h>
#include <cuda_fp16.h>
#include <math.h>

#define BB 512
#define TT 192
#define CC 256
#define NCH0 17           // layer0 ci chunks of 16 (257 -> 272)
#define XSTR 24           // xg smem row stride (fp16): conflict-free
#define IMG ((size_t)BB * NCH0 * 196 * 16)

typedef unsigned int u32;

// ---------------- scratch (device globals; no allocation) ----------------
__device__ float g_xg[(size_t)2 * BB * TT * 128]; // lstm pre-gates [dir,B,T,128]
__device__ float g_mu[BB * 16];
__device__ float g_rsig[BB * 16];
__device__ int   g_gi[3 * BB * TT];
__device__ float g_lam[3 * BB * TT];
// DOUBLE-BUFFERED fp16-split x images: [buf 2][b][chunk<17][row 0..195][ci16]
__device__ __half g_xh[2 * IMG];
__device__ __half g_xl[2 * IMG];
// fp16 conv weights, all 3 layers: [layer-chunk 49][k 5][o 256][ci16]
__device__ __half g_wh[49 * 5 * 256 * 16];
// fp16 xg weights: [dir 2][chunk 16][g 128][ci16]
__device__ __half g_wxh[2 * 16 * 128 * 16];

// ---------------- threefry2x32 (JAX), host + device ----------------
__host__ __device__ __forceinline__ void tf2x32(unsigned k0, unsigned k1,
                                                unsigned x0, unsigned x1,
                                                unsigned& y0, unsigned& y1) {
  unsigned ks2 = k0 ^ k1 ^ 0x1BD11BDAu;
  x0 += k0; x1 += k1;
#define TFR(r) x0 += x1; x1 = (x1 << (r)) | (x1 >> (32 - (r))); x1 ^= x0;
  TFR(13) TFR(15) TFR(26) TFR(6)
  x0 += k1;  x1 += ks2 + 1u;
  TFR(17) TFR(29) TFR(16) TFR(24)
  x0 += ks2; x1 += k0 + 2u;
  TFR(13) TFR(15) TFR(26) TFR(6)
  x0 += k0;  x1 += k1 + 3u;
  TFR(17) TFR(29) TFR(16) TFR(24)
  x0 += k1;  x1 += ks2 + 4u;
  TFR(13) TFR(15) TFR(26) TFR(6)
  x0 += ks2; x1 += k0 + 5u;
#undef TFR
  y0 = x0; y1 = x1;
}

__device__ __forceinline__ unsigned tf_bits32(unsigned k0, unsigned k1, unsigned n) {
  unsigned y0, y1;
  tf2x32(k0, k1, 0u, n, y0, y1);
  return y0 ^ y1;
}

// ---------------- mma.sync (fp16) + ldmatrix + cp.async ----------------
__device__ __forceinline__ void mma16816(float* c, const u32* a, const u32* b) {
  asm volatile(
      "mma.sync.aligned.m16n8k16.row.col.f32.f16.f16.f32 "
      "{%0,%1,%2,%3}, {%4,%5,%6,%7}, {%8,%9}, {%0,%1,%2,%3};"
      : "+f"(c[0]), "+f"(c[1]), "+f"(c[2]), "+f"(c[3])
      : "r"(a[0]), "r"(a[1]), "r"(a[2]), "r"(a[3]), "r"(b[0]), "r"(b[1]));
}

__device__ __forceinline__ void ldsm4(u32* r, unsigned addr) {
  asm volatile("ldmatrix.sync.aligned.m8n8.x4.shared.b16 {%0,%1,%2,%3}, [%4];"
               : "=r"(r[0]), "=r"(r[1]), "=r"(r[2]), "=r"(r[3]) : "r"(addr));
}

__device__ __forceinline__ void cpasync16(unsigned d, const void* g) {
  asm volatile("cp.async.cg.shared.global [%0], [%1], 16;" :: "r"(d), "l"(g));
}
#define CP_COMMIT() asm volatile("cp.async.commit_group;" ::: "memory")

// ---------------- fused prep: x0prep + wprep + wprep_xg + interp_meta ----------------
struct KeyPack { unsigned v[18]; };

#define NB_X0 (BB * NCH0)       // 8704
#define NB_W  245
#define NB_WXG 32
#define NB_META 48
#define NB_PREP (NB_X0 + NB_W + NB_WXG + NB_META)

__global__ __launch_bounds__(256) void prep_all(
    const float* __restrict__ x, const float* __restrict__ w0,
    const float* __restrict__ w1, const float* __restrict__ w2,
    const float* __restrict__ wxf, const float* __restrict__ wxb,
    int* __restrict__ gi, float* __restrict__ lam, KeyPack kp) {
  __shared__ float s[16][193];
  int blk = blockIdx.x;
  int tid = threadIdx.x;

  if (blk < NB_X0) {
    // ---- x0prep: transpose + fp16 split into buf0; pads in buf1 ----
    int b = blk / NCH0, ch = blk - b * NCH0;
    if (tid < TT) {
#pragma unroll
      for (int i = 0; i < 16; i++) {
        int ci = ch * 16 + i;
        s[i][tid] = (ci < 257) ? x[((size_t)b * 257 + ci) * TT + tid] : 0.f;
      }
    }
    __syncthreads();
    size_t ob = (size_t)b * NCH0 * 196 * 16 + (size_t)ch * 196 * 16;
    for (int idx = tid; idx < 196 * 16; idx += 256) {
      int row = idx >> 4, cl = idx & 15;
      int t = row - 2;
      float v = (t >= 0 && t < TT) ? s[cl][t] : 0.f;
      __half h = __float2half_rn(v);
      g_xh[ob + idx] = h;
      g_xl[ob + idx] = __float2half_rn(v - __half2float(h));
    }
    if (tid < 64) {
      int rr = tid >> 4, cl = tid & 15;
      int r = (rr < 2) ? rr : (192 + rr);
      size_t xi = IMG + ob + (size_t)r * 16 + cl;
      g_xh[xi] = __float2half_rn(0.f);
      g_xl[xi] = __float2half_rn(0.f);
    }
    return;
  }
  blk -= NB_X0;
  if (blk < NB_W) {
    // ---- conv weight prep ----
    int layer, lblk;
    if (blk < 85) { layer = 0; lblk = blk; }
    else if (blk < 165) { layer = 1; lblk = blk - 85; }
    else { layer = 2; lblk = blk - 165; }
    const float* w = (layer == 0) ? w0 : ((layer == 1) ? w1 : w2);
    int Cin = (layer == 0) ? 257 : 256;
    int wof = (layer == 0) ? 0 : ((layer == 1) ? 17 * 5 * 256 * 16 : 33 * 5 * 256 * 16);
    int chunk = lblk / 5, k = lblk % 5;
    int o = tid;
    size_t base = (size_t)wof + (size_t)((chunk * 5 + k) * 256 + o) * 16;
    for (int cl = 0; cl < 16; cl++) {
      int ci = chunk * 16 + cl;
      float v = (ci < Cin) ? w[((size_t)o * Cin + ci) * 5 + k] : 0.f;
      g_wh[base + cl] = __float2half_rn(v);
    }
    return;
  }
  blk -= NB_W;
  if (blk < NB_WXG) {
    // ---- xg weight prep ----
    if (tid >= 128) return;
    int dir = blk >> 4, chunk = blk & 15;
    int g = tid;
    const float* w = dir ? wxb : wxf;
    size_t base = (size_t)((dir * 16 + chunk) * 128 + g) * 16;
    for (int cl = 0; cl < 16; cl++)
      g_wxh[base + cl] = __float2half_rn(w[(size_t)g * CC + chunk * 16 + cl]);
    return;
  }
  blk -= NB_WXG;
  {
    // ---- interp_lnr metadata ----
    if (tid >= 32) return;
    int layer = blk / 16;
    int b = (blk - layer * 16) * 32 + tid;
    const unsigned* K = kp.v + layer * 6;
    int base = layer * BB * TT + b * TT;
    for (int t = 0; t < TT; t++) gi[base + t] = -1;
    int off = 0, pos = 0;
    for (int sg = 0; sg < 7; sg++) {
      unsigned n = (unsigned)(b * 7 + sg);
      unsigned ub = tf_bits32(K[0], K[1], n);
      float f = __uint_as_float((ub >> 9) | 0x3f800000u) - 1.0f;
      float scale = f + 0.5f;
      unsigned hb = tf_bits32(K[2], K[3], n);
      unsigned lb = tf_bits32(K[4], K[5], n);
      unsigned offt = ((hb % 13u) * 9u + lb % 13u) % 13u;
      int len = 19 + (int)offt;
      float lenm1 = (float)(len - 1);
      for (int l = 0; l < 64; l++) {
        float idx = __fdiv_rn((float)l, scale);
        float fl = floorf(idx);
        float lm = idx - fl;
        if (fl < lenm1) {
          int io = (int)fl + off;
          if (io < TT - 1) {
            if (pos < TT) { gi[base + pos] = io; lam[base + pos] = lm; }
            pos++;
          }
        }
      }
      off += len;
    }
  }
}

// ---------------- HMMA conv: fp16 2-pass; 64-o CTAs, 128 thr, 3 CTA/SM ----------------
#define SA_BYTES (5 * 64 * 32)
#define SB_BYTES (2 * 196 * 32)
#define STAGE_BYTES (SA_BYTES + SB_BYTES)
#define META_OFF 52224
#define CONV_SMEM (META_OFF + 1792)

__device__ __forceinline__ void conv_fill(int chunk, unsigned sstage, int oQr,
                                          const __half* wh,
                                          const __half* xbh,
                                          const __half* xbl, int tid) {
  for (int i = tid; i < 640; i += 128) {
    int k = i >> 7;
    int rem = i & 127;
    int o = rem >> 1, half = rem & 1;
    const void* g = wh + ((size_t)((chunk * 5 + k) * 256 + oQr * 64 + o) * 16 + half * 8);
    unsigned d = sstage + (unsigned)((k * 64 + o) * 32 + ((half ^ ((o >> 2) & 1)) << 4));
    cpasync16(d, g);
  }
  for (int i = tid; i < 784; i += 128) {
    int sp = i >= 392;
    int rem = sp ? i - 392 : i;
    int row = rem >> 1, half = rem & 1;
    const __half* xs = sp ? xbl : xbh;
    const void* g = xs + ((size_t)(chunk * 196 + row) * 16 + half * 8);
    int rowg = sp * 196 + row;
    unsigned d = sstage + (unsigned)(SA_BYTES + rowg * 32 + ((half ^ ((rowg >> 2) & 1)) << 4));
    cpasync16(d, g);
  }
}

__global__ __launch_bounds__(128, 3) void mma_conv(
    const __half* __restrict__ wh,
    const float* __restrict__ bias,
    const int* __restrict__ gi, const float* __restrict__ lam,
    const float* __restrict__ gnw, const float* __restrict__ gnb,
    const __half* __restrict__ ixh, const __half* __restrict__ ixl,
    __half* __restrict__ oxh, __half* __restrict__ oxl,
    int NCH) {
  extern __shared__ __half sm[];
  int oQr = blockIdx.x, b = blockIdx.y;
  int tid = threadIdx.x;
  int warp = tid >> 5, lane = tid & 31;
  int tBase = warp * 48;
  int lr = lane >> 2, lc = lane & 3;

  unsigned sb0 = (unsigned)__cvta_generic_to_shared(sm);
  int lane_rA = (lane & 7) + ((lane >> 3) & 1) * 8;
  unsigned rowA_off = (unsigned)(lane_rA * 32 +
                                 ((((lane >> 4) & 1) ^ ((lane_rA >> 2) & 1)) << 4));
  int tbl = tBase + (lane & 7) + ((lane >> 4) & 1) * 8;
  unsigned hB16 = (unsigned)(((lane >> 3) & 1) << 4);

  int*   sgi = (int*)((char*)sm + META_OFF);           // 192
  float* sla = (float*)((char*)sm + META_OFF + 768);   // 192
  float* gsm = (float*)((char*)sm + META_OFF + 1536);  // 32
  float* smu = gsm + 32;                               // 4
  float* srs = gsm + 36;                               // 4

  float acc[4][6][4];
#pragma unroll
  for (int ot = 0; ot < 4; ot++)
#pragma unroll
    for (int tt = 0; tt < 6; tt++)
#pragma unroll
      for (int q = 0; q < 4; q++) acc[ot][tt][q] = 0.f;

  const __half* xbh = ixh + (size_t)b * NCH0 * 196 * 16;
  const __half* xbl = ixl + (size_t)b * NCH0 * 196 * 16;

  conv_fill(0, sb0, oQr, wh, xbh, xbl, tid);
  CP_COMMIT();
  for (int i = tid; i < 192; i += 128) {
    sgi[i] = gi[b * TT + i];
    sla[i] = lam[b * TT + i];
  }

  for (int it = 0; it < NCH; it++) {
    int s = it & 1;
    if (it + 1 < NCH) {
      conv_fill(it + 1, sb0 + (unsigned)((s ^ 1) * STAGE_BYTES), oQr, wh, xbh, xbl, tid);
      CP_COMMIT();
      asm volatile("cp.async.wait_group 1;" ::: "memory");
    } else {
      asm volatile("cp.async.wait_group 0;" ::: "memory");
    }
    __syncthreads();
    unsigned sbA = sb0 + (unsigned)(s * STAGE_BYTES);
    unsigned sbB = sbA + (unsigned)SA_BYTES;
#pragma unroll 1
    for (int k = 0; k < 5; k++) {
      // A fragments shared by both passes (hoisted)
      u32 af[4][4];
      unsigned baseA = sbA + (unsigned)(k * 64 * 32) + rowA_off;
#pragma unroll
      for (int ot = 0; ot < 4; ot++) ldsm4(af[ot], baseA + (unsigned)(ot * 16 * 32));
#pragma unroll
      for (int sp = 0; sp < 2; sp++) {   // wh*xh, wh*xl
        int row0 = sp * 196 + tbl + k;
        unsigned baseB = sbB + (unsigned)(row0 * 32) +
                         (hB16 ^ (unsigned)((((unsigned)row0 >> 2) & 1) << 4));
        u32 bfr[6][2];
#pragma unroll
        for (int q = 0; q < 3; q++)
          ldsm4(&bfr[2 * q][0], baseB + (unsigned)(q * 512));
#pragma unroll
        for (int ot = 0; ot < 4; ot++)
#pragma unroll
          for (int tt = 0; tt < 6; tt++) mma16816(acc[ot][tt], af[ot], bfr[tt]);
      }
    }
    __syncthreads();
  }

  // ---- epilogue: full-tile smem stage [192][68] + GN stats + fused interp ----
  float* stage = (float*)sm;                 // [192][68]

  float bvA[4], bvB[4];
#pragma unroll
  for (int ot = 0; ot < 4; ot++) {
    int o0 = oQr * 64 + ot * 16 + lr;
    bvA[ot] = __ldg(bias + o0);
    bvB[ot] = __ldg(bias + o0 + 8);
  }
#pragma unroll
  for (int ot = 0; ot < 4; ot++) {
    int o0 = ot * 16 + lr;
    float s = 0.f, s2 = 0.f;
#pragma unroll
    for (int tt = 0; tt < 6; tt++) {
      int t = tBase + tt * 8 + lc * 2;
      float v0 = acc[ot][tt][0] + bvA[ot];
      float v1 = acc[ot][tt][1] + bvA[ot];
      float v2 = acc[ot][tt][2] + bvB[ot];
      float v3 = acc[ot][tt][3] + bvB[ot];
      stage[t * 68 + o0] = v0;
      stage[(t + 1) * 68 + o0] = v1;
      stage[t * 68 + o0 + 8] = v2;
      stage[(t + 1) * 68 + o0 + 8] = v3;
      s += v0 + v1 + v2 + v3;
      s2 = fmaf(v0, v0, s2); s2 = fmaf(v1, v1, s2);
      s2 = fmaf(v2, v2, s2); s2 = fmaf(v3, v3, s2);
    }
#pragma unroll
    for (int off = 16; off; off >>= 1) {
      s += __shfl_xor_sync(0xffffffffu, s, off);
      s2 += __shfl_xor_sync(0xffffffffu, s2, off);
    }
    if (lane == 0) {
      gsm[warp * 8 + ot * 2] = s;
      gsm[warp * 8 + ot * 2 + 1] = s2;
    }
  }
  __syncthreads();
  if (tid < 4) {
    int g = tid;
    float s = 0.f, s2 = 0.f;
#pragma unroll
    for (int wt = 0; wt < 4; wt++) {
      s += gsm[wt * 8 + g * 2];
      s2 += gsm[wt * 8 + g * 2 + 1];
    }
    float m = s * (1.0f / 3072.0f);
    float var = s2 * (1.0f / 3072.0f) - m * m;
    float rs = rsqrtf(var + 1e-5f);
    smu[g] = m;
    srs[g] = rs;
    g_mu[b * 16 + oQr * 4 + g] = m;
    g_rsig[b * 16 + oQr * 4 + g] = rs;
  }
  __syncthreads();

  // fused interp: thread = (channel c = tid&63, t-half = tid>>6)
  {
    int c = tid & 63;
    int th = tid >> 6;
    float m = smu[c >> 4];
    float rs = srs[c >> 4];
    int gc = oQr * 64 + c;
    float w = __ldg(gnw + gc), be = __ldg(gnb + gc);
    int chunk = gc >> 4, cl = gc & 15;
    __half* xhp = oxh + (size_t)b * NCH0 * 196 * 16 + (size_t)chunk * 196 * 16 + cl;
    __half* xlp = oxl + (size_t)b * NCH0 * 196 * 16 + (size_t)chunk * 196 * 16 + cl;
#pragma unroll 1
    for (int tp = th * 96; tp < th * 96 + 96; tp++) {
      int g = sgi[tp];
      float val = 0.f;
      if (g >= 0) {
        float lm = sla[tp];
        float a = stage[g * 68 + c];
        float e = stage[(g + 1) * 68 + c];
        float fa = fmaxf((a - m) * rs * w + be, 0.f);
        float fb = fmaxf((e - m) * rs * w + be, 0.f);
        val = (1.0f - lm) * fa + lm * fb;
      }
      __half h = __float2half_rn(val);
      xhp[(size_t)(tp + 2) * 16] = h;
      xlp[(size_t)(tp + 2) * 16] = __float2half_rn(val - __half2float(h));
    }
  }
}

// ---------------- HMMA xg GEMM: fp16 2-pass, 2-stage cp.async ----------------
#define XA_BYTES (128 * XSTR * 2)
#define XB_BYTES (2 * 192 * XSTR * 2)
#define XSTAGE_BYTES (XA_BYTES + XB_BYTES)
#define XG_SMEM_MAIN (XSTAGE_BYTES * 2)
#define XG_SMEM_STAGE (48 * 132 * 4)
#define XG_SMEM (XG_SMEM_MAIN > XG_SMEM_STAGE ? XG_SMEM_MAIN : XG_SMEM_STAGE)

__device__ __forceinline__ void xg_fill(int chunk, unsigned sstage, int dir,
                                        const __half* xbh,
                                        const __half* xbl, int tid) {
  for (int i = tid; i < 256; i += 256) {
    int o = i >> 1, half = i & 1;
    const void* g = g_wxh + ((size_t)((dir * 16 + chunk) * 128 + o) * 16 + half * 8);
    unsigned d = sstage + (unsigned)(o * XSTR * 2 + half * 16);
    cpasync16(d, g);
  }
  for (int i = tid; i < 768; i += 256) {
    int sp = i >= 384;
    int rem = sp ? i - 384 : i;
    int row = rem >> 1, half = rem & 1;
    const __half* xs = sp ? xbl : xbh;
    const void* g = xs + ((size_t)(chunk * 196 + 2 + row) * 16 + half * 8);
    unsigned d = sstage + (unsigned)(XA_BYTES + (sp * 192 + row) * XSTR * 2 + half * 16);
    cpasync16(d, g);
  }
}

__global__ __launch_bounds__(256) void xg_mma(
    const __half* __restrict__ xh, const __half* __restrict__ xl,
    const float* __restrict__ bif, const float* __restrict__ bhf,
    const float* __restrict__ bib, const float* __restrict__ bhb,
    float* __restrict__ xg) {
  extern __shared__ char xsm[];
  float* stage = (float*)xsm;                         // [48][132], epilogue reuse
  int dir = blockIdx.x, b = blockIdx.y;
  const float* bi = dir ? bib : bif;
  const float* bh = dir ? bhb : bhf;
  int tid = threadIdx.x;
  int warp = tid >> 5, lane = tid & 31;
  int warpO = warp & 1, warpT = warp >> 1;
  int oBaseL = warpO * 64, tBase = warpT * 48;
  int lr = lane >> 2, lc = lane & 3;

  unsigned sb0 = (unsigned)__cvta_generic_to_shared(xsm);
  unsigned rowA_off = ((oBaseL + (lane & 7) + ((lane >> 3) & 1) * 8) * XSTR +
                       ((lane >> 4) & 1) * 8) * 2;
  unsigned rowB_off = ((tBase + (lane & 7) + ((lane >> 4) & 1) * 8) * XSTR +
                       ((lane >> 3) & 1) * 8) * 2;

  float acc[4][6][4];
#pragma unroll
  for (int ot = 0; ot < 4; ot++)
#pragma unroll
    for (int tt = 0; tt < 6; tt++)
#pragma unroll
      for (int q = 0; q < 4; q++) acc[ot][tt][q] = 0.f;

  const __half* xbh = xh + (size_t)b * NCH0 * 196 * 16;
  const __half* xbl = xl + (size_t)b * NCH0 * 196 * 16;

  xg_fill(0, sb0, dir, xbh, xbl, tid);
  CP_COMMIT();

  for (int chunk = 0; chunk < 16; chunk++) {
    int s = chunk & 1;
    if (chunk + 1 < 16) {
      xg_fill(chunk + 1, sb0 + (unsigned)((s ^ 1) * XSTAGE_BYTES), dir, xbh, xbl, tid);
      CP_COMMIT();
      asm volatile("cp.async.wait_group 1;" ::: "memory");
    } else {
      asm volatile("cp.async.wait_group 0;" ::: "memory");
    }
    __syncthreads();
    unsigned sbA = sb0 + (unsigned)(s * XSTAGE_BYTES);
    unsigned sbB = sbA + (unsigned)XA_BYTES;
    u32 af[4][4];
    unsigned baseA = sbA + rowA_off;
#pragma unroll
    for (int ot = 0; ot < 4; ot++) ldsm4(af[ot], baseA + (unsigned)(ot * 16 * XSTR * 2));
#pragma unroll 1
    for (int sp = 0; sp < 2; sp++) {
      u32 bfr[6][2];
      unsigned baseB = sbB + (unsigned)(sp * 192 * XSTR * 2) + rowB_off;
#pragma unroll
      for (int q = 0; q < 3; q++)
        ldsm4(&bfr[2 * q][0], baseB + (unsigned)(q * 16 * XSTR * 2));
#pragma unroll
      for (int ot = 0; ot < 4; ot++)
#pragma unroll
        for (int tt = 0; tt < 6; tt++) mma16816(acc[ot][tt], af[ot], bfr[tt]);
    }
    __syncthreads();
  }
  float* xgb = xg + (size_t)(dir * BB + b) * TT * 128;
  for (int q = 0; q < 4; q++) {
    __syncthreads();
    if (warpT == q) {
#pragma unroll
      for (int ot = 0; ot < 4; ot++) {
        int o0 = oBaseL + ot * 16 + lr;
#pragma unroll
        for (int tt = 0; tt < 6; tt++) {
          int tl = tt * 8 + lc * 2;
          stage[tl * 132 + o0] = acc[ot][tt][0];
          stage[(tl + 1) * 132 + o0] = acc[ot][tt][1];
          stage[tl * 132 + o0 + 8] = acc[ot][tt][2];
          stage[(tl + 1) * 132 + o0 + 8] = acc[ot][tt][3];
        }
      }
    }
    __syncthreads();
    for (int i = tid; i < 6144; i += 256) {
      int tl = i >> 7, g = i & 127;
      xgb[(size_t)(q * 48 + tl) * 128 + g] =
          stage[tl * 132 + g] + __ldg(bi + g) + __ldg(bh + g);
    }
  }
}

// ---------------- LSTM recurrence: warp per batch, prefetched gates ----------------
__device__ __forceinline__ float sigf(float x) { return 1.0f / (1.0f + expf(-x)); }

__global__ __launch_bounds__(256) void lstm_kernel(
    const float* __restrict__ xg, const float* __restrict__ whf,
    const float* __restrict__ whb, float* __restrict__ out) {
  __shared__ float ws[32 * 128];
  int dir = blockIdx.y;
  const float* wh = dir ? whb : whf;
  int tid = threadIdx.x;
  for (int idx = tid; idx < 4096; idx += 256) {
    int j = idx >> 7, r = idx & 127;
    ws[idx] = wh[r * 32 + j];
  }
  __syncthreads();
  int warp = tid >> 5, lane = tid & 31;
  int b = blockIdx.x * 8 + warp;
  const float* xgb = xg + (size_t)(dir * BB + b) * TT * 128;
  float h = 0.f, c = 0.f;
  int t0 = dir ? (TT - 1) : 0;
  const float* p0 = xgb + (size_t)t0 * 128;
  float gi = p0[lane], gf = p0[32 + lane], gg = p0[64 + lane], go = p0[96 + lane];
  for (int step = 0; step < TT; step++) {
    int t = dir ? (TT - 1 - step) : step;
    float ni = 0.f, nf = 0.f, ng = 0.f, no = 0.f;
    if (step + 1 < TT) {
      int tn = dir ? (t - 1) : (t + 1);
      const float* pn = xgb + (size_t)tn * 128;
      ni = pn[lane]; nf = pn[32 + lane]; ng = pn[64 + lane]; no = pn[96 + lane];
    }
#pragma unroll
    for (int j = 0; j < 32; j++) {
      float hj = __shfl_sync(0xffffffffu, h, j);
      const float* wr = ws + j * 128;
      gi = fmaf(wr[lane], hj, gi);
      gf = fmaf(wr[32 + lane], hj, gf);
      gg = fmaf(wr[64 + lane], hj, gg);
      go = fmaf(wr[96 + lane], hj, go);
    }
    c = sigf(gf) * c + sigf(gi) * tanhf(gg);
    h = sigf(go) * tanhf(c);
    if (dir == 0) {
      if ((t & 7) == 7) out[((size_t)b * 24 + (t >> 3)) * 64 + lane] = h;
    } else {
      if ((t & 7) == 0) out[((size_t)b * 24 + (t >> 3)) * 64 + 32 + lane] = h;
    }
    gi = ni; gf = nf; gg = ng; go = no;
  }
}

// ---------------- launch ----------------
extern "C" void kernel_launch(void* const* d_in, const int* in_sizes, int n_in,
                              void* d_out, int out_size) {
  (void)in_sizes; (void)n_in; (void)out_size;
  float *p_xg, *p_lam;
  int* p_gi;
  __half *p_xh, *p_xl, *p_wh;
  cudaGetSymbolAddress((void**)&p_xg, g_xg);
  cudaGetSymbolAddress((void**)&p_gi, g_gi);
  cudaGetSymbolAddress((void**)&p_lam, g_lam);
  cudaGetSymbolAddress((void**)&p_xh, g_xh);
  cudaGetSymbolAddress((void**)&p_xl, g_xl);
  cudaGetSymbolAddress((void**)&p_wh, g_wh);

  static int smem_set = 0;
  if (!smem_set) {
    cudaFuncSetAttribute(mma_conv, cudaFuncAttributeMaxDynamicSharedMemorySize, CONV_SMEM);
    cudaFuncSetAttribute(xg_mma, cudaFuncAttributeMaxDynamicSharedMemorySize, XG_SMEM);
    smem_set = 1;
  }

  const float* x0 = (const float*)d_in[0];

  // JAX threefry keys: rng = key(42); per layer i: fold_in -> split -> randint split
  KeyPack kp;
  for (int i = 0; i < 3; i++) {
    unsigned f0, f1;
    tf2x32(0u, 42u, 0u, (unsigned)i, f0, f1);
    unsigned k1a, k1b, k2a, k2b;
    tf2x32(f0, f1, 0u, 0u, k1a, k1b);
    tf2x32(f0, f1, 0u, 1u, k2a, k2b);
    unsigned ha, hb2, la, lb2;
    tf2x32(k2a, k2b, 0u, 0u, ha, hb2);
    tf2x32(k2a, k2b, 0u, 1u, la, lb2);
    kp.v[i * 6 + 0] = k1a; kp.v[i * 6 + 1] = k1b;
    kp.v[i * 6 + 2] = ha;  kp.v[i * 6 + 3] = hb2;
    kp.v[i * 6 + 4] = la;  kp.v[i * 6 + 5] = lb2;
  }

  const int wofs[3] = {0, 17 * 5 * 256 * 16, 33 * 5 * 256 * 16};
  // ping-pong: layer0 buf0->buf1, layer1 buf1->buf0, layer2 buf0->buf1
  const size_t inof[3] = {0, IMG, 0};
  const size_t outof[3] = {IMG, 0, IMG};

  prep_all<<<NB_PREP, 256>>>(x0, (const float*)d_in[1], (const float*)d_in[5],
                             (const float*)d_in[9], (const float*)d_in[13],
                             (const float*)d_in[17], p_gi, p_lam, kp);
  for (int i = 0; i < 3; i++) {
    const float* cb = (const float*)d_in[2 + 4 * i];
    const float* gw = (const float*)d_in[3 + 4 * i];
    const float* gb = (const float*)d_in[4 + 4 * i];
    int NCH = (i == 0) ? 17 : 16;
    mma_conv<<<dim3(4, BB), 128, CONV_SMEM>>>(
        p_wh + wofs[i], cb,
        p_gi + i * BB * TT, p_lam + i * BB * TT, gw, gb,
        p_xh + inof[i], p_xl + inof[i], p_xh + outof[i], p_xl + outof[i], NCH);
  }
  xg_mma<<<dim3(2, BB), 256, XG_SMEM>>>(p_xh + IMG, p_xl + IMG,
                                        (const float*)d_in[15], (const float*)d_in[16],
                                        (const float*)d_in[19], (const float*)d_in[20],
                                        p_xg);
  lstm_kernel<<<dim3(64, 2), 256>>>(p_xg, (const float*)d_in[14],
                                    (const float*)d_in[18], (float*)d_out);
}